// round 1
// baseline (speedup 1.0000x reference)
#include <cuda_runtime.h>
#include <math.h>

#define B_   32
#define L_   512
#define D_   512
#define H_   8
#define DH_  64
#define NL_  2
#define DFF_ 2048
#define NB_  32
#define ML_  (B_*L_)   // 16384 rows

// ---------------- scratch (device globals; no allocations) ----------------
__device__ float g_x [B_*L_*D_];
__device__ float g_q [B_*L_*D_];
__device__ float g_k [B_*L_*D_];
__device__ float g_v [B_*L_*D_];
__device__ float g_ao[B_*L_*D_];
__device__ float g_po[B_*L_*D_];
__device__ float g_ff[B_*L_*DFF_];

// ---------------- embedding: x = item_emb[seq] + pos_emb[0:L] ----------------
__global__ void embed_kernel(const int* __restrict__ seq,
                             const float* __restrict__ item_emb,
                             const float* __restrict__ pos_emb)
{
    int idx = blockIdx.x * blockDim.x + threadIdx.x;   // over ML*D/4
    int d4 = idx & (D_/4 - 1);
    int bl = idx >> 7;                                  // idx / (D_/4)
    int l  = bl & (L_-1);
    int it = seq[bl];
    float4 a = *(const float4*)(item_emb + (size_t)it * D_ + d4*4);
    float4 p = *(const float4*)(pos_emb  + (size_t)l  * D_ + d4*4);
    a.x += p.x; a.y += p.y; a.z += p.z; a.w += p.w;
    ((float4*)g_x)[idx] = a;
}

// ---------------- SGEMM: C[M,N] = A[M,K] @ B[K,N] + bias (opt relu) ----------------
// 128x128 tile, TK=8, 256 threads, 8x8 per thread, double-buffered smem.
__global__ __launch_bounds__(256, 2)
void sgemm_kernel(const float* __restrict__ A, const float* __restrict__ Bm,
                  const float* __restrict__ bias, float* __restrict__ C,
                  int M, int N, int K, int applyRelu)
{
    __shared__ float As[2][8][132];
    __shared__ float Bs[2][8][128];

    int tid = threadIdx.x;
    int tx = tid & 15, ty = tid >> 4;
    int m0 = blockIdx.y * 128, n0 = blockIdx.x * 128;

    int arow = tid >> 1;           // 0..127
    int acol = (tid & 1) * 4;      // 0 or 4
    int brow = tid >> 5;           // 0..7
    int bcol = (tid & 31) * 4;     // 0..124

    const float* Aptr = A + (size_t)(m0 + arow) * K + acol;
    const float* Bptr = Bm + (size_t)brow * N + n0 + bcol;

    float acc[8][8];
    #pragma unroll
    for (int i = 0; i < 8; i++)
        #pragma unroll
        for (int j = 0; j < 8; j++) acc[i][j] = 0.f;

    int ktiles = K >> 3;

    float4 a4 = *(const float4*)Aptr;
    float4 b4 = *(const float4*)Bptr;
    As[0][acol+0][arow] = a4.x; As[0][acol+1][arow] = a4.y;
    As[0][acol+2][arow] = a4.z; As[0][acol+3][arow] = a4.w;
    *(float4*)&Bs[0][brow][bcol] = b4;
    __syncthreads();

    for (int kt = 0; kt < ktiles; ++kt) {
        int buf = kt & 1;
        if (kt + 1 < ktiles) {
            a4 = *(const float4*)(Aptr + (kt + 1) * 8);
            b4 = *(const float4*)(Bptr + (size_t)(kt + 1) * 8 * N);
        }
        #pragma unroll
        for (int kk = 0; kk < 8; ++kk) {
            float4 ra0 = *(const float4*)&As[buf][kk][ty*8];
            float4 ra1 = *(const float4*)&As[buf][kk][ty*8+4];
            float4 rb0 = *(const float4*)&Bs[buf][kk][tx*8];
            float4 rb1 = *(const float4*)&Bs[buf][kk][tx*8+4];
            float ra[8] = {ra0.x,ra0.y,ra0.z,ra0.w,ra1.x,ra1.y,ra1.z,ra1.w};
            float rb[8] = {rb0.x,rb0.y,rb0.z,rb0.w,rb1.x,rb1.y,rb1.z,rb1.w};
            #pragma unroll
            for (int i = 0; i < 8; i++)
                #pragma unroll
                for (int j = 0; j < 8; j++)
                    acc[i][j] += ra[i] * rb[j];
        }
        if (kt + 1 < ktiles) {
            int nb = buf ^ 1;
            As[nb][acol+0][arow] = a4.x; As[nb][acol+1][arow] = a4.y;
            As[nb][acol+2][arow] = a4.z; As[nb][acol+3][arow] = a4.w;
            *(float4*)&Bs[nb][brow][bcol] = b4;
        }
        __syncthreads();
    }

    #pragma unroll
    for (int i = 0; i < 8; i++) {
        int m = m0 + ty * 8 + i;
        #pragma unroll
        for (int j = 0; j < 8; j += 4) {
            int n = n0 + tx * 8 + j;
            float4 o;
            o.x = acc[i][j+0] + bias[n+0];
            o.y = acc[i][j+1] + bias[n+1];
            o.z = acc[i][j+2] + bias[n+2];
            o.w = acc[i][j+3] + bias[n+3];
            if (applyRelu) {
                o.x = fmaxf(o.x, 0.f); o.y = fmaxf(o.y, 0.f);
                o.z = fmaxf(o.z, 0.f); o.w = fmaxf(o.w, 0.f);
            }
            *(float4*)(C + (size_t)m * N + n) = o;
        }
    }
}

// ---------------- time bucket (matches TiSASRec _bucket exactly) ----------------
__device__ __forceinline__ int time_bucket(float delta)
{
    float a = fmaxf(fabsf(delta), 1.0f);
    // scale = float32(log2(2592000)/30); log2(2592000)=21.305634287546712
    const float scale = 0.71018780958489f;
    int idx = (int)(log2f(a) / scale) + 1;   // log2f(a) >= 0 -> trunc == floor-toward-zero
    idx = max(1, min(idx, NB_ - 2));
    if (a <= 1.0f)       idx = 0;
    if (a >= 2592000.0f) idx = NB_ - 1;
    return idx;
}

// ---------------- attention: flash-style fp32, inline time bias ----------------
// grid (L/64, H, B), 256 threads = 8 warps, each warp owns 8 q rows.
#define ATTN_SMEM ((3*64*65 + 64*64 + 64 + 32) * 4)

__global__ __launch_bounds__(256)
void attn_kernel(const float* __restrict__ q, const float* __restrict__ k,
                 const float* __restrict__ v, const float* __restrict__ ts,
                 const float* __restrict__ tbias, float* __restrict__ out)
{
    extern __shared__ float sh[];
    float* sQ   = sh;               // [64][65]
    float* sK   = sQ + 64*65;       // [64][65]
    float* sV   = sK + 64*65;       // [64][65]
    float* sP   = sV + 64*65;       // [64][64]
    float* sTsK = sP + 64*64;       // [64]
    float* sTb  = sTsK + 64;        // [32]

    int b = blockIdx.z, h = blockIdx.y, qt = blockIdx.x;
    int q0 = qt * 64;
    int tid = threadIdx.x;
    int lane = tid & 31, w = tid >> 5;

    const float* qbase = q + ((size_t)(b * L_ + q0)) * D_ + h * DH_;
    for (int idx = tid; idx < 64 * 16; idx += 256) {
        int r = idx >> 4, c4 = idx & 15;
        float4 t4 = *(const float4*)(qbase + (size_t)r * D_ + c4 * 4);
        float* dst = sQ + r * 65 + c4 * 4;
        dst[0] = t4.x; dst[1] = t4.y; dst[2] = t4.z; dst[3] = t4.w;
    }
    if (tid < NB_) sTb[tid] = tbias[tid * H_ + h];

    float m[8], lsum[8], acc0[8], acc1[8], tsq[8];
    #pragma unroll
    for (int r = 0; r < 8; r++) {
        m[r] = -1e30f; lsum[r] = 0.f; acc0[r] = 0.f; acc1[r] = 0.f;
        tsq[r] = ts[b * L_ + q0 + w * 8 + r];
    }

    int ntiles = qt + 1;
    for (int kt = 0; kt < ntiles; ++kt) {
        __syncthreads();  // covers sQ stores (first iter) + protects sK/sV reuse
        int kr0 = kt * 64;
        const float* kb = k + ((size_t)(b * L_ + kr0)) * D_ + h * DH_;
        const float* vb = v + ((size_t)(b * L_ + kr0)) * D_ + h * DH_;
        for (int idx = tid; idx < 64 * 16; idx += 256) {
            int r = idx >> 4, c4 = idx & 15;
            float4 t4 = *(const float4*)(kb + (size_t)r * D_ + c4 * 4);
            float* dk = sK + r * 65 + c4 * 4;
            dk[0] = t4.x; dk[1] = t4.y; dk[2] = t4.z; dk[3] = t4.w;
            float4 u4 = *(const float4*)(vb + (size_t)r * D_ + c4 * 4);
            float* dv = sV + r * 65 + c4 * 4;
            dv[0] = u4.x; dv[1] = u4.y; dv[2] = u4.z; dv[3] = u4.w;
        }
        if (tid < 64) sTsK[tid] = ts[b * L_ + kr0 + tid];
        __syncthreads();

        bool diag = (kt == qt);
        #pragma unroll 1
        for (int r = 0; r < 8; ++r) {
            int qlocal = w * 8 + r;
            int qglob  = q0 + qlocal;
            int k1 = lane, k2 = lane + 32;

            const float* qrow  = sQ + qlocal * 65;
            const float* krow1 = sK + k1 * 65;
            const float* krow2 = sK + k2 * 65;
            float s1 = 0.f, s2 = 0.f;
            #pragma unroll
            for (int d = 0; d < 64; ++d) {
                float qd = qrow[d];
                s1 += qd * krow1[d];
                s2 += qd * krow2[d];
            }
            s1 *= 0.125f; s2 *= 0.125f;   // 1/sqrt(64)
            s1 += sTb[time_bucket(tsq[r] - sTsK[k1])];
            s2 += sTb[time_bucket(tsq[r] - sTsK[k2])];
            if (diag) {
                if (kr0 + k1 > qglob) s1 = -1e30f;
                if (kr0 + k2 > qglob) s2 = -1e30f;
            }
            float lm = fmaxf(s1, s2);
            #pragma unroll
            for (int o = 16; o > 0; o >>= 1)
                lm = fmaxf(lm, __shfl_xor_sync(0xffffffffu, lm, o));
            float mnew = fmaxf(m[r], lm);
            float p1 = __expf(s1 - mnew);
            float p2 = __expf(s2 - mnew);
            float rscl = __expf(m[r] - mnew);
            m[r] = mnew;
            float psum = p1 + p2;
            #pragma unroll
            for (int o = 16; o > 0; o >>= 1)
                psum += __shfl_xor_sync(0xffffffffu, psum, o);
            lsum[r] = lsum[r] * rscl + psum;
            acc0[r] *= rscl; acc1[r] *= rscl;

            sP[qlocal * 64 + k1] = p1;
            sP[qlocal * 64 + k2] = p2;
            __syncwarp();
            const float* prow = sP + qlocal * 64;
            float a0 = acc0[r], a1 = acc1[r];
            #pragma unroll
            for (int j = 0; j < 64; ++j) {
                float pv = prow[j];
                a0 += pv * sV[j * 65 + lane];
                a1 += pv * sV[j * 65 + lane + 32];
            }
            acc0[r] = a0; acc1[r] = a1;
            __syncwarp();
        }
    }

    #pragma unroll
    for (int r = 0; r < 8; r++) {
        int qlocal = w * 8 + r;
        float inv = 1.0f / lsum[r];
        float* o = out + ((size_t)(b * L_ + q0 + qlocal)) * D_ + h * DH_;
        o[lane]      = acc0[r] * inv;
        o[lane + 32] = acc1[r] * inv;
    }
}

// ---------------- fused residual add + LayerNorm (row of 512) ----------------
__global__ __launch_bounds__(128)
void add_ln_kernel(const float* __restrict__ xin, const float* __restrict__ res,
                   const float* __restrict__ g, const float* __restrict__ bb,
                   float* __restrict__ xout)
{
    __shared__ float sy[D_];
    __shared__ float red[4];
    int row = blockIdx.x;
    int tid = threadIdx.x;
    int lane = tid & 31, w = tid >> 5;

    const float* xr = xin + (size_t)row * D_;
    const float* rr = res + (size_t)row * D_;

    float lsum = 0.f;
    #pragma unroll
    for (int i = 0; i < 4; i++) {
        int d = tid + i * 128;
        float val = xr[d] + rr[d];
        sy[d] = val;
        lsum += val;
    }
    #pragma unroll
    for (int o = 16; o > 0; o >>= 1) lsum += __shfl_xor_sync(~0u, lsum, o);
    if (lane == 0) red[w] = lsum;
    __syncthreads();
    float mean = (red[0] + red[1] + red[2] + red[3]) * (1.0f / D_);
    __syncthreads();

    float lv = 0.f;
    #pragma unroll
    for (int i = 0; i < 4; i++) {
        int d = tid + i * 128;
        float c = sy[d] - mean;
        lv += c * c;
    }
    #pragma unroll
    for (int o = 16; o > 0; o >>= 1) lv += __shfl_xor_sync(~0u, lv, o);
    if (lane == 0) red[w] = lv;
    __syncthreads();
    float var = (red[0] + red[1] + red[2] + red[3]) * (1.0f / D_);
    float inv = rsqrtf(var + 1e-5f);

    #pragma unroll
    for (int i = 0; i < 4; i++) {
        int d = tid + i * 128;
        xout[(size_t)row * D_ + d] = (sy[d] - mean) * inv * g[d] + bb[d];
    }
}

// ---------------- launch ----------------
extern "C" void kernel_launch(void* const* d_in, const int* in_sizes, int n_in,
                              void* d_out, int out_size)
{
    const int*   seq      = (const int*)  d_in[0];
    const float* ts       = (const float*)d_in[1];
    const float* item_emb = (const float*)d_in[2];
    const float* pos_emb  = (const float*)d_in[3];
    const float* Wq  = (const float*)d_in[4];  const float* bq  = (const float*)d_in[5];
    const float* Wk  = (const float*)d_in[6];  const float* bk  = (const float*)d_in[7];
    const float* Wv  = (const float*)d_in[8];  const float* bv  = (const float*)d_in[9];
    const float* tbias = (const float*)d_in[10];
    const float* Wo  = (const float*)d_in[11]; const float* bo  = (const float*)d_in[12];
    const float* g1  = (const float*)d_in[13]; const float* be1 = (const float*)d_in[14];
    const float* W1  = (const float*)d_in[15]; const float* bf1 = (const float*)d_in[16];
    const float* W2  = (const float*)d_in[17]; const float* bf2 = (const float*)d_in[18];
    const float* g2  = (const float*)d_in[19]; const float* be2 = (const float*)d_in[20];

    float *x, *q, *k, *v, *ao, *po, *ff;
    cudaGetSymbolAddress((void**)&x,  g_x);
    cudaGetSymbolAddress((void**)&q,  g_q);
    cudaGetSymbolAddress((void**)&k,  g_k);
    cudaGetSymbolAddress((void**)&v,  g_v);
    cudaGetSymbolAddress((void**)&ao, g_ao);
    cudaGetSymbolAddress((void**)&po, g_po);
    cudaGetSymbolAddress((void**)&ff, g_ff);

    cudaFuncSetAttribute(attn_kernel, cudaFuncAttributeMaxDynamicSharedMemorySize, ATTN_SMEM);

    embed_kernel<<<(ML_ * D_ / 4) / 256, 256>>>(seq, item_emb, pos_emb);

    for (int i = 0; i < NL_; i++) {
        dim3 gD(D_ / 128, ML_ / 128);       // (4, 128)
        dim3 gF(DFF_ / 128, ML_ / 128);     // (16, 128)

        sgemm_kernel<<<gD, 256>>>(x, Wq + (size_t)i*D_*D_, bq + i*D_, q, ML_, D_, D_, 0);
        sgemm_kernel<<<gD, 256>>>(x, Wk + (size_t)i*D_*D_, bk + i*D_, k, ML_, D_, D_, 0);
        sgemm_kernel<<<gD, 256>>>(x, Wv + (size_t)i*D_*D_, bv + i*D_, v, ML_, D_, D_, 0);

        dim3 ga(L_ / 64, H_, B_);           // (8, 8, 32)
        attn_kernel<<<ga, 256, ATTN_SMEM>>>(q, k, v, ts, tbias + (size_t)i*NB_*H_, ao);

        sgemm_kernel<<<gD, 256>>>(ao, Wo + (size_t)i*D_*D_, bo + i*D_, po, ML_, D_, D_, 0);
        add_ln_kernel<<<ML_, 128>>>(x, po, g1 + i*D_, be1 + i*D_, x);

        sgemm_kernel<<<gF, 256>>>(x, W1 + (size_t)i*D_*DFF_, bf1 + i*DFF_, ff, ML_, DFF_, D_, 1);
        sgemm_kernel<<<gD, 256>>>(ff, W2 + (size_t)i*DFF_*D_, bf2 + i*D_, po, ML_, D_, DFF_, 0);

        float* xo = (i == NL_ - 1) ? (float*)d_out : x;
        add_ln_kernel<<<ML_, 128>>>(x, po, g2 + i*D_, be2 + i*D_, xo);
    }
}

// round 3
// speedup vs baseline: 1.5836x; 1.5836x over previous
#include <cuda_runtime.h>
#include <cuda_bf16.h>
#include <math.h>
#include <stdint.h>

#define B_   32
#define L_   512
#define D_   512
#define H_   8
#define DH_  64
#define NL_  2
#define DFF_ 2048
#define NB_  32
#define ML_  (B_*L_)   // 16384 rows

typedef __nv_bfloat16 bf16;

// ---------------- scratch (device globals; no allocations) ----------------
__device__ float g_x [ML_*D_];
__device__ float g_q [ML_*D_];
__device__ float g_k [ML_*D_];
__device__ float g_v [ML_*D_];
__device__ float g_po[ML_*D_];
// split activations, D-wide
__device__ __align__(16) bf16 g_ah[ML_*D_];
__device__ __align__(16) bf16 g_al[ML_*D_];
// split activations, DFF-wide (FF1 output)
__device__ __align__(16) bf16 g_fh[ML_*DFF_];
__device__ __align__(16) bf16 g_fl[ML_*DFF_];
// transposed split weights per layer: {Wq,Wk,Wv,Wo: 512x512} {W1t: 2048x512} {W2t: 512x2048}
#define WT_LAYER (4*512*512 + 2048*512 + 512*2048)
__device__ __align__(16) bf16 g_wth[NL_*WT_LAYER];
__device__ __align__(16) bf16 g_wtl[NL_*WT_LAYER];

// ====================== PTX helpers (base ISA, sm_80+) ======================
__device__ __forceinline__ uint32_t smem_u32(const void* p) {
    uint32_t a;
    asm("{ .reg .u64 t; cvta.to.shared.u64 t, %1; cvt.u32.u64 %0, t; }" : "=r"(a) : "l"(p));
    return a;
}
__device__ __forceinline__ void cp16(uint32_t s, const void* g) {
    asm volatile("cp.async.cg.shared.global [%0], [%1], 16;" :: "r"(s), "l"(g));
}
__device__ __forceinline__ void ldsm4(uint32_t* r, uint32_t a) {
    asm volatile("ldmatrix.sync.aligned.m8n8.x4.shared.b16 {%0,%1,%2,%3}, [%4];"
        : "=r"(r[0]), "=r"(r[1]), "=r"(r[2]), "=r"(r[3]) : "r"(a));
}
__device__ __forceinline__ void mma16816(float* c, const uint32_t* a, const uint32_t* b) {
    asm volatile("mma.sync.aligned.m16n8k16.row.col.f32.bf16.bf16.f32 "
        "{%0,%1,%2,%3}, {%4,%5,%6,%7}, {%8,%9}, {%0,%1,%2,%3};"
        : "+f"(c[0]), "+f"(c[1]), "+f"(c[2]), "+f"(c[3])
        : "r"(a[0]), "r"(a[1]), "r"(a[2]), "r"(a[3]), "r"(b[0]), "r"(b[1]));
}

__device__ __forceinline__ void split_store(bf16* Oh, bf16* Ol, size_t off, float v0, float v1) {
    bf16 h0 = __float2bfloat16_rn(v0), h1 = __float2bfloat16_rn(v1);
    bf16 l0 = __float2bfloat16_rn(v0 - __bfloat162float(h0));
    bf16 l1 = __float2bfloat16_rn(v1 - __bfloat162float(h1));
    *(__nv_bfloat162*)(Oh + off) = __halves2bfloat162(h0, h1);
    *(__nv_bfloat162*)(Ol + off) = __halves2bfloat162(l0, l1);
}

// ====================== embedding (+ bf16 split) ======================
__global__ void embed_kernel(const int* __restrict__ seq,
                             const float* __restrict__ item_emb,
                             const float* __restrict__ pos_emb)
{
    int idx = blockIdx.x * blockDim.x + threadIdx.x;   // over ML*D/4
    int d4 = idx & (D_/4 - 1);
    int bl = idx >> 7;
    int l  = bl & (L_-1);
    int it = seq[bl];
    float4 a = *(const float4*)(item_emb + (size_t)it * D_ + d4*4);
    float4 p = *(const float4*)(pos_emb  + (size_t)l  * D_ + d4*4);
    a.x += p.x; a.y += p.y; a.z += p.z; a.w += p.w;
    ((float4*)g_x)[idx] = a;
    size_t off = (size_t)idx * 4;
    split_store(g_ah, g_al, off,     a.x, a.y);
    split_store(g_ah, g_al, off + 2, a.z, a.w);
}

// ====================== weight transpose + split: W[K,N] -> T[N,K] hi/lo ======================
__global__ void conv_wt_kernel(const float* __restrict__ W,
                               bf16* __restrict__ Th, bf16* __restrict__ Tl,
                               int K, int N)
{
    __shared__ float s[32][33];
    int tx = threadIdx.x, ty = threadIdx.y;   // 32 x 8
    int n0 = blockIdx.x * 32, k0 = blockIdx.y * 32;
    #pragma unroll
    for (int j = 0; j < 32; j += 8)
        s[ty + j][tx] = W[(size_t)(k0 + ty + j) * N + n0 + tx];
    __syncthreads();
    #pragma unroll
    for (int j = 0; j < 32; j += 8) {
        int n = n0 + ty + j, k = k0 + tx;
        float v = s[tx][ty + j];
        bf16 h = __float2bfloat16_rn(v);
        bf16 l = __float2bfloat16_rn(v - __bfloat162float(h));
        Th[(size_t)n * K + k] = h;
        Tl[(size_t)n * K + k] = l;
    }
}

// ====================== HMMA GEMM: C[M,N] = A[M,K] @ Bt[N,K]^T + bias ======================
// 128x128x32 tile, 256 threads (8 warps, each 64x32), cp.async double buffer,
// split-bf16: acc += Ah*Bh + Al*Bh + Ah*Bl.
// smem: 2 stages x 4 tiles(Ah,Al,Bh,Bl) x (128 rows x 80B) = 81920 B
#define TILE_B   10240
#define STAGE_B  40960
#define GSMEM    81920
#define STRIDE   40   // elements per smem row (80 bytes)

// flags: 1 = relu, 2 = write fp32 C, 4 = write split (Oh/Ol)
__global__ __launch_bounds__(256, 1)
void gemm_hmma(const bf16* __restrict__ Ah, const bf16* __restrict__ Al,
               const bf16* __restrict__ Bh, const bf16* __restrict__ Bl,
               const float* __restrict__ bias, float* __restrict__ C,
               bf16* __restrict__ Oh, bf16* __restrict__ Ol,
               int M, int N, int K, int flags)
{
    extern __shared__ char sm[];
    uint32_t sb = smem_u32(sm);
    int tid = threadIdx.x, lane = tid & 31, wid = tid >> 5;
    int wm = wid & 1, wn = wid >> 1;
    int m0 = blockIdx.y * 128, n0 = blockIdx.x * 128;

    // cp.async assignment: per tile, thread covers rows lrow and lrow+64, segment lseg (16B)
    int lrow = tid >> 2, lseg = tid & 3;
    const char* gAh = (const char*)(Ah + (size_t)(m0 + lrow) * K + lseg * 8);
    const char* gAl = (const char*)(Al + (size_t)(m0 + lrow) * K + lseg * 8);
    const char* gBh = (const char*)(Bh + (size_t)(n0 + lrow) * K + lseg * 8);
    const char* gBl = (const char*)(Bl + (size_t)(n0 + lrow) * K + lseg * 8);
    size_t rowskip = (size_t)64 * K * 2;   // bytes: +64 rows
    uint32_t s0off = (uint32_t)(lrow * STRIDE + lseg * 8) * 2;
    uint32_t s1off = s0off + 64 * STRIDE * 2;

    float acc[4][4][4];
    #pragma unroll
    for (int a = 0; a < 4; a++)
        #pragma unroll
        for (int b = 0; b < 4; b++)
            #pragma unroll
            for (int c = 0; c < 4; c++) acc[a][b][c] = 0.f;

    int NC = K >> 5;

#define LOADC(cc, st) do { \
    size_t ko = (size_t)(cc) * 64; /* bytes: 32 elems * 2 */ \
    uint32_t s0 = sb + (st) * STAGE_B + s0off; \
    uint32_t s1 = sb + (st) * STAGE_B + s1off; \
    cp16(s0,            gAh + ko); cp16(s1,            gAh + ko + rowskip); \
    cp16(s0 + TILE_B,   gAl + ko); cp16(s1 + TILE_B,   gAl + ko + rowskip); \
    cp16(s0 + 2*TILE_B, gBh + ko); cp16(s1 + 2*TILE_B, gBh + ko + rowskip); \
    cp16(s0 + 3*TILE_B, gBl + ko); cp16(s1 + 3*TILE_B, gBl + ko + rowskip); \
    asm volatile("cp.async.commit_group;"); \
} while (0)

    LOADC(0, 0);

    int ar = lane & 15, a8 = lane >> 4;

    for (int c = 0; c < NC; c++) {
        int st = c & 1;
        if (c + 1 < NC) {
            LOADC(c + 1, st ^ 1);
            asm volatile("cp.async.wait_group 1;");
        } else {
            asm volatile("cp.async.wait_group 0;");
        }
        __syncthreads();

        uint32_t tb = sb + st * STAGE_B;
        #pragma unroll
        for (int ks = 0; ks < 2; ks++) {
            int acol = ks * 16 + a8 * 8;
            uint32_t Ahf[4][4], Alf[4][4], Bhf[4][2], Blf[4][2];
            #pragma unroll
            for (int mt = 0; mt < 4; mt++) {
                uint32_t ad = tb + (uint32_t)((wm * 64 + mt * 16 + ar) * STRIDE + acol) * 2;
                ldsm4(Ahf[mt], ad);
                ldsm4(Alf[mt], ad + TILE_B);
            }
            #pragma unroll
            for (int p = 0; p < 2; p++) {
                uint32_t bd = tb + 2 * TILE_B +
                              (uint32_t)((wn * 32 + p * 16 + ar) * STRIDE + acol) * 2;
                uint32_t t[4];
                ldsm4(t, bd);
                Bhf[2*p][0] = t[0]; Bhf[2*p][1] = t[2];
                Bhf[2*p+1][0] = t[1]; Bhf[2*p+1][1] = t[3];
                ldsm4(t, bd + TILE_B);
                Blf[2*p][0] = t[0]; Blf[2*p][1] = t[2];
                Blf[2*p+1][0] = t[1]; Blf[2*p+1][1] = t[3];
            }
            #pragma unroll
            for (int mt = 0; mt < 4; mt++)
                #pragma unroll
                for (int nt = 0; nt < 4; nt++) {
                    mma16816(acc[mt][nt], Ahf[mt], Bhf[nt]);
                    mma16816(acc[mt][nt], Alf[mt], Bhf[nt]);
                    mma16816(acc[mt][nt], Ahf[mt], Blf[nt]);
                }
        }
        __syncthreads();
    }
#undef LOADC

    // epilogue
    int relu = flags & 1, wf = flags & 2, ws = flags & 4;
    int r_base = m0 + wm * 64 + (lane >> 2);
    int c_base = n0 + wn * 32 + (lane & 3) * 2;
    #pragma unroll
    for (int nt = 0; nt < 4; nt++) {
        int c0 = c_base + nt * 8;
        float2 bv = *(const float2*)(bias + c0);
        #pragma unroll
        for (int mt = 0; mt < 4; mt++) {
            #pragma unroll
            for (int h = 0; h < 2; h++) {
                int r = r_base + mt * 16 + h * 8;
                float v0 = acc[mt][nt][h*2+0] + bv.x;
                float v1 = acc[mt][nt][h*2+1] + bv.y;
                if (relu) { v0 = fmaxf(v0, 0.f); v1 = fmaxf(v1, 0.f); }
                size_t off = (size_t)r * N + c0;
                if (wf) *(float2*)(C + off) = make_float2(v0, v1);
                if (ws) split_store(Oh, Ol, off, v0, v1);
            }
        }
    }
}

// ====================== time bucket ======================
__device__ __forceinline__ int time_bucket(float delta)
{
    float a = fmaxf(fabsf(delta), 1.0f);
    const float scale = 0.71018780958489f;   // float32(log2(2592000)/30)
    int idx = (int)(log2f(a) / scale) + 1;
    idx = max(1, min(idx, NB_ - 2));
    if (a <= 1.0f)       idx = 0;
    if (a >= 2592000.0f) idx = NB_ - 1;
    return idx;
}

// ====================== attention (fp32 flash-style; split-bf16 output) ======================
#define ATTN_SMEM ((3*64*65 + 64*64 + 64 + 32) * 4)

__global__ __launch_bounds__(256)
void attn_kernel(const float* __restrict__ q, const float* __restrict__ k,
                 const float* __restrict__ v, const float* __restrict__ ts,
                 const float* __restrict__ tbias,
                 bf16* __restrict__ oh, bf16* __restrict__ ol)
{
    extern __shared__ float sh[];
    float* sQ   = sh;
    float* sK   = sQ + 64*65;
    float* sV   = sK + 64*65;
    float* sP   = sV + 64*65;
    float* sTsK = sP + 64*64;
    float* sTb  = sTsK + 64;

    int b = blockIdx.z, h = blockIdx.y, qt = blockIdx.x;
    int q0 = qt * 64;
    int tid = threadIdx.x;
    int lane = tid & 31, w = tid >> 5;

    const float* qbase = q + ((size_t)(b * L_ + q0)) * D_ + h * DH_;
    for (int idx = tid; idx < 64 * 16; idx += 256) {
        int r = idx >> 4, c4 = idx & 15;
        float4 t4 = *(const float4*)(qbase + (size_t)r * D_ + c4 * 4);
        float* dst = sQ + r * 65 + c4 * 4;
        dst[0] = t4.x; dst[1] = t4.y; dst[2] = t4.z; dst[3] = t4.w;
    }
    if (tid < NB_) sTb[tid] = tbias[tid * H_ + h];

    float m[8], lsum[8], acc0[8], acc1[8], tsq[8];
    #pragma unroll
    for (int r = 0; r < 8; r++) {
        m[r] = -1e30f; lsum[r] = 0.f; acc0[r] = 0.f; acc1[r] = 0.f;
        tsq[r] = ts[b * L_ + q0 + w * 8 + r];
    }

    int ntiles = qt + 1;
    for (int kt = 0; kt < ntiles; ++kt) {
        __syncthreads();
        int kr0 = kt * 64;
        const float* kb = k + ((size_t)(b * L_ + kr0)) * D_ + h * DH_;
        const float* vb = v + ((size_t)(b * L_ + kr0)) * D_ + h * DH_;
        for (int idx = tid; idx < 64 * 16; idx += 256) {
            int r = idx >> 4, c4 = idx & 15;
            float4 t4 = *(const float4*)(kb + (size_t)r * D_ + c4 * 4);
            float* dk = sK + r * 65 + c4 * 4;
            dk[0] = t4.x; dk[1] = t4.y; dk[2] = t4.z; dk[3] = t4.w;
            float4 u4 = *(const float4*)(vb + (size_t)r * D_ + c4 * 4);
            float* dv = sV + r * 65 + c4 * 4;
            dv[0] = u4.x; dv[1] = u4.y; dv[2] = u4.z; dv[3] = u4.w;
        }
        if (tid < 64) sTsK[tid] = ts[b * L_ + kr0 + tid];
        __syncthreads();

        bool diag = (kt == qt);
        #pragma unroll 1
        for (int r = 0; r < 8; ++r) {
            int qlocal = w * 8 + r;
            int qglob  = q0 + qlocal;
            int k1 = lane, k2 = lane + 32;

            const float* qrow  = sQ + qlocal * 65;
            const float* krow1 = sK + k1 * 65;
            const float* krow2 = sK + k2 * 65;
            float s1 = 0.f, s2 = 0.f;
            #pragma unroll
            for (int d = 0; d < 64; ++d) {
                float qd = qrow[d];
                s1 += qd * krow1[d];
                s2 += qd * krow2[d];
            }
            s1 *= 0.125f; s2 *= 0.125f;
            s1 += sTb[time_bucket(tsq[r] - sTsK[k1])];
            s2 += sTb[time_bucket(tsq[r] - sTsK[k2])];
            if (diag) {
                if (kr0 + k1 > qglob) s1 = -1e30f;
                if (kr0 + k2 > qglob) s2 = -1e30f;
            }
            float lm = fmaxf(s1, s2);
            #pragma unroll
            for (int o = 16; o > 0; o >>= 1)
                lm = fmaxf(lm, __shfl_xor_sync(0xffffffffu, lm, o));
            float mnew = fmaxf(m[r], lm);
            float p1 = __expf(s1 - mnew);
            float p2 = __expf(s2 - mnew);
            float rscl = __expf(m[r] - mnew);
            m[r] = mnew;
            float psum = p1 + p2;
            #pragma unroll
            for (int o = 16; o > 0; o >>= 1)
                psum += __shfl_xor_sync(0xffffffffu, psum, o);
            lsum[r] = lsum[r] * rscl + psum;
            acc0[r] *= rscl; acc1[r] *= rscl;

            sP[qlocal * 64 + k1] = p1;
            sP[qlocal * 64 + k2] = p2;
            __syncwarp();
            const float* prow = sP + qlocal * 64;
            float a0 = acc0[r], a1 = acc1[r];
            #pragma unroll
            for (int j = 0; j < 64; ++j) {
                float pv = prow[j];
                a0 += pv * sV[j * 65 + lane];
                a1 += pv * sV[j * 65 + lane + 32];
            }
            acc0[r] = a0; acc1[r] = a1;
            __syncwarp();
        }
    }

    #pragma unroll
    for (int r = 0; r < 8; r++) {
        int qlocal = w * 8 + r;
        float inv = 1.0f / lsum[r];
        size_t off = ((size_t)(b * L_ + q0 + qlocal)) * D_ + h * DH_;
        float v0 = acc0[r] * inv;
        float v1 = acc1[r] * inv;
        bf16 h0 = __float2bfloat16_rn(v0);
        bf16 h1 = __float2bfloat16_rn(v1);
        oh[off + lane]      = h0;
        oh[off + lane + 32] = h1;
        ol[off + lane]      = __float2bfloat16_rn(v0 - __bfloat162float(h0));
        ol[off + lane + 32] = __float2bfloat16_rn(v1 - __bfloat162float(h1));
    }
}

// ====================== fused residual add + LayerNorm (+ optional split) ======================
__global__ __launch_bounds__(128)
void add_ln_kernel(const float* __restrict__ xin, const float* __restrict__ res,
                   const float* __restrict__ g, const float* __restrict__ bb,
                   float* __restrict__ xout,
                   bf16* __restrict__ oh, bf16* __restrict__ ol, int writeSplit)
{
    __shared__ float sy[D_];
    __shared__ float red[4];
    int row = blockIdx.x;
    int tid = threadIdx.x;
    int lane = tid & 31, w = tid >> 5;

    const float* xr = xin + (size_t)row * D_;
    const float* rr = res + (size_t)row * D_;

    float lsum = 0.f;
    #pragma unroll
    for (int i = 0; i < 4; i++) {
        int d = tid + i * 128;
        float val = xr[d] + rr[d];
        sy[d] = val;
        lsum += val;
    }
    #pragma unroll
    for (int o = 16; o > 0; o >>= 1) lsum += __shfl_xor_sync(~0u, lsum, o);
    if (lane == 0) red[w] = lsum;
    __syncthreads();
    float mean = (red[0] + red[1] + red[2] + red[3]) * (1.0f / D_);
    __syncthreads();

    float lv = 0.f;
    #pragma unroll
    for (int i = 0; i < 4; i++) {
        int d = tid + i * 128;
        float c = sy[d] - mean;
        lv += c * c;
    }
    #pragma unroll
    for (int o = 16; o > 0; o >>= 1) lv += __shfl_xor_sync(~0u, lv, o);
    if (lane == 0) red[w] = lv;
    __syncthreads();
    float var = (red[0] + red[1] + red[2] + red[3]) * (1.0f / D_);
    float inv = rsqrtf(var + 1e-5f);

    #pragma unroll
    for (int i = 0; i < 4; i++) {
        int d = tid + i * 128;
        float val = (sy[d] - mean) * inv * g[d] + bb[d];
        xout[(size_t)row * D_ + d] = val;
        if (writeSplit) {
            size_t off = (size_t)row * D_ + d;
            bf16 hh = __float2bfloat16_rn(val);
            oh[off] = hh;
            ol[off] = __float2bfloat16_rn(val - __bfloat162float(hh));
        }
    }
}

// ====================== launch ======================
extern "C" void kernel_launch(void* const* d_in, const int* in_sizes, int n_in,
                              void* d_out, int out_size)
{
    const int*   seq      = (const int*)  d_in[0];
    const float* ts       = (const float*)d_in[1];
    const float* item_emb = (const float*)d_in[2];
    const float* pos_emb  = (const float*)d_in[3];
    const float* Wq  = (const float*)d_in[4];  const float* bq  = (const float*)d_in[5];
    const float* Wk  = (const float*)d_in[6];  const float* bk  = (const float*)d_in[7];
    const float* Wv  = (const float*)d_in[8];  const float* bv  = (const float*)d_in[9];
    const float* tbias = (const float*)d_in[10];
    const float* Wo  = (const float*)d_in[11]; const float* bo  = (const float*)d_in[12];
    const float* g1  = (const float*)d_in[13]; const float* be1 = (const float*)d_in[14];
    const float* W1  = (const float*)d_in[15]; const float* bf1 = (const float*)d_in[16];
    const float* W2  = (const float*)d_in[17]; const float* bf2 = (const float*)d_in[18];
    const float* g2  = (const float*)d_in[19]; const float* be2 = (const float*)d_in[20];

    float *x, *q, *k, *v, *po;
    bf16 *ah, *al, *fh, *fl, *wth, *wtl;
    cudaGetSymbolAddress((void**)&x,  g_x);
    cudaGetSymbolAddress((void**)&q,  g_q);
    cudaGetSymbolAddress((void**)&k,  g_k);
    cudaGetSymbolAddress((void**)&v,  g_v);
    cudaGetSymbolAddress((void**)&po, g_po);
    cudaGetSymbolAddress((void**)&ah, g_ah);
    cudaGetSymbolAddress((void**)&al, g_al);
    cudaGetSymbolAddress((void**)&fh, g_fh);
    cudaGetSymbolAddress((void**)&fl, g_fl);
    cudaGetSymbolAddress((void**)&wth, g_wth);
    cudaGetSymbolAddress((void**)&wtl, g_wtl);

    cudaFuncSetAttribute(attn_kernel, cudaFuncAttributeMaxDynamicSharedMemorySize, ATTN_SMEM);
    cudaFuncSetAttribute(gemm_hmma,   cudaFuncAttributeMaxDynamicSharedMemorySize, GSMEM);

    const size_t OQ = 0, OK = 262144, OV = 524288, OO = 786432, O1 = 1048576, O2 = 2097152;

    // convert weights (transpose + bf16 hi/lo split)
    for (int i = 0; i < NL_; i++) {
        size_t wb = (size_t)i * WT_LAYER;
        dim3 t32(32, 8);
        conv_wt_kernel<<<dim3(16, 16),  t32>>>(Wq + (size_t)i*D_*D_,   wth+wb+OQ, wtl+wb+OQ, 512, 512);
        conv_wt_kernel<<<dim3(16, 16),  t32>>>(Wk + (size_t)i*D_*D_,   wth+wb+OK, wtl+wb+OK, 512, 512);
        conv_wt_kernel<<<dim3(16, 16),  t32>>>(Wv + (size_t)i*D_*D_,   wth+wb+OV, wtl+wb+OV, 512, 512);
        conv_wt_kernel<<<dim3(16, 16),  t32>>>(Wo + (size_t)i*D_*D_,   wth+wb+OO, wtl+wb+OO, 512, 512);
        conv_wt_kernel<<<dim3(64, 16),  t32>>>(W1 + (size_t)i*D_*DFF_, wth+wb+O1, wtl+wb+O1, 512, 2048);
        conv_wt_kernel<<<dim3(16, 64),  t32>>>(W2 + (size_t)i*DFF_*D_, wth+wb+O2, wtl+wb+O2, 2048, 512);
    }

    embed_kernel<<<(ML_ * D_ / 4) / 256, 256>>>(seq, item_emb, pos_emb);

    for (int i = 0; i < NL_; i++) {
        size_t wb = (size_t)i * WT_LAYER;
        dim3 gD(D_ / 128, ML_ / 128);      // (4, 128)
        dim3 gF(DFF_ / 128, ML_ / 128);    // (16, 128)

        // QKV from x-split (flags=2: fp32 out)
        gemm_hmma<<<gD, 256, GSMEM>>>(ah, al, wth+wb+OQ, wtl+wb+OQ, bq + i*D_, q, 0, 0, ML_, D_, D_, 2);
        gemm_hmma<<<gD, 256, GSMEM>>>(ah, al, wth+wb+OK, wtl+wb+OK, bk + i*D_, k, 0, 0, ML_, D_, D_, 2);
        gemm_hmma<<<gD, 256, GSMEM>>>(ah, al, wth+wb+OV, wtl+wb+OV, bv + i*D_, v, 0, 0, ML_, D_, D_, 2);

        dim3 ga(L_ / 64, H_, B_);
        attn_kernel<<<ga, 256, ATTN_SMEM>>>(q, k, v, ts, tbias + (size_t)i*NB_*H_, ah, al);

        // Wo from attn-split -> po fp32
        gemm_hmma<<<gD, 256, GSMEM>>>(ah, al, wth+wb+OO, wtl+wb+OO, bo + i*D_, po, 0, 0, ML_, D_, D_, 2);
        add_ln_kernel<<<ML_, 128>>>(x, po, g1 + i*D_, be1 + i*D_, x, ah, al, 1);

        // FF1: relu + split output only (flags = 1|4)
        gemm_hmma<<<gF, 256, GSMEM>>>(ah, al, wth+wb+O1, wtl+wb+O1, bf1 + i*DFF_, 0, fh, fl, ML_, DFF_, D_, 5);
        // FF2: fp32 out
        gemm_hmma<<<gD, 256, GSMEM>>>(fh, fl, wth+wb+O2, wtl+wb+O2, bf2 + i*D_, po, 0, 0, ML_, D_, DFF_, 2);

        float* xo = (i == NL_ - 1) ? (float*)d_out : x;
        add_ln_kernel<<<ML_, 128>>>(x, po, g2 + i*D_, be2 + i*D_, xo, ah, al, (i < NL_ - 1) ? 1 : 0);
    }
}

// round 5
// speedup vs baseline: 2.2474x; 1.4191x over previous
#include <cuda_runtime.h>
#include <cuda_bf16.h>
#include <math.h>
#include <stdint.h>

#define B_   32
#define L_   512
#define D_   512
#define H_   8
#define DH_  64
#define NL_  2
#define DFF_ 2048
#define NB_  32
#define ML_  (B_*L_)   // 16384 rows

typedef __nv_bfloat16 bf16;

// ---------------- scratch (device globals; no allocations) ----------------
__device__ float g_x [ML_*D_];
__device__ float g_po[ML_*D_];
// split activations, D-wide (x / attn-out)
__device__ __align__(16) bf16 g_ah[ML_*D_];
__device__ __align__(16) bf16 g_al[ML_*D_];
// split q/k/v
__device__ __align__(16) bf16 g_qh[ML_*D_];
__device__ __align__(16) bf16 g_ql[ML_*D_];
__device__ __align__(16) bf16 g_kh[ML_*D_];
__device__ __align__(16) bf16 g_kl[ML_*D_];
__device__ __align__(16) bf16 g_vh[ML_*D_];
__device__ __align__(16) bf16 g_vl[ML_*D_];
// split FF1 output
__device__ __align__(16) bf16 g_fh[ML_*DFF_];
__device__ __align__(16) bf16 g_fl[ML_*DFF_];
// transposed split weights per layer
#define WT_LAYER (4*512*512 + 2048*512 + 512*2048)
__device__ __align__(16) bf16 g_wth[NL_*WT_LAYER];
__device__ __align__(16) bf16 g_wtl[NL_*WT_LAYER];

// ====================== PTX helpers ======================
__device__ __forceinline__ uint32_t smem_u32(const void* p) {
    uint32_t a;
    asm("{ .reg .u64 t; cvta.to.shared.u64 t, %1; cvt.u32.u64 %0, t; }" : "=r"(a) : "l"(p));
    return a;
}
__device__ __forceinline__ void cp16(uint32_t s, const void* g) {
    asm volatile("cp.async.cg.shared.global [%0], [%1], 16;" :: "r"(s), "l"(g));
}
__device__ __forceinline__ void ldsm4(uint32_t* r, uint32_t a) {
    asm volatile("ldmatrix.sync.aligned.m8n8.x4.shared.b16 {%0,%1,%2,%3}, [%4];"
        : "=r"(r[0]), "=r"(r[1]), "=r"(r[2]), "=r"(r[3]) : "r"(a));
}
__device__ __forceinline__ void ldsm4t(uint32_t* r, uint32_t a) {
    asm volatile("ldmatrix.sync.aligned.m8n8.x4.trans.shared.b16 {%0,%1,%2,%3}, [%4];"
        : "=r"(r[0]), "=r"(r[1]), "=r"(r[2]), "=r"(r[3]) : "r"(a));
}
__device__ __forceinline__ void mma16816(float* c, const uint32_t* a, const uint32_t* b) {
    asm volatile("mma.sync.aligned.m16n8k16.row.col.f32.bf16.bf16.f32 "
        "{%0,%1,%2,%3}, {%4,%5,%6,%7}, {%8,%9}, {%0,%1,%2,%3};"
        : "+f"(c[0]), "+f"(c[1]), "+f"(c[2]), "+f"(c[3])
        : "r"(a[0]), "r"(a[1]), "r"(a[2]), "r"(a[3]), "r"(b[0]), "r"(b[1]));
}

__device__ __forceinline__ void pack_hilo(float x, float y, uint32_t& h, uint32_t& l) {
    bf16 hx = __float2bfloat16_rn(x), hy = __float2bfloat16_rn(y);
    __nv_bfloat162 th = __halves2bfloat162(hx, hy);
    h = *(uint32_t*)&th;
    __nv_bfloat162 tl = __halves2bfloat162(
        __float2bfloat16_rn(x - __bfloat162float(hx)),
        __float2bfloat16_rn(y - __bfloat162float(hy)));
    l = *(uint32_t*)&tl;
}
__device__ __forceinline__ void split_store(bf16* Oh, bf16* Ol, size_t off, float v0, float v1) {
    uint32_t h, l;
    pack_hilo(v0, v1, h, l);
    *(uint32_t*)(Oh + off) = h;
    *(uint32_t*)(Ol + off) = l;
}

// ====================== embedding (+ bf16 split) ======================
__global__ void embed_kernel(const int* __restrict__ seq,
                             const float* __restrict__ item_emb,
                             const float* __restrict__ pos_emb)
{
    int idx = blockIdx.x * blockDim.x + threadIdx.x;   // over ML*D/4
    int d4 = idx & (D_/4 - 1);
    int bl = idx >> 7;
    int l  = bl & (L_-1);
    int it = seq[bl];
    float4 a = *(const float4*)(item_emb + (size_t)it * D_ + d4*4);
    float4 p = *(const float4*)(pos_emb  + (size_t)l  * D_ + d4*4);
    a.x += p.x; a.y += p.y; a.z += p.z; a.w += p.w;
    ((float4*)g_x)[idx] = a;
    size_t off = (size_t)idx * 4;
    split_store(g_ah, g_al, off,     a.x, a.y);
    split_store(g_ah, g_al, off + 2, a.z, a.w);
}

// ====================== weight transpose + split ======================
__global__ void conv_wt_kernel(const float* __restrict__ W,
                               bf16* __restrict__ Th, bf16* __restrict__ Tl,
                               int K, int N)
{
    __shared__ float s[32][33];
    int tx = threadIdx.x, ty = threadIdx.y;   // 32 x 8
    int n0 = blockIdx.x * 32, k0 = blockIdx.y * 32;
    #pragma unroll
    for (int j = 0; j < 32; j += 8)
        s[ty + j][tx] = W[(size_t)(k0 + ty + j) * N + n0 + tx];
    __syncthreads();
    #pragma unroll
    for (int j = 0; j < 32; j += 8) {
        int n = n0 + ty + j, k = k0 + tx;
        float v = s[tx][ty + j];
        bf16 h = __float2bfloat16_rn(v);
        bf16 l = __float2bfloat16_rn(v - __bfloat162float(h));
        Th[(size_t)n * K + k] = h;
        Tl[(size_t)n * K + k] = l;
    }
}

// ====================== HMMA GEMM ======================
#define TILE_B   10240
#define STAGE_B  40960
#define GSMEM    81920
#define STRIDE   40

// flags: 1 = relu, 2 = write fp32 C, 4 = write split (Oh/Ol)
__global__ __launch_bounds__(256, 1)
void gemm_hmma(const bf16* __restrict__ Ah, const bf16* __restrict__ Al,
               const bf16* __restrict__ Bh, const bf16* __restrict__ Bl,
               const float* __restrict__ bias, float* __restrict__ C,
               bf16* __restrict__ Oh, bf16* __restrict__ Ol,
               int M, int N, int K, int flags, float oscale)
{
    extern __shared__ char sm[];
    uint32_t sb = smem_u32(sm);
    int tid = threadIdx.x, lane = tid & 31, wid = tid >> 5;
    int wm = wid & 1, wn = wid >> 1;
    int m0 = blockIdx.y * 128, n0 = blockIdx.x * 128;

    int lrow = tid >> 2, lseg = tid & 3;
    const char* gAh = (const char*)(Ah + (size_t)(m0 + lrow) * K + lseg * 8);
    const char* gAl = (const char*)(Al + (size_t)(m0 + lrow) * K + lseg * 8);
    const char* gBh = (const char*)(Bh + (size_t)(n0 + lrow) * K + lseg * 8);
    const char* gBl = (const char*)(Bl + (size_t)(n0 + lrow) * K + lseg * 8);
    size_t rowskip = (size_t)64 * K * 2;
    uint32_t s0off = (uint32_t)(lrow * STRIDE + lseg * 8) * 2;
    uint32_t s1off = s0off + 64 * STRIDE * 2;

    float acc[4][4][4];
    #pragma unroll
    for (int a = 0; a < 4; a++)
        #pragma unroll
        for (int b = 0; b < 4; b++)
            #pragma unroll
            for (int c = 0; c < 4; c++) acc[a][b][c] = 0.f;

    int NC = K >> 5;

#define LOADC(cc, st) do { \
    size_t ko = (size_t)(cc) * 64; \
    uint32_t s0 = sb + (st) * STAGE_B + s0off; \
    uint32_t s1 = sb + (st) * STAGE_B + s1off; \
    cp16(s0,            gAh + ko); cp16(s1,            gAh + ko + rowskip); \
    cp16(s0 + TILE_B,   gAl + ko); cp16(s1 + TILE_B,   gAl + ko + rowskip); \
    cp16(s0 + 2*TILE_B, gBh + ko); cp16(s1 + 2*TILE_B, gBh + ko + rowskip); \
    cp16(s0 + 3*TILE_B, gBl + ko); cp16(s1 + 3*TILE_B, gBl + ko + rowskip); \
    asm volatile("cp.async.commit_group;"); \
} while (0)

    LOADC(0, 0);

    int ar = lane & 15, a8 = lane >> 4;

    for (int c = 0; c < NC; c++) {
        int st = c & 1;
        if (c + 1 < NC) {
            LOADC(c + 1, st ^ 1);
            asm volatile("cp.async.wait_group 1;");
        } else {
            asm volatile("cp.async.wait_group 0;");
        }
        __syncthreads();

        uint32_t tb = sb + st * STAGE_B;
        #pragma unroll
        for (int ks = 0; ks < 2; ks++) {
            int acol = ks * 16 + a8 * 8;
            uint32_t Ahf[4][4], Alf[4][4], Bhf[4][2], Blf[4][2];
            #pragma unroll
            for (int mt = 0; mt < 4; mt++) {
                uint32_t ad = tb + (uint32_t)((wm * 64 + mt * 16 + ar) * STRIDE + acol) * 2;
                ldsm4(Ahf[mt], ad);
                ldsm4(Alf[mt], ad + TILE_B);
            }
            #pragma unroll
            for (int p = 0; p < 2; p++) {
                uint32_t bd = tb + 2 * TILE_B +
                              (uint32_t)((wn * 32 + p * 16 + ar) * STRIDE + acol) * 2;
                uint32_t t[4];
                ldsm4(t, bd);
                Bhf[2*p][0] = t[0]; Bhf[2*p][1] = t[2];
                Bhf[2*p+1][0] = t[1]; Bhf[2*p+1][1] = t[3];
                ldsm4(t, bd + TILE_B);
                Blf[2*p][0] = t[0]; Blf[2*p][1] = t[2];
                Blf[2*p+1][0] = t[1]; Blf[2*p+1][1] = t[3];
            }
            #pragma unroll
            for (int mt = 0; mt < 4; mt++)
                #pragma unroll
                for (int nt = 0; nt < 4; nt++) {
                    mma16816(acc[mt][nt], Ahf[mt], Bhf[nt]);
                    mma16816(acc[mt][nt], Alf[mt], Bhf[nt]);
                    mma16816(acc[mt][nt], Ahf[mt], Blf[nt]);
                }
        }
        __syncthreads();
    }
#undef LOADC

    int relu = flags & 1, wf = flags & 2, ws = flags & 4;
    int r_base = m0 + wm * 64 + (lane >> 2);
    int c_base = n0 + wn * 32 + (lane & 3) * 2;
    #pragma unroll
    for (int nt = 0; nt < 4; nt++) {
        int c0 = c_base + nt * 8;
        float2 bv = *(const float2*)(bias + c0);
        #pragma unroll
        for (int mt = 0; mt < 4; mt++) {
            #pragma unroll
            for (int h = 0; h < 2; h++) {
                int r = r_base + mt * 16 + h * 8;
                float v0 = (acc[mt][nt][h*2+0] + bv.x) * oscale;
                float v1 = (acc[mt][nt][h*2+1] + bv.y) * oscale;
                if (relu) { v0 = fmaxf(v0, 0.f); v1 = fmaxf(v1, 0.f); }
                size_t off = (size_t)r * N + c0;
                if (wf) *(float2*)(C + off) = make_float2(v0, v1);
                if (ws) split_store(Oh, Ol, off, v0, v1);
            }
        }
    }
}

// ====================== time bucket ======================
__device__ __forceinline__ int time_bucket(float delta)
{
    float a = fmaxf(fabsf(delta), 1.0f);
    const float scale = 0.71018780958489f;   // float32(log2(2592000)/30)
    int idx = (int)(log2f(a) / scale) + 1;
    idx = max(1, min(idx, NB_ - 2));
    if (a <= 1.0f)       idx = 0;
    if (a >= 2592000.0f) idx = NB_ - 1;
    return idx;
}

// ====================== HMMA flash attention ======================
// block = 128 q rows of one (b,h); 8 warps x 16 rows; 64-key K/V tiles, double-buffered.
// Q pre-scaled by 1/8 in Q-GEMM. smem rows: 72 elements (144B) stride.
#define AQH_OFF   0
#define AQL_OFF   18432
#define ASTG_BASE 36864
#define ASTG_SZ   37120
#define AKH_OFF   0
#define AKL_OFF   9216
#define AVH_OFF   18432
#define AVL_OFF   27648
#define ATSK_OFF  36864
#define ATB_OFF   (ASTG_BASE + 2*ASTG_SZ)        // 111104
#define ATTN2_SMEM (ATB_OFF + 128)               // 111232

__device__ __forceinline__ void load_kv_tile(
    uint32_t sb, const bf16* kh, const bf16* kl, const bf16* vh, const bf16* vl,
    const float* ts, size_t kvbase, int b, int kt, int st, int tid)
{
    uint32_t stb = sb + ASTG_BASE + st * ASTG_SZ;
    #pragma unroll
    for (int i = 0; i < 2; i++) {
        int idx = tid + i * 256;             // 0..511: r = idx>>3, c = idx&7
        int r = idx >> 3, c = idx & 7;
        size_t go = kvbase * 2 + ((size_t)(kt * 64 + r) * D_) * 2 + c * 16;
        uint32_t so = (uint32_t)(r * 144 + c * 16);
        cp16(stb + AKH_OFF + so, (const char*)kh + go);
        cp16(stb + AKL_OFF + so, (const char*)kl + go);
        cp16(stb + AVH_OFF + so, (const char*)vh + go);
        cp16(stb + AVL_OFF + so, (const char*)vl + go);
    }
    if (tid < 16) cp16(stb + ATSK_OFF + tid * 16, ts + (size_t)b * L_ + kt * 64 + tid * 4);
    asm volatile("cp.async.commit_group;");
}

__global__ __launch_bounds__(256, 1)
void attn_mma(const bf16* __restrict__ qh, const bf16* __restrict__ ql,
              const bf16* __restrict__ kh, const bf16* __restrict__ kl,
              const bf16* __restrict__ vh, const bf16* __restrict__ vl,
              const float* __restrict__ ts, const float* __restrict__ tbias,
              bf16* __restrict__ oh, bf16* __restrict__ ol)
{
    extern __shared__ char sm[];
    uint32_t sb = smem_u32(sm);
    float* smf = (float*)sm;

    int qt = blockIdx.x, h = blockIdx.y, b = blockIdx.z;
    int q0 = qt * 128;
    int tid = threadIdx.x, lane = tid & 31, wid = tid >> 5;
    int g = lane >> 2, tig = lane & 3, tig2 = tig * 2;
    int ar = lane & 15, a8 = lane >> 4;

    // ---- load Q tile (128 rows x 64 cols, hi+lo) + tb ----
    {
        const char* gq  = (const char*)(qh + ((size_t)(b * L_ + q0) * D_) + h * DH_);
        const char* gq2 = (const char*)(ql + ((size_t)(b * L_ + q0) * D_) + h * DH_);
        #pragma unroll
        for (int i = 0; i < 4; i++) {
            int idx = tid + i * 256;          // 0..1023: r = idx>>3, c = idx&7
            int r = idx >> 3, c = idx & 7;
            size_t go = (size_t)r * D_ * 2 + c * 16;
            uint32_t so = (uint32_t)(r * 144 + c * 16);
            cp16(sb + AQH_OFF + so, gq + go);
            cp16(sb + AQL_OFF + so, gq2 + go);
        }
    }
    if (tid < NB_) smf[ATB_OFF/4 + tid] = tbias[tid * H_ + h];

    const size_t kvbase = ((size_t)(b * L_)) * D_ + h * DH_;
    int nkt = 2 * qt + 2;
    load_kv_tile(sb, kh, kl, vh, vl, ts, kvbase, b, 0, 0, tid);

    // per-row state
    int qg0 = q0 + wid * 16 + g, qg1 = qg0 + 8;
    float tsq0 = ts[(size_t)b * L_ + qg0];
    float tsq1 = ts[(size_t)b * L_ + qg1];
    float m0 = -1e30f, m1 = -1e30f, l0 = 0.f, l1 = 0.f;
    float acc_o[8][4];
    #pragma unroll
    for (int nt = 0; nt < 8; nt++)
        #pragma unroll
        for (int i = 0; i < 4; i++) acc_o[nt][i] = 0.f;

    // Q fragments (loop invariant)
    uint32_t qhf[4][4], qlf[4][4];
    asm volatile("cp.async.wait_group 0;");
    __syncthreads();
    #pragma unroll
    for (int kc = 0; kc < 4; kc++) {
        uint32_t ad = sb + AQH_OFF + (uint32_t)((wid * 16 + ar) * 72 + kc * 16 + a8 * 8) * 2;
        ldsm4(qhf[kc], ad);
        ldsm4(qlf[kc], ad + (AQL_OFF - AQH_OFF));
    }

    for (int kt = 0; kt < nkt; kt++) {
        int st = kt & 1;
        if (kt + 1 < nkt) {
            load_kv_tile(sb, kh, kl, vh, vl, ts, kvbase, b, kt + 1, st ^ 1, tid);
            asm volatile("cp.async.wait_group 1;");
        } else {
            asm volatile("cp.async.wait_group 0;");
        }
        __syncthreads();

        uint32_t stb = sb + ASTG_BASE + st * ASTG_SZ;
        const float* tsk = (const float*)(sm + ASTG_BASE + st * ASTG_SZ + ATSK_OFF);
        const float* tb  = (const float*)(sm + ATB_OFF);

        // ---- S = Q @ K^T ----
        float S[8][4];
        #pragma unroll
        for (int nt = 0; nt < 8; nt++)
            #pragma unroll
            for (int i = 0; i < 4; i++) S[nt][i] = 0.f;

        #pragma unroll
        for (int kc = 0; kc < 4; kc++) {
            #pragma unroll
            for (int nt2 = 0; nt2 < 4; nt2++) {
                uint32_t kd = stb + AKH_OFF + (uint32_t)((nt2 * 16 + ar) * 72 + kc * 16 + a8 * 8) * 2;
                uint32_t th[4], tl[4];
                ldsm4(th, kd);
                ldsm4(tl, kd + (AKL_OFF - AKH_OFF));
                uint32_t b0h[2] = {th[0], th[2]}, b1h[2] = {th[1], th[3]};
                uint32_t b0l[2] = {tl[0], tl[2]}, b1l[2] = {tl[1], tl[3]};
                mma16816(S[2*nt2],   qhf[kc], b0h);
                mma16816(S[2*nt2],   qlf[kc], b0h);
                mma16816(S[2*nt2],   qhf[kc], b0l);
                mma16816(S[2*nt2+1], qhf[kc], b1h);
                mma16816(S[2*nt2+1], qlf[kc], b1h);
                mma16816(S[2*nt2+1], qhf[kc], b1l);
            }
        }

        // ---- bias + mask + online softmax ----
        bool needMask = (kt >= 2 * qt);
        float mx0 = -1e30f, mx1 = -1e30f;
        #pragma unroll
        for (int nt = 0; nt < 8; nt++) {
            #pragma unroll
            for (int e = 0; e < 2; e++) {
                int col = nt * 8 + tig2 + e;
                float tk = tsk[col];
                float s0 = S[nt][e]   + tb[time_bucket(tsq0 - tk)];
                float s1 = S[nt][2+e] + tb[time_bucket(tsq1 - tk)];
                if (needMask) {
                    int kg = kt * 64 + col;
                    if (kg > qg0) s0 = -1e30f;
                    if (kg > qg1) s1 = -1e30f;
                }
                S[nt][e] = s0; S[nt][2+e] = s1;
                mx0 = fmaxf(mx0, s0); mx1 = fmaxf(mx1, s1);
            }
        }
        mx0 = fmaxf(mx0, __shfl_xor_sync(~0u, mx0, 1));
        mx0 = fmaxf(mx0, __shfl_xor_sync(~0u, mx0, 2));
        mx1 = fmaxf(mx1, __shfl_xor_sync(~0u, mx1, 1));
        mx1 = fmaxf(mx1, __shfl_xor_sync(~0u, mx1, 2));
        float mn0 = fmaxf(m0, mx0), mn1 = fmaxf(m1, mx1);
        float rs0 = __expf(m0 - mn0), rs1 = __expf(m1 - mn1);
        m0 = mn0; m1 = mn1;

        float sum0 = 0.f, sum1 = 0.f;
        #pragma unroll
        for (int nt = 0; nt < 8; nt++) {
            float p0 = __expf(S[nt][0] - mn0);
            float p1 = __expf(S[nt][1] - mn0);
            float p2 = __expf(S[nt][2] - mn1);
            float p3 = __expf(S[nt][3] - mn1);
            S[nt][0] = p0; S[nt][1] = p1; S[nt][2] = p2; S[nt][3] = p3;
            sum0 += p0 + p1; sum1 += p2 + p3;
        }
        sum0 += __shfl_xor_sync(~0u, sum0, 1); sum0 += __shfl_xor_sync(~0u, sum0, 2);
        sum1 += __shfl_xor_sync(~0u, sum1, 1); sum1 += __shfl_xor_sync(~0u, sum1, 2);
        l0 = l0 * rs0 + sum0;
        l1 = l1 * rs1 + sum1;
        #pragma unroll
        for (int nt = 0; nt < 8; nt++) {
            acc_o[nt][0] *= rs0; acc_o[nt][1] *= rs0;
            acc_o[nt][2] *= rs1; acc_o[nt][3] *= rs1;
        }

        // ---- O += P @ V ----
        #pragma unroll
        for (int t = 0; t < 4; t++) {
            uint32_t aph[4], apl[4];
            pack_hilo(S[2*t][0],   S[2*t][1],   aph[0], apl[0]);
            pack_hilo(S[2*t][2],   S[2*t][3],   aph[1], apl[1]);
            pack_hilo(S[2*t+1][0], S[2*t+1][1], aph[2], apl[2]);
            pack_hilo(S[2*t+1][2], S[2*t+1][3], aph[3], apl[3]);
            #pragma unroll
            for (int j2 = 0; j2 < 4; j2++) {
                uint32_t vd = stb + AVH_OFF + (uint32_t)((t * 16 + ar) * 72 + j2 * 16 + a8 * 8) * 2;
                uint32_t th[4], tl[4];
                ldsm4t(th, vd);
                ldsm4t(tl, vd + (AVL_OFF - AVH_OFF));
                uint32_t bh0[2] = {th[0], th[1]}, bh1[2] = {th[2], th[3]};
                uint32_t bl0[2] = {tl[0], tl[1]}, bl1[2] = {tl[2], tl[3]};
                mma16816(acc_o[2*j2],   aph, bh0);
                mma16816(acc_o[2*j2],   apl, bh0);
                mma16816(acc_o[2*j2],   aph, bl0);
                mma16816(acc_o[2*j2+1], aph, bh1);
                mma16816(acc_o[2*j2+1], apl, bh1);
                mma16816(acc_o[2*j2+1], aph, bl1);
            }
        }
        __syncthreads();
    }

    // ---- epilogue: split-bf16 output ----
    float inv0 = 1.0f / l0, inv1 = 1.0f / l1;
    size_t row0 = ((size_t)(b * L_ + qg0)) * D_ + h * DH_;
    size_t row1 = ((size_t)(b * L_ + qg1)) * D_ + h * DH_;
    #pragma unroll
    for (int nt = 0; nt < 8; nt++) {
        int cc = nt * 8 + tig2;
        split_store(oh, ol, row0 + cc, acc_o[nt][0] * inv0, acc_o[nt][1] * inv0);
        split_store(oh, ol, row1 + cc, acc_o[nt][2] * inv1, acc_o[nt][3] * inv1);
    }
}

// ====================== fused residual add + LayerNorm (+ optional split) ======================
__global__ __launch_bounds__(128)
void add_ln_kernel(const float* __restrict__ xin, const float* __restrict__ res,
                   const float* __restrict__ g, const float* __restrict__ bb,
                   float* __restrict__ xout,
                   bf16* __restrict__ oh, bf16* __restrict__ ol, int writeSplit)
{
    __shared__ float sy[D_];
    __shared__ float red[4];
    int row = blockIdx.x;
    int tid = threadIdx.x;
    int lane = tid & 31, w = tid >> 5;

    const float* xr = xin + (size_t)row * D_;
    const float* rr = res + (size_t)row * D_;

    float lsum = 0.f;
    #pragma unroll
    for (int i = 0; i < 4; i++) {
        int d = tid + i * 128;
        float val = xr[d] + rr[d];
        sy[d] = val;
        lsum += val;
    }
    #pragma unroll
    for (int o = 16; o > 0; o >>= 1) lsum += __shfl_xor_sync(~0u, lsum, o);
    if (lane == 0) red[w] = lsum;
    __syncthreads();
    float mean = (red[0] + red[1] + red[2] + red[3]) * (1.0f / D_);
    __syncthreads();

    float lv = 0.f;
    #pragma unroll
    for (int i = 0; i < 4; i++) {
        int d = tid + i * 128;
        float c = sy[d] - mean;
        lv += c * c;
    }
    #pragma unroll
    for (int o = 16; o > 0; o >>= 1) lv += __shfl_xor_sync(~0u, lv, o);
    if (lane == 0) red[w] = lv;
    __syncthreads();
    float var = (red[0] + red[1] + red[2] + red[3]) * (1.0f / D_);
    float inv = rsqrtf(var + 1e-5f);

    #pragma unroll
    for (int i = 0; i < 4; i++) {
        int d = tid + i * 128;
        float val = (sy[d] - mean) * inv * g[d] + bb[d];
        xout[(size_t)row * D_ + d] = val;
        if (writeSplit) {
            size_t off = (size_t)row * D_ + d;
            bf16 hh = __float2bfloat16_rn(val);
            oh[off] = hh;
            ol[off] = __float2bfloat16_rn(val - __bfloat162float(hh));
        }
    }
}

// ====================== launch ======================
extern "C" void kernel_launch(void* const* d_in, const int* in_sizes, int n_in,
                              void* d_out, int out_size)
{
    const int*   seq      = (const int*)  d_in[0];
    const float* ts       = (const float*)d_in[1];
    const float* item_emb = (const float*)d_in[2];
    const float* pos_emb  = (const float*)d_in[3];
    const float* Wq  = (const float*)d_in[4];  const float* bq  = (const float*)d_in[5];
    const float* Wk  = (const float*)d_in[6];  const float* bk  = (const float*)d_in[7];
    const float* Wv  = (const float*)d_in[8];  const float* bv  = (const float*)d_in[9];
    const float* tbias = (const float*)d_in[10];
    const float* Wo  = (const float*)d_in[11]; const float* bo  = (const float*)d_in[12];
    const float* g1  = (const float*)d_in[13]; const float* be1 = (const float*)d_in[14];
    const float* W1  = (const float*)d_in[15]; const float* bf1 = (const float*)d_in[16];
    const float* W2  = (const float*)d_in[17]; const float* bf2 = (const float*)d_in[18];
    const float* g2  = (const float*)d_in[19]; const float* be2 = (const float*)d_in[20];

    float *x, *po;
    bf16 *ah, *al, *qhp, *qlp, *khp, *klp, *vhp, *vlp, *fh, *fl, *wth, *wtl;
    cudaGetSymbolAddress((void**)&x,  g_x);
    cudaGetSymbolAddress((void**)&po, g_po);
    cudaGetSymbolAddress((void**)&ah, g_ah);
    cudaGetSymbolAddress((void**)&al, g_al);
    cudaGetSymbolAddress((void**)&qhp, g_qh);
    cudaGetSymbolAddress((void**)&qlp, g_ql);
    cudaGetSymbolAddress((void**)&khp, g_kh);
    cudaGetSymbolAddress((void**)&klp, g_kl);
    cudaGetSymbolAddress((void**)&vhp, g_vh);
    cudaGetSymbolAddress((void**)&vlp, g_vl);
    cudaGetSymbolAddress((void**)&fh, g_fh);
    cudaGetSymbolAddress((void**)&fl, g_fl);
    cudaGetSymbolAddress((void**)&wth, g_wth);
    cudaGetSymbolAddress((void**)&wtl, g_wtl);

    cudaFuncSetAttribute(attn_mma,  cudaFuncAttributeMaxDynamicSharedMemorySize, ATTN2_SMEM);
    cudaFuncSetAttribute(gemm_hmma, cudaFuncAttributeMaxDynamicSharedMemorySize, GSMEM);

    const size_t OQ = 0, OK = 262144, OV = 524288, OO = 786432, O1 = 1048576, O2 = 2097152;

    for (int i = 0; i < NL_; i++) {
        size_t wb = (size_t)i * WT_LAYER;
        dim3 t32(32, 8);
        conv_wt_kernel<<<dim3(16, 16),  t32>>>(Wq + (size_t)i*D_*D_,   wth+wb+OQ, wtl+wb+OQ, 512, 512);
        conv_wt_kernel<<<dim3(16, 16),  t32>>>(Wk + (size_t)i*D_*D_,   wth+wb+OK, wtl+wb+OK, 512, 512);
        conv_wt_kernel<<<dim3(16, 16),  t32>>>(Wv + (size_t)i*D_*D_,   wth+wb+OV, wtl+wb+OV, 512, 512);
        conv_wt_kernel<<<dim3(16, 16),  t32>>>(Wo + (size_t)i*D_*D_,   wth+wb+OO, wtl+wb+OO, 512, 512);
        conv_wt_kernel<<<dim3(64, 16),  t32>>>(W1 + (size_t)i*D_*DFF_, wth+wb+O1, wtl+wb+O1, 512, 2048);
        conv_wt_kernel<<<dim3(16, 64),  t32>>>(W2 + (size_t)i*DFF_*D_, wth+wb+O2, wtl+wb+O2, 2048, 512);
    }

    embed_kernel<<<(ML_ * D_ / 4) / 256, 256>>>(seq, item_emb, pos_emb);

    for (int i = 0; i < NL_; i++) {
        size_t wb = (size_t)i * WT_LAYER;
        dim3 gD(D_ / 128, ML_ / 128);      // (4, 128)
        dim3 gF(DFF_ / 128, ML_ / 128);    // (16, 128)

        // QKV: split-bf16 outputs only; Q pre-scaled by 1/sqrt(DH)=0.125
        gemm_hmma<<<gD, 256, GSMEM>>>(ah, al, wth+wb+OQ, wtl+wb+OQ, bq + i*D_, 0, qhp, qlp, ML_, D_, D_, 4, 0.125f);
        gemm_hmma<<<gD, 256, GSMEM>>>(ah, al, wth+wb+OK, wtl+wb+OK, bk + i*D_, 0, khp, klp, ML_, D_, D_, 4, 1.0f);
        gemm_hmma<<<gD, 256, GSMEM>>>(ah, al, wth+wb+OV, wtl+wb+OV, bv + i*D_, 0, vhp, vlp, ML_, D_, D_, 4, 1.0f);

        dim3 ga(L_ / 128, H_, B_);   // (4, 8, 32)
        attn_mma<<<ga, 256, ATTN2_SMEM>>>(qhp, qlp, khp, klp, vhp, vlp, ts,
                                          tbias + (size_t)i*NB_*H_, ah, al);

        gemm_hmma<<<gD, 256, GSMEM>>>(ah, al, wth+wb+OO, wtl+wb+OO, bo + i*D_, po, 0, 0, ML_, D_, D_, 2, 1.0f);
        add_ln_kernel<<<ML_, 128>>>(x, po, g1 + i*D_, be1 + i*D_, x, ah, al, 1);

        gemm_hmma<<<gF, 256, GSMEM>>>(ah, al, wth+wb+O1, wtl+wb+O1, bf1 + i*DFF_, 0, fh, fl, ML_, DFF_, D_, 5, 1.0f);
        gemm_hmma<<<gD, 256, GSMEM>>>(fh, fl, wth+wb+O2, wtl+wb+O2, bf2 + i*D_, po, 0, 0, ML_, D_, DFF_, 2, 1.0f);

        float* xo = (i == NL_ - 1) ? (float*)d_out : x;
        add_ln_kernel<<<ML_, 128>>>(x, po, g2 + i*D_, be2 + i*D_, xo, ah, al, (i < NL_ - 1) ? 1 : 0);
    }
}

// round 6
// speedup vs baseline: 2.3840x; 1.0608x over previous
#include <cuda_runtime.h>
#include <cuda_bf16.h>
#include <math.h>
#include <stdint.h>

#define B_   32
#define L_   512
#define D_   512
#define H_   8
#define DH_  64
#define NL_  2
#define DFF_ 2048
#define NB_  32
#define ML_  (B_*L_)   // 16384 rows
#define NQKV 1536

typedef __nv_bfloat16 bf16;

// ---------------- scratch (device globals; no allocations) ----------------
__device__ float g_x [ML_*D_];
__device__ float g_po[ML_*D_];
// split activations, D-wide (x / attn-out)
__device__ __align__(16) bf16 g_ah[ML_*D_];
__device__ __align__(16) bf16 g_al[ML_*D_];
// fused split qkv: [ML][1536] = [q(512) | k(512) | v(512)]
__device__ __align__(16) bf16 g_qvh[ML_*NQKV];
__device__ __align__(16) bf16 g_qvl[ML_*NQKV];
// split FF1 output
__device__ __align__(16) bf16 g_fh[ML_*DFF_];
__device__ __align__(16) bf16 g_fl[ML_*DFF_];
// transposed split weights per layer
#define WT_LAYER (4*512*512 + 2048*512 + 512*2048)
__device__ __align__(16) bf16 g_wth[NL_*WT_LAYER];
__device__ __align__(16) bf16 g_wtl[NL_*WT_LAYER];
// precomputed time-bucket indices [B][L][L] (head/layer independent)
__device__ __align__(16) unsigned char g_bk[B_*L_*L_];
// concatenated qkv bias per layer
__device__ float g_bqkv[NL_*NQKV];

// ====================== PTX helpers ======================
__device__ __forceinline__ uint32_t smem_u32(const void* p) {
    uint32_t a;
    asm("{ .reg .u64 t; cvta.to.shared.u64 t, %1; cvt.u32.u64 %0, t; }" : "=r"(a) : "l"(p));
    return a;
}
__device__ __forceinline__ void cp16(uint32_t s, const void* g) {
    asm volatile("cp.async.cg.shared.global [%0], [%1], 16;" :: "r"(s), "l"(g));
}
__device__ __forceinline__ void ldsm4(uint32_t* r, uint32_t a) {
    asm volatile("ldmatrix.sync.aligned.m8n8.x4.shared.b16 {%0,%1,%2,%3}, [%4];"
        : "=r"(r[0]), "=r"(r[1]), "=r"(r[2]), "=r"(r[3]) : "r"(a));
}
__device__ __forceinline__ void ldsm4t(uint32_t* r, uint32_t a) {
    asm volatile("ldmatrix.sync.aligned.m8n8.x4.trans.shared.b16 {%0,%1,%2,%3}, [%4];"
        : "=r"(r[0]), "=r"(r[1]), "=r"(r[2]), "=r"(r[3]) : "r"(a));
}
__device__ __forceinline__ void mma16816(float* c, const uint32_t* a, const uint32_t* b) {
    asm volatile("mma.sync.aligned.m16n8k16.row.col.f32.bf16.bf16.f32 "
        "{%0,%1,%2,%3}, {%4,%5,%6,%7}, {%8,%9}, {%0,%1,%2,%3};"
        : "+f"(c[0]), "+f"(c[1]), "+f"(c[2]), "+f"(c[3])
        : "r"(a[0]), "r"(a[1]), "r"(a[2]), "r"(a[3]), "r"(b[0]), "r"(b[1]));
}

__device__ __forceinline__ void pack_hilo(float x, float y, uint32_t& h, uint32_t& l) {
    bf16 hx = __float2bfloat16_rn(x), hy = __float2bfloat16_rn(y);
    __nv_bfloat162 th = __halves2bfloat162(hx, hy);
    h = *(uint32_t*)&th;
    __nv_bfloat162 tl = __halves2bfloat162(
        __float2bfloat16_rn(x - __bfloat162float(hx)),
        __float2bfloat16_rn(y - __bfloat162float(hy)));
    l = *(uint32_t*)&tl;
}
__device__ __forceinline__ void split_store(bf16* Oh, bf16* Ol, size_t off, float v0, float v1) {
    uint32_t h, l;
    pack_hilo(v0, v1, h, l);
    *(uint32_t*)(Oh + off) = h;
    *(uint32_t*)(Ol + off) = l;
}

// ====================== time bucket ======================
__device__ __forceinline__ int time_bucket(float delta)
{
    float a = fmaxf(fabsf(delta), 1.0f);
    const float scale = 0.71018780958489f;   // float32(log2(2592000)/30)
    int idx = (int)(log2f(a) / scale) + 1;
    idx = max(1, min(idx, NB_ - 2));
    if (a <= 1.0f)       idx = 0;
    if (a >= 2592000.0f) idx = NB_ - 1;
    return idx;
}

// precompute bucket bytes for all (b,q,k)
__global__ void bucket_kernel(const float* __restrict__ ts)
{
    int idx = blockIdx.x * blockDim.x + threadIdx.x;   // over B*L*L
    int k = idx & (L_-1);
    int q = (idx >> 9) & (L_-1);
    int b = idx >> 18;
    float d = ts[b * L_ + q] - ts[b * L_ + k];
    g_bk[idx] = (unsigned char)time_bucket(d);
}

// concat qkv biases per layer
__global__ void biascat_kernel(const float* __restrict__ bq,
                               const float* __restrict__ bk,
                               const float* __restrict__ bv)
{
    int i = blockIdx.x * blockDim.x + threadIdx.x;   // NL*1536
    int l = i / NQKV, c = i % NQKV;
    float v = (c < 512) ? bq[l*512 + c] : (c < 1024 ? bk[l*512 + c - 512] : bv[l*512 + c - 1024]);
    g_bqkv[i] = v;
}

// ====================== embedding (+ bf16 split) ======================
__global__ void embed_kernel(const int* __restrict__ seq,
                             const float* __restrict__ item_emb,
                             const float* __restrict__ pos_emb)
{
    int idx = blockIdx.x * blockDim.x + threadIdx.x;   // over ML*D/4
    int d4 = idx & (D_/4 - 1);
    int bl = idx >> 7;
    int l  = bl & (L_-1);
    int it = seq[bl];
    float4 a = *(const float4*)(item_emb + (size_t)it * D_ + d4*4);
    float4 p = *(const float4*)(pos_emb  + (size_t)l  * D_ + d4*4);
    a.x += p.x; a.y += p.y; a.z += p.z; a.w += p.w;
    ((float4*)g_x)[idx] = a;
    size_t off = (size_t)idx * 4;
    split_store(g_ah, g_al, off,     a.x, a.y);
    split_store(g_ah, g_al, off + 2, a.z, a.w);
}

// ====================== weight transpose + split ======================
__global__ void conv_wt_kernel(const float* __restrict__ W,
                               bf16* __restrict__ Th, bf16* __restrict__ Tl,
                               int K, int N)
{
    __shared__ float s[32][33];
    int tx = threadIdx.x, ty = threadIdx.y;   // 32 x 8
    int n0 = blockIdx.x * 32, k0 = blockIdx.y * 32;
    #pragma unroll
    for (int j = 0; j < 32; j += 8)
        s[ty + j][tx] = W[(size_t)(k0 + ty + j) * N + n0 + tx];
    __syncthreads();
    #pragma unroll
    for (int j = 0; j < 32; j += 8) {
        int n = n0 + ty + j, k = k0 + tx;
        float v = s[tx][ty + j];
        bf16 h = __float2bfloat16_rn(v);
        bf16 l = __float2bfloat16_rn(v - __bfloat162float(h));
        Th[(size_t)n * K + k] = h;
        Tl[(size_t)n * K + k] = l;
    }
}

// ====================== HMMA GEMM ======================
#define TILE_B   10240
#define STAGE_B  40960
#define GSMEM    81920
#define STRIDE   40

// flags: 1 = relu, 2 = write fp32 C, 4 = write split (Oh/Ol), 8 = qkv col-scale (0.125 for n<512)
__global__ __launch_bounds__(256, 1)
void gemm_hmma(const bf16* __restrict__ Ah, const bf16* __restrict__ Al,
               const bf16* __restrict__ Bh, const bf16* __restrict__ Bl,
               const float* __restrict__ bias, float* __restrict__ C,
               bf16* __restrict__ Oh, bf16* __restrict__ Ol,
               int M, int N, int K, int flags, float oscale)
{
    extern __shared__ char sm[];
    uint32_t sb = smem_u32(sm);
    int tid = threadIdx.x, lane = tid & 31, wid = tid >> 5;
    int wm = wid & 1, wn = wid >> 1;
    int m0 = blockIdx.y * 128, n0 = blockIdx.x * 128;

    int lrow = tid >> 2, lseg = tid & 3;
    const char* gAh = (const char*)(Ah + (size_t)(m0 + lrow) * K + lseg * 8);
    const char* gAl = (const char*)(Al + (size_t)(m0 + lrow) * K + lseg * 8);
    const char* gBh = (const char*)(Bh + (size_t)(n0 + lrow) * K + lseg * 8);
    const char* gBl = (const char*)(Bl + (size_t)(n0 + lrow) * K + lseg * 8);
    size_t rowskip = (size_t)64 * K * 2;
    uint32_t s0off = (uint32_t)(lrow * STRIDE + lseg * 8) * 2;
    uint32_t s1off = s0off + 64 * STRIDE * 2;

    float acc[4][4][4];
    #pragma unroll
    for (int a = 0; a < 4; a++)
        #pragma unroll
        for (int b = 0; b < 4; b++)
            #pragma unroll
            for (int c = 0; c < 4; c++) acc[a][b][c] = 0.f;

    int NC = K >> 5;

#define LOADC(cc, st) do { \
    size_t ko = (size_t)(cc) * 64; \
    uint32_t s0 = sb + (st) * STAGE_B + s0off; \
    uint32_t s1 = sb + (st) * STAGE_B + s1off; \
    cp16(s0,            gAh + ko); cp16(s1,            gAh + ko + rowskip); \
    cp16(s0 + TILE_B,   gAl + ko); cp16(s1 + TILE_B,   gAl + ko + rowskip); \
    cp16(s0 + 2*TILE_B, gBh + ko); cp16(s1 + 2*TILE_B, gBh + ko + rowskip); \
    cp16(s0 + 3*TILE_B, gBl + ko); cp16(s1 + 3*TILE_B, gBl + ko + rowskip); \
    asm volatile("cp.async.commit_group;"); \
} while (0)

    LOADC(0, 0);

    int ar = lane & 15, a8 = lane >> 4;

    for (int c = 0; c < NC; c++) {
        int st = c & 1;
        if (c + 1 < NC) {
            LOADC(c + 1, st ^ 1);
            asm volatile("cp.async.wait_group 1;");
        } else {
            asm volatile("cp.async.wait_group 0;");
        }
        __syncthreads();

        uint32_t tb = sb + st * STAGE_B;
        #pragma unroll
        for (int ks = 0; ks < 2; ks++) {
            int acol = ks * 16 + a8 * 8;
            uint32_t Ahf[4][4], Alf[4][4], Bhf[4][2], Blf[4][2];
            #pragma unroll
            for (int mt = 0; mt < 4; mt++) {
                uint32_t ad = tb + (uint32_t)((wm * 64 + mt * 16 + ar) * STRIDE + acol) * 2;
                ldsm4(Ahf[mt], ad);
                ldsm4(Alf[mt], ad + TILE_B);
            }
            #pragma unroll
            for (int p = 0; p < 2; p++) {
                uint32_t bd = tb + 2 * TILE_B +
                              (uint32_t)((wn * 32 + p * 16 + ar) * STRIDE + acol) * 2;
                uint32_t t[4];
                ldsm4(t, bd);
                Bhf[2*p][0] = t[0]; Bhf[2*p][1] = t[2];
                Bhf[2*p+1][0] = t[1]; Bhf[2*p+1][1] = t[3];
                ldsm4(t, bd + TILE_B);
                Blf[2*p][0] = t[0]; Blf[2*p][1] = t[2];
                Blf[2*p+1][0] = t[1]; Blf[2*p+1][1] = t[3];
            }
            #pragma unroll
            for (int mt = 0; mt < 4; mt++)
                #pragma unroll
                for (int nt = 0; nt < 4; nt++) {
                    mma16816(acc[mt][nt], Ahf[mt], Bhf[nt]);
                    mma16816(acc[mt][nt], Alf[mt], Bhf[nt]);
                    mma16816(acc[mt][nt], Ahf[mt], Blf[nt]);
                }
        }
        __syncthreads();
    }
#undef LOADC

    int relu = flags & 1, wf = flags & 2, ws = flags & 4;
    int r_base = m0 + wm * 64 + (lane >> 2);
    int c_base = n0 + wn * 32 + (lane & 3) * 2;
    #pragma unroll
    for (int nt = 0; nt < 4; nt++) {
        int c0 = c_base + nt * 8;
        float sc = (flags & 8) ? ((c0 < 512) ? 0.125f : 1.0f) : oscale;
        float2 bv = *(const float2*)(bias + c0);
        #pragma unroll
        for (int mt = 0; mt < 4; mt++) {
            #pragma unroll
            for (int h = 0; h < 2; h++) {
                int r = r_base + mt * 16 + h * 8;
                float v0 = (acc[mt][nt][h*2+0] + bv.x) * sc;
                float v1 = (acc[mt][nt][h*2+1] + bv.y) * sc;
                if (relu) { v0 = fmaxf(v0, 0.f); v1 = fmaxf(v1, 0.f); }
                size_t off = (size_t)r * N + c0;
                if (wf) *(float2*)(C + off) = make_float2(v0, v1);
                if (ws) split_store(Oh, Ol, off, v0, v1);
            }
        }
    }
}

// ====================== HMMA flash attention (precomputed buckets) ======================
// block = 128 q rows of one (b,h); 8 warps x 16 rows; 64-key K/V tiles, double-buffered.
// QKV packed [ML][1536]: q|k|v sections. Q pre-scaled by 1/8 in QKV GEMM.
#define AQH_OFF   0
#define AQL_OFF   18432
#define ASTG_BASE 36864
#define ASTG_SZ   45056
#define AKH_OFF   0
#define AKL_OFF   9216
#define AVH_OFF   18432
#define AVL_OFF   27648
#define ABK_OFF   36864
#define ATB_OFF   (ASTG_BASE + 2*ASTG_SZ)        // 126976
#define ATTN2_SMEM (ATB_OFF + 128)               // 127104

__device__ __forceinline__ void load_kv_tile(
    uint32_t sb, const bf16* qvh, const bf16* qvl, const unsigned char* bkp,
    int b, int h, int q0, int kt, int st, int tid)
{
    uint32_t stb = sb + ASTG_BASE + st * ASTG_SZ;
    const char* gkh = (const char*)qvh + ((size_t)(b * L_) * NQKV + 512  + h * DH_) * 2;
    const char* gkl = (const char*)qvl + ((size_t)(b * L_) * NQKV + 512  + h * DH_) * 2;
    const char* gvh = (const char*)qvh + ((size_t)(b * L_) * NQKV + 1024 + h * DH_) * 2;
    const char* gvl = (const char*)qvl + ((size_t)(b * L_) * NQKV + 1024 + h * DH_) * 2;
    #pragma unroll
    for (int i = 0; i < 2; i++) {
        int idx = tid + i * 256;             // 0..511: r = idx>>3 (0..63), c = idx&7
        int r = idx >> 3, c = idx & 7;
        size_t go = (size_t)(kt * 64 + r) * (NQKV * 2) + c * 16;
        uint32_t so = (uint32_t)(r * 144 + c * 16);
        cp16(stb + AKH_OFF + so, gkh + go);
        cp16(stb + AKL_OFF + so, gkl + go);
        cp16(stb + AVH_OFF + so, gvh + go);
        cp16(stb + AVL_OFF + so, gvl + go);
    }
    // bucket byte tile: 128 q rows x 64 k cols
    #pragma unroll
    for (int i = 0; i < 2; i++) {
        int idx = tid + i * 256;             // 0..511: r = idx>>2 (0..127), c = idx&3
        int r = idx >> 2, c = idx & 3;
        size_t go = ((size_t)(b * L_ + q0 + r)) * L_ + kt * 64 + c * 16;
        cp16(stb + ABK_OFF + (uint32_t)(r * 64 + c * 16), bkp + go);
    }
    asm volatile("cp.async.commit_group;");
}

__global__ __launch_bounds__(256, 1)
void attn_mma(const bf16* __restrict__ qvh, const bf16* __restrict__ qvl,
              const unsigned char* __restrict__ bkp, const float* __restrict__ tbias,
              bf16* __restrict__ oh, bf16* __restrict__ ol)
{
    extern __shared__ char sm[];
    uint32_t sb = smem_u32(sm);
    float* smf = (float*)sm;

    int qt = blockIdx.x, h = blockIdx.y, b = blockIdx.z;
    int q0 = qt * 128;
    int tid = threadIdx.x, lane = tid & 31, wid = tid >> 5;
    int g = lane >> 2, tig = lane & 3, tig2 = tig * 2;
    int ar = lane & 15, a8 = lane >> 4;

    // ---- load Q tile (128 rows x 64 cols, hi+lo) + tb ----
    {
        const char* gq  = (const char*)qvh + ((size_t)(b * L_ + q0) * NQKV + h * DH_) * 2;
        const char* gq2 = (const char*)qvl + ((size_t)(b * L_ + q0) * NQKV + h * DH_) * 2;
        #pragma unroll
        for (int i = 0; i < 4; i++) {
            int idx = tid + i * 256;          // 0..1023: r = idx>>3, c = idx&7
            int r = idx >> 3, c = idx & 7;
            size_t go = (size_t)r * (NQKV * 2) + c * 16;
            uint32_t so = (uint32_t)(r * 144 + c * 16);
            cp16(sb + AQH_OFF + so, gq + go);
            cp16(sb + AQL_OFF + so, gq2 + go);
        }
    }
    if (tid < NB_) smf[ATB_OFF/4 + tid] = tbias[tid * H_ + h];

    int nkt = 2 * qt + 2;
    load_kv_tile(sb, qvh, qvl, bkp, b, h, q0, 0, 0, tid);

    // per-row state
    int qg0 = q0 + wid * 16 + g, qg1 = qg0 + 8;
    int r0l = wid * 16 + g, r1l = r0l + 8;     // local q rows
    float m0 = -1e30f, m1 = -1e30f, l0 = 0.f, l1 = 0.f;
    float acc_o[8][4];
    #pragma unroll
    for (int nt = 0; nt < 8; nt++)
        #pragma unroll
        for (int i = 0; i < 4; i++) acc_o[nt][i] = 0.f;

    // Q fragments (loop invariant)
    uint32_t qhf[4][4], qlf[4][4];
    asm volatile("cp.async.wait_group 0;");
    __syncthreads();
    #pragma unroll
    for (int kc = 0; kc < 4; kc++) {
        uint32_t ad = sb + AQH_OFF + (uint32_t)((wid * 16 + ar) * 72 + kc * 16 + a8 * 8) * 2;
        ldsm4(qhf[kc], ad);
        ldsm4(qlf[kc], ad + (AQL_OFF - AQH_OFF));
    }

    const float* tb = (const float*)(sm + ATB_OFF);

    for (int kt = 0; kt < nkt; kt++) {
        int st = kt & 1;
        if (kt + 1 < nkt) {
            load_kv_tile(sb, qvh, qvl, bkp, b, h, q0, kt + 1, st ^ 1, tid);
            asm volatile("cp.async.wait_group 1;");
        } else {
            asm volatile("cp.async.wait_group 0;");
        }
        __syncthreads();

        uint32_t stb = sb + ASTG_BASE + st * ASTG_SZ;
        const unsigned char* bkt = (const unsigned char*)(sm + ASTG_BASE + st * ASTG_SZ + ABK_OFF);

        // ---- S = Q @ K^T ----
        float S[8][4];
        #pragma unroll
        for (int nt = 0; nt < 8; nt++)
            #pragma unroll
            for (int i = 0; i < 4; i++) S[nt][i] = 0.f;

        #pragma unroll
        for (int kc = 0; kc < 4; kc++) {
            #pragma unroll
            for (int nt2 = 0; nt2 < 4; nt2++) {
                uint32_t kd = stb + AKH_OFF + (uint32_t)((nt2 * 16 + ar) * 72 + kc * 16 + a8 * 8) * 2;
                uint32_t th[4], tl[4];
                ldsm4(th, kd);
                ldsm4(tl, kd + (AKL_OFF - AKH_OFF));
                uint32_t b0h[2] = {th[0], th[2]}, b1h[2] = {th[1], th[3]};
                uint32_t b0l[2] = {tl[0], tl[2]}, b1l[2] = {tl[1], tl[3]};
                mma16816(S[2*nt2],   qhf[kc], b0h);
                mma16816(S[2*nt2],   qlf[kc], b0h);
                mma16816(S[2*nt2],   qhf[kc], b0l);
                mma16816(S[2*nt2+1], qhf[kc], b1h);
                mma16816(S[2*nt2+1], qlf[kc], b1h);
                mma16816(S[2*nt2+1], qhf[kc], b1l);
            }
        }

        // ---- bias (precomputed bucket) + mask + online softmax ----
        bool needMask = (kt >= 2 * qt);
        float mx0 = -1e30f, mx1 = -1e30f;
        #pragma unroll
        for (int nt = 0; nt < 8; nt++) {
            int colb = nt * 8 + tig2;
            uint32_t pb0 = *(const unsigned short*)(bkt + r0l * 64 + colb);
            uint32_t pb1 = *(const unsigned short*)(bkt + r1l * 64 + colb);
            float s0a = S[nt][0] + tb[pb0 & 0xFF];
            float s0b = S[nt][1] + tb[pb0 >> 8];
            float s1a = S[nt][2] + tb[pb1 & 0xFF];
            float s1b = S[nt][3] + tb[pb1 >> 8];
            if (needMask) {
                int kg = kt * 64 + colb;
                if (kg     > qg0) s0a = -1e30f;
                if (kg + 1 > qg0) s0b = -1e30f;
                if (kg     > qg1) s1a = -1e30f;
                if (kg + 1 > qg1) s1b = -1e30f;
            }
            S[nt][0] = s0a; S[nt][1] = s0b; S[nt][2] = s1a; S[nt][3] = s1b;
            mx0 = fmaxf(mx0, fmaxf(s0a, s0b));
            mx1 = fmaxf(mx1, fmaxf(s1a, s1b));
        }
        mx0 = fmaxf(mx0, __shfl_xor_sync(~0u, mx0, 1));
        mx0 = fmaxf(mx0, __shfl_xor_sync(~0u, mx0, 2));
        mx1 = fmaxf(mx1, __shfl_xor_sync(~0u, mx1, 1));
        mx1 = fmaxf(mx1, __shfl_xor_sync(~0u, mx1, 2));
        float mn0 = fmaxf(m0, mx0), mn1 = fmaxf(m1, mx1);
        float rs0 = __expf(m0 - mn0), rs1 = __expf(m1 - mn1);
        m0 = mn0; m1 = mn1;

        float sum0 = 0.f, sum1 = 0.f;
        #pragma unroll
        for (int nt = 0; nt < 8; nt++) {
            float p0 = __expf(S[nt][0] - mn0);
            float p1 = __expf(S[nt][1] - mn0);
            float p2 = __expf(S[nt][2] - mn1);
            float p3 = __expf(S[nt][3] - mn1);
            S[nt][0] = p0; S[nt][1] = p1; S[nt][2] = p2; S[nt][3] = p3;
            sum0 += p0 + p1; sum1 += p2 + p3;
        }
        sum0 += __shfl_xor_sync(~0u, sum0, 1); sum0 += __shfl_xor_sync(~0u, sum0, 2);
        sum1 += __shfl_xor_sync(~0u, sum1, 1); sum1 += __shfl_xor_sync(~0u, sum1, 2);
        l0 = l0 * rs0 + sum0;
        l1 = l1 * rs1 + sum1;
        #pragma unroll
        for (int nt = 0; nt < 8; nt++) {
            acc_o[nt][0] *= rs0; acc_o[nt][1] *= rs0;
            acc_o[nt][2] *= rs1; acc_o[nt][3] *= rs1;
        }

        // ---- O += P @ V ----
        #pragma unroll
        for (int t = 0; t < 4; t++) {
            uint32_t aph[4], apl[4];
            pack_hilo(S[2*t][0],   S[2*t][1],   aph[0], apl[0]);
            pack_hilo(S[2*t][2],   S[2*t][3],   aph[1], apl[1]);
            pack_hilo(S[2*t+1][0], S[2*t+1][1], aph[2], apl[2]);
            pack_hilo(S[2*t+1][2], S[2*t+1][3], aph[3], apl[3]);
            #pragma unroll
            for (int j2 = 0; j2 < 4; j2++) {
                uint32_t vd = stb + AVH_OFF + (uint32_t)((t * 16 + ar) * 72 + j2 * 16 + a8 * 8) * 2;
                uint32_t th[4], tl[4];
                ldsm4t(th, vd);
                ldsm4t(tl, vd + (AVL_OFF - AVH_OFF));
                uint32_t bh0[2] = {th[0], th[1]}, bh1[2] = {th[2], th[3]};
                uint32_t bl0[2] = {tl[0], tl[1]}, bl1[2] = {tl[2], tl[3]};
                mma16816(acc_o[2*j2],   aph, bh0);
                mma16816(acc_o[2*j2],   apl, bh0);
                mma16816(acc_o[2*j2],   aph, bl0);
                mma16816(acc_o[2*j2+1], aph, bh1);
                mma16816(acc_o[2*j2+1], apl, bh1);
                mma16816(acc_o[2*j2+1], aph, bl1);
            }
        }
        __syncthreads();
    }

    // ---- epilogue: split-bf16 output into ah/al (D-wide) ----
    float inv0 = 1.0f / l0, inv1 = 1.0f / l1;
    size_t row0 = ((size_t)(b * L_ + qg0)) * D_ + h * DH_;
    size_t row1 = ((size_t)(b * L_ + qg1)) * D_ + h * DH_;
    #pragma unroll
    for (int nt = 0; nt < 8; nt++) {
        int cc = nt * 8 + tig2;
        split_store(oh, ol, row0 + cc, acc_o[nt][0] * inv0, acc_o[nt][1] * inv0);
        split_store(oh, ol, row1 + cc, acc_o[nt][2] * inv1, acc_o[nt][3] * inv1);
    }
}

// ====================== fused residual add + LayerNorm (+ optional split) ======================
__global__ __launch_bounds__(128)
void add_ln_kernel(const float* __restrict__ xin, const float* __restrict__ res,
                   const float* __restrict__ g, const float* __restrict__ bb,
                   float* __restrict__ xout,
                   bf16* __restrict__ oh, bf16* __restrict__ ol, int writeSplit)
{
    __shared__ float sy[D_];
    __shared__ float red[4];
    int row = blockIdx.x;
    int tid = threadIdx.x;
    int lane = tid & 31, w = tid >> 5;

    const float* xr = xin + (size_t)row * D_;
    const float* rr = res + (size_t)row * D_;

    float lsum = 0.f;
    #pragma unroll
    for (int i = 0; i < 4; i++) {
        int d = tid + i * 128;
        float val = xr[d] + rr[d];
        sy[d] = val;
        lsum += val;
    }
    #pragma unroll
    for (int o = 16; o > 0; o >>= 1) lsum += __shfl_xor_sync(~0u, lsum, o);
    if (lane == 0) red[w] = lsum;
    __syncthreads();
    float mean = (red[0] + red[1] + red[2] + red[3]) * (1.0f / D_);
    __syncthreads();

    float lv = 0.f;
    #pragma unroll
    for (int i = 0; i < 4; i++) {
        int d = tid + i * 128;
        float c = sy[d] - mean;
        lv += c * c;
    }
    #pragma unroll
    for (int o = 16; o > 0; o >>= 1) lv += __shfl_xor_sync(~0u, lv, o);
    if (lane == 0) red[w] = lv;
    __syncthreads();
    float var = (red[0] + red[1] + red[2] + red[3]) * (1.0f / D_);
    float inv = rsqrtf(var + 1e-5f);

    #pragma unroll
    for (int i = 0; i < 4; i++) {
        int d = tid + i * 128;
        float val = (sy[d] - mean) * inv * g[d] + bb[d];
        xout[(size_t)row * D_ + d] = val;
        if (writeSplit) {
            size_t off = (size_t)row * D_ + d;
            bf16 hh = __float2bfloat16_rn(val);
            oh[off] = hh;
            ol[off] = __float2bfloat16_rn(val - __bfloat162float(hh));
        }
    }
}

// ====================== launch ======================
extern "C" void kernel_launch(void* const* d_in, const int* in_sizes, int n_in,
                              void* d_out, int out_size)
{
    const int*   seq      = (const int*)  d_in[0];
    const float* ts       = (const float*)d_in[1];
    const float* item_emb = (const float*)d_in[2];
    const float* pos_emb  = (const float*)d_in[3];
    const float* Wq  = (const float*)d_in[4];  const float* bq  = (const float*)d_in[5];
    const float* Wk  = (const float*)d_in[6];  const float* bk  = (const float*)d_in[7];
    const float* Wv  = (const float*)d_in[8];  const float* bv  = (const float*)d_in[9];
    const float* tbias = (const float*)d_in[10];
    const float* Wo  = (const float*)d_in[11]; const float* bo  = (const float*)d_in[12];
    const float* g1  = (const float*)d_in[13]; const float* be1 = (const float*)d_in[14];
    const float* W1  = (const float*)d_in[15]; const float* bf1 = (const float*)d_in[16];
    const float* W2  = (const float*)d_in[17]; const float* bf2 = (const float*)d_in[18];
    const float* g2  = (const float*)d_in[19]; const float* be2 = (const float*)d_in[20];

    float *x, *po, *bqkv;
    bf16 *ah, *al, *qvh, *qvl, *fh, *fl, *wth, *wtl;
    unsigned char* bkptr;
    cudaGetSymbolAddress((void**)&x,  g_x);
    cudaGetSymbolAddress((void**)&po, g_po);
    cudaGetSymbolAddress((void**)&ah, g_ah);
    cudaGetSymbolAddress((void**)&al, g_al);
    cudaGetSymbolAddress((void**)&qvh, g_qvh);
    cudaGetSymbolAddress((void**)&qvl, g_qvl);
    cudaGetSymbolAddress((void**)&fh, g_fh);
    cudaGetSymbolAddress((void**)&fl, g_fl);
    cudaGetSymbolAddress((void**)&wth, g_wth);
    cudaGetSymbolAddress((void**)&wtl, g_wtl);
    cudaGetSymbolAddress((void**)&bkptr, g_bk);
    cudaGetSymbolAddress((void**)&bqkv, g_bqkv);

    cudaFuncSetAttribute(attn_mma,  cudaFuncAttributeMaxDynamicSharedMemorySize, ATTN2_SMEM);
    cudaFuncSetAttribute(gemm_hmma, cudaFuncAttributeMaxDynamicSharedMemorySize, GSMEM);

    const size_t OQ = 0, OO = 786432, O1 = 1048576, O2 = 2097152;

    for (int i = 0; i < NL_; i++) {
        size_t wb = (size_t)i * WT_LAYER;
        dim3 t32(32, 8);
        conv_wt_kernel<<<dim3(16, 16),  t32>>>(Wq + (size_t)i*D_*D_,   wth+wb+0,      wtl+wb+0,      512, 512);
        conv_wt_kernel<<<dim3(16, 16),  t32>>>(Wk + (size_t)i*D_*D_,   wth+wb+262144, wtl+wb+262144, 512, 512);
        conv_wt_kernel<<<dim3(16, 16),  t32>>>(Wv + (size_t)i*D_*D_,   wth+wb+524288, wtl+wb+524288, 512, 512);
        conv_wt_kernel<<<dim3(16, 16),  t32>>>(Wo + (size_t)i*D_*D_,   wth+wb+OO, wtl+wb+OO, 512, 512);
        conv_wt_kernel<<<dim3(64, 16),  t32>>>(W1 + (size_t)i*D_*DFF_, wth+wb+O1, wtl+wb+O1, 512, 2048);
        conv_wt_kernel<<<dim3(16, 64),  t32>>>(W2 + (size_t)i*DFF_*D_, wth+wb+O2, wtl+wb+O2, 2048, 512);
    }
    biascat_kernel<<<(NL_*NQKV)/256, 256>>>(bq, bk, bv);
    embed_kernel<<<(ML_ * D_ / 4) / 256, 256>>>(seq, item_emb, pos_emb);
    bucket_kernel<<<(B_*L_*L_)/256, 256>>>(ts);

    for (int i = 0; i < NL_; i++) {
        size_t wb = (size_t)i * WT_LAYER;
        dim3 gQKV(NQKV / 128, ML_ / 128);  // (12, 128)
        dim3 gD(D_ / 128, ML_ / 128);      // (4, 128)
        dim3 gF(DFF_ / 128, ML_ / 128);    // (16, 128)

        // fused QKV: split-bf16 packed output, q-section scaled 0.125
        gemm_hmma<<<gQKV, 256, GSMEM>>>(ah, al, wth+wb+OQ, wtl+wb+OQ, bqkv + i*NQKV,
                                        0, qvh, qvl, ML_, NQKV, D_, 4|8, 1.0f);

        dim3 ga(L_ / 128, H_, B_);   // (4, 8, 32)
        attn_mma<<<ga, 256, ATTN2_SMEM>>>(qvh, qvl, bkptr, tbias + (size_t)i*NB_*H_, ah, al);

        gemm_hmma<<<gD, 256, GSMEM>>>(ah, al, wth+wb+OO, wtl+wb+OO, bo + i*D_, po, 0, 0, ML_, D_, D_, 2, 1.0f);
        add_ln_kernel<<<ML_, 128>>>(x, po, g1 + i*D_, be1 + i*D_, x, ah, al, 1);

        gemm_hmma<<<gF, 256, GSMEM>>>(ah, al, wth+wb+O1, wtl+wb+O1, bf1 + i*DFF_, 0, fh, fl, ML_, DFF_, D_, 5, 1.0f);
        gemm_hmma<<<gD, 256, GSMEM>>>(fh, fl, wth+wb+O2, wtl+wb+O2, bf2 + i*D_, po, 0, 0, ML_, D_, DFF_, 2, 1.0f);

        float* xo = (i == NL_ - 1) ? (float*)d_out : x;
        add_ln_kernel<<<ML_, 128>>>(x, po, g2 + i*D_, be2 + i*D_, xo, ah, al, (i < NL_ - 1) ? 1 : 0);
    }
}

// round 7
// speedup vs baseline: 2.3884x; 1.0018x over previous
#include <cuda_runtime.h>
#include <cuda_bf16.h>
#include <math.h>
#include <stdint.h>

#define B_   32
#define L_   512
#define D_   512
#define H_   8
#define DH_  64
#define NL_  2
#define DFF_ 2048
#define NB_  32
#define ML_  (B_*L_)   // 16384 rows
#define NQKV 1536

typedef __nv_bfloat16 bf16;

// ---------------- scratch (device globals; no allocations) ----------------
__device__ float g_x [ML_*D_];
__device__ float g_po[ML_*D_];
__device__ __align__(16) bf16 g_ah[ML_*D_];
__device__ __align__(16) bf16 g_al[ML_*D_];
__device__ __align__(16) bf16 g_qvh[ML_*NQKV];
__device__ __align__(16) bf16 g_qvl[ML_*NQKV];
__device__ __align__(16) bf16 g_fh[ML_*DFF_];
__device__ __align__(16) bf16 g_fl[ML_*DFF_];
#define WT_LAYER (4*512*512 + 2048*512 + 512*2048)
__device__ __align__(16) bf16 g_wth[NL_*WT_LAYER];
__device__ __align__(16) bf16 g_wtl[NL_*WT_LAYER];
__device__ __align__(16) unsigned char g_bk[B_*L_*L_];
__device__ float g_bqkv[NL_*NQKV];

// ====================== PTX helpers ======================
__device__ __forceinline__ uint32_t smem_u32(const void* p) {
    uint32_t a;
    asm("{ .reg .u64 t; cvta.to.shared.u64 t, %1; cvt.u32.u64 %0, t; }" : "=r"(a) : "l"(p));
    return a;
}
__device__ __forceinline__ void cp16(uint32_t s, const void* g) {
    asm volatile("cp.async.cg.shared.global [%0], [%1], 16;" :: "r"(s), "l"(g));
}
__device__ __forceinline__ void ldsm4(uint32_t* r, uint32_t a) {
    asm volatile("ldmatrix.sync.aligned.m8n8.x4.shared.b16 {%0,%1,%2,%3}, [%4];"
        : "=r"(r[0]), "=r"(r[1]), "=r"(r[2]), "=r"(r[3]) : "r"(a));
}
__device__ __forceinline__ void ldsm4t(uint32_t* r, uint32_t a) {
    asm volatile("ldmatrix.sync.aligned.m8n8.x4.trans.shared.b16 {%0,%1,%2,%3}, [%4];"
        : "=r"(r[0]), "=r"(r[1]), "=r"(r[2]), "=r"(r[3]) : "r"(a));
}
__device__ __forceinline__ void mma16816(float* c, const uint32_t* a, const uint32_t* b) {
    asm volatile("mma.sync.aligned.m16n8k16.row.col.f32.bf16.bf16.f32 "
        "{%0,%1,%2,%3}, {%4,%5,%6,%7}, {%8,%9}, {%0,%1,%2,%3};"
        : "+f"(c[0]), "+f"(c[1]), "+f"(c[2]), "+f"(c[3])
        : "r"(a[0]), "r"(a[1]), "r"(a[2]), "r"(a[3]), "r"(b[0]), "r"(b[1]));
}

__device__ __forceinline__ void pack_hilo(float x, float y, uint32_t& h, uint32_t& l) {
    bf16 hx = __float2bfloat16_rn(x), hy = __float2bfloat16_rn(y);
    __nv_bfloat162 th = __halves2bfloat162(hx, hy);
    h = *(uint32_t*)&th;
    __nv_bfloat162 tl = __halves2bfloat162(
        __float2bfloat16_rn(x - __bfloat162float(hx)),
        __float2bfloat16_rn(y - __bfloat162float(hy)));
    l = *(uint32_t*)&tl;
}
__device__ __forceinline__ void split_store(bf16* Oh, bf16* Ol, size_t off, float v0, float v1) {
    uint32_t h, l;
    pack_hilo(v0, v1, h, l);
    *(uint32_t*)(Oh + off) = h;
    *(uint32_t*)(Ol + off) = l;
}

// ====================== time bucket ======================
__device__ __forceinline__ int time_bucket(float delta)
{
    float a = fmaxf(fabsf(delta), 1.0f);
    const float scale = 0.71018780958489f;   // float32(log2(2592000)/30)
    int idx = (int)(log2f(a) / scale) + 1;
    idx = max(1, min(idx, NB_ - 2));
    if (a <= 1.0f)       idx = 0;
    if (a >= 2592000.0f) idx = NB_ - 1;
    return idx;
}

__global__ void bucket_kernel(const float* __restrict__ ts)
{
    int idx = blockIdx.x * blockDim.x + threadIdx.x;   // over B*L*L
    int k = idx & (L_-1);
    int q = (idx >> 9) & (L_-1);
    int b = idx >> 18;
    float d = ts[b * L_ + q] - ts[b * L_ + k];
    g_bk[idx] = (unsigned char)time_bucket(d);
}

__global__ void biascat_kernel(const float* __restrict__ bq,
                               const float* __restrict__ bk,
                               const float* __restrict__ bv)
{
    int i = blockIdx.x * blockDim.x + threadIdx.x;   // NL*1536
    int l = i / NQKV, c = i % NQKV;
    float v = (c < 512) ? bq[l*512 + c] : (c < 1024 ? bk[l*512 + c - 512] : bv[l*512 + c - 1024]);
    g_bqkv[i] = v;
}

// ====================== embedding (+ bf16 split) ======================
__global__ void embed_kernel(const int* __restrict__ seq,
                             const float* __restrict__ item_emb,
                             const float* __restrict__ pos_emb)
{
    int idx = blockIdx.x * blockDim.x + threadIdx.x;   // over ML*D/4
    int d4 = idx & (D_/4 - 1);
    int bl = idx >> 7;
    int l  = bl & (L_-1);
    int it = seq[bl];
    float4 a = *(const float4*)(item_emb + (size_t)it * D_ + d4*4);
    float4 p = *(const float4*)(pos_emb  + (size_t)l  * D_ + d4*4);
    a.x += p.x; a.y += p.y; a.z += p.z; a.w += p.w;
    ((float4*)g_x)[idx] = a;
    size_t off = (size_t)idx * 4;
    split_store(g_ah, g_al, off,     a.x, a.y);
    split_store(g_ah, g_al, off + 2, a.z, a.w);
}

// ====================== weight transpose + split ======================
__global__ void conv_wt_kernel(const float* __restrict__ W,
                               bf16* __restrict__ Th, bf16* __restrict__ Tl,
                               int K, int N)
{
    __shared__ float s[32][33];
    int tx = threadIdx.x, ty = threadIdx.y;   // 32 x 8
    int n0 = blockIdx.x * 32, k0 = blockIdx.y * 32;
    #pragma unroll
    for (int j = 0; j < 32; j += 8)
        s[ty + j][tx] = W[(size_t)(k0 + ty + j) * N + n0 + tx];
    __syncthreads();
    #pragma unroll
    for (int j = 0; j < 32; j += 8) {
        int n = n0 + ty + j, k = k0 + tx;
        float v = s[tx][ty + j];
        bf16 h = __float2bfloat16_rn(v);
        bf16 l = __float2bfloat16_rn(v - __bfloat162float(h));
        Th[(size_t)n * K + k] = h;
        Tl[(size_t)n * K + k] = l;
    }
}

// ====================== HMMA GEMM (3-stage cp.async pipeline) ======================
#define TILE_B   10240
#define STAGE_B  40960
#define GSMEM    122880   // 3 stages
#define STRIDE   40

// flags: 1 = relu, 2 = write fp32 C, 4 = write split (Oh/Ol), 8 = qkv col-scale (0.125 for n<512)
__global__ __launch_bounds__(256, 1)
void gemm_hmma(const bf16* __restrict__ Ah, const bf16* __restrict__ Al,
               const bf16* __restrict__ Bh, const bf16* __restrict__ Bl,
               const float* __restrict__ bias, float* __restrict__ C,
               bf16* __restrict__ Oh, bf16* __restrict__ Ol,
               int M, int N, int K, int flags, float oscale)
{
    extern __shared__ char sm[];
    uint32_t sb = smem_u32(sm);
    int tid = threadIdx.x, lane = tid & 31, wid = tid >> 5;
    int wm = wid & 1, wn = wid >> 1;
    int m0 = blockIdx.y * 128, n0 = blockIdx.x * 128;

    int lrow = tid >> 2, lseg = tid & 3;
    const char* gAh = (const char*)(Ah + (size_t)(m0 + lrow) * K + lseg * 8);
    const char* gAl = (const char*)(Al + (size_t)(m0 + lrow) * K + lseg * 8);
    const char* gBh = (const char*)(Bh + (size_t)(n0 + lrow) * K + lseg * 8);
    const char* gBl = (const char*)(Bl + (size_t)(n0 + lrow) * K + lseg * 8);
    size_t rowskip = (size_t)64 * K * 2;
    uint32_t s0off = (uint32_t)(lrow * STRIDE + lseg * 8) * 2;
    uint32_t s1off = s0off + 64 * STRIDE * 2;

    float acc[4][4][4];
    #pragma unroll
    for (int a = 0; a < 4; a++)
        #pragma unroll
        for (int b = 0; b < 4; b++)
            #pragma unroll
            for (int c = 0; c < 4; c++) acc[a][b][c] = 0.f;

    int NC = K >> 5;

#define LOADC(cc, st) do { \
    size_t ko = (size_t)(cc) * 64; \
    uint32_t s0 = sb + (st) * STAGE_B + s0off; \
    uint32_t s1 = sb + (st) * STAGE_B + s1off; \
    cp16(s0,            gAh + ko); cp16(s1,            gAh + ko + rowskip); \
    cp16(s0 + TILE_B,   gAl + ko); cp16(s1 + TILE_B,   gAl + ko + rowskip); \
    cp16(s0 + 2*TILE_B, gBh + ko); cp16(s1 + 2*TILE_B, gBh + ko + rowskip); \
    cp16(s0 + 3*TILE_B, gBl + ko); cp16(s1 + 3*TILE_B, gBl + ko + rowskip); \
    asm volatile("cp.async.commit_group;"); \
} while (0)

    LOADC(0, 0);
    LOADC(1, 1);

    int ar = lane & 15, a8 = lane >> 4;
    int st = 0;

    for (int c = 0; c < NC; c++) {
        if (c + 2 < NC) {
            LOADC(c + 2, (c + 2) % 3);
            asm volatile("cp.async.wait_group 2;");
        } else if (c + 1 < NC) {
            asm volatile("cp.async.wait_group 1;");
        } else {
            asm volatile("cp.async.wait_group 0;");
        }
        __syncthreads();

        uint32_t tb = sb + st * STAGE_B;
        st = (st + 1 == 3) ? 0 : st + 1;
        #pragma unroll
        for (int ks = 0; ks < 2; ks++) {
            int acol = ks * 16 + a8 * 8;
            uint32_t Ahf[4][4], Alf[4][4], Bhf[4][2], Blf[4][2];
            #pragma unroll
            for (int mt = 0; mt < 4; mt++) {
                uint32_t ad = tb + (uint32_t)((wm * 64 + mt * 16 + ar) * STRIDE + acol) * 2;
                ldsm4(Ahf[mt], ad);
                ldsm4(Alf[mt], ad + TILE_B);
            }
            #pragma unroll
            for (int p = 0; p < 2; p++) {
                uint32_t bd = tb + 2 * TILE_B +
                              (uint32_t)((wn * 32 + p * 16 + ar) * STRIDE + acol) * 2;
                uint32_t t[4];
                ldsm4(t, bd);
                Bhf[2*p][0] = t[0]; Bhf[2*p][1] = t[2];
                Bhf[2*p+1][0] = t[1]; Bhf[2*p+1][1] = t[3];
                ldsm4(t, bd + TILE_B);
                Blf[2*p][0] = t[0]; Blf[2*p][1] = t[2];
                Blf[2*p+1][0] = t[1]; Blf[2*p+1][1] = t[3];
            }
            #pragma unroll
            for (int mt = 0; mt < 4; mt++)
                #pragma unroll
                for (int nt = 0; nt < 4; nt++) {
                    mma16816(acc[mt][nt], Ahf[mt], Bhf[nt]);
                    mma16816(acc[mt][nt], Alf[mt], Bhf[nt]);
                    mma16816(acc[mt][nt], Ahf[mt], Blf[nt]);
                }
        }
        __syncthreads();
    }
#undef LOADC

    int relu = flags & 1, wf = flags & 2, ws = flags & 4;
    int r_base = m0 + wm * 64 + (lane >> 2);
    int c_base = n0 + wn * 32 + (lane & 3) * 2;
    #pragma unroll
    for (int nt = 0; nt < 4; nt++) {
        int c0 = c_base + nt * 8;
        float sc = (flags & 8) ? ((c0 < 512) ? 0.125f : 1.0f) : oscale;
        float2 bv = *(const float2*)(bias + c0);
        #pragma unroll
        for (int mt = 0; mt < 4; mt++) {
            #pragma unroll
            for (int h = 0; h < 2; h++) {
                int r = r_base + mt * 16 + h * 8;
                float v0 = (acc[mt][nt][h*2+0] + bv.x) * sc;
                float v1 = (acc[mt][nt][h*2+1] + bv.y) * sc;
                if (relu) { v0 = fmaxf(v0, 0.f); v1 = fmaxf(v1, 0.f); }
                size_t off = (size_t)r * N + c0;
                if (wf) *(float2*)(C + off) = make_float2(v0, v1);
                if (ws) split_store(Oh, Ol, off, v0, v1);
            }
        }
    }
}

// ====================== HMMA flash attention (precomputed buckets) ======================
#define AQH_OFF   0
#define AQL_OFF   18432
#define ASTG_BASE 36864
#define ASTG_SZ   45056
#define AKH_OFF   0
#define AKL_OFF   9216
#define AVH_OFF   18432
#define AVL_OFF   27648
#define ABK_OFF   36864
#define ATB_OFF   (ASTG_BASE + 2*ASTG_SZ)        // 126976
#define ATTN2_SMEM (ATB_OFF + 128)               // 127104

__device__ __forceinline__ void load_kv_tile(
    uint32_t sb, const bf16* qvh, const bf16* qvl, const unsigned char* bkp,
    int b, int h, int q0, int kt, int st, int tid)
{
    uint32_t stb = sb + ASTG_BASE + st * ASTG_SZ;
    const char* gkh = (const char*)qvh + ((size_t)(b * L_) * NQKV + 512  + h * DH_) * 2;
    const char* gkl = (const char*)qvl + ((size_t)(b * L_) * NQKV + 512  + h * DH_) * 2;
    const char* gvh = (const char*)qvh + ((size_t)(b * L_) * NQKV + 1024 + h * DH_) * 2;
    const char* gvl = (const char*)qvl + ((size_t)(b * L_) * NQKV + 1024 + h * DH_) * 2;
    #pragma unroll
    for (int i = 0; i < 2; i++) {
        int idx = tid + i * 256;             // 0..511: r = idx>>3 (0..63), c = idx&7
        int r = idx >> 3, c = idx & 7;
        size_t go = (size_t)(kt * 64 + r) * (NQKV * 2) + c * 16;
        uint32_t so = (uint32_t)(r * 144 + c * 16);
        cp16(stb + AKH_OFF + so, gkh + go);
        cp16(stb + AKL_OFF + so, gkl + go);
        cp16(stb + AVH_OFF + so, gvh + go);
        cp16(stb + AVL_OFF + so, gvl + go);
    }
    #pragma unroll
    for (int i = 0; i < 2; i++) {
        int idx = tid + i * 256;             // 0..511: r = idx>>2 (0..127), c = idx&3
        int r = idx >> 2, c = idx & 3;
        size_t go = ((size_t)(b * L_ + q0 + r)) * L_ + kt * 64 + c * 16;
        cp16(stb + ABK_OFF + (uint32_t)(r * 64 + c * 16), bkp + go);
    }
    asm volatile("cp.async.commit_group;");
}

__global__ __launch_bounds__(256, 1)
void attn_mma(const bf16* __restrict__ qvh, const bf16* __restrict__ qvl,
              const unsigned char* __restrict__ bkp, const float* __restrict__ tbias,
              bf16* __restrict__ oh, bf16* __restrict__ ol)
{
    extern __shared__ char sm[];
    uint32_t sb = smem_u32(sm);
    float* smf = (float*)sm;

    int qt = blockIdx.x, h = blockIdx.y, b = blockIdx.z;
    int q0 = qt * 128;
    int tid = threadIdx.x, lane = tid & 31, wid = tid >> 5;
    int g = lane >> 2, tig = lane & 3, tig2 = tig * 2;
    int ar = lane & 15, a8 = lane >> 4;

    {
        const char* gq  = (const char*)qvh + ((size_t)(b * L_ + q0) * NQKV + h * DH_) * 2;
        const char* gq2 = (const char*)qvl + ((size_t)(b * L_ + q0) * NQKV + h * DH_) * 2;
        #pragma unroll
        for (int i = 0; i < 4; i++) {
            int idx = tid + i * 256;
            int r = idx >> 3, c = idx & 7;
            size_t go = (size_t)r * (NQKV * 2) + c * 16;
            uint32_t so = (uint32_t)(r * 144 + c * 16);
            cp16(sb + AQH_OFF + so, gq + go);
            cp16(sb + AQL_OFF + so, gq2 + go);
        }
    }
    if (tid < NB_) smf[ATB_OFF/4 + tid] = tbias[tid * H_ + h];

    int nkt = 2 * qt + 2;
    load_kv_tile(sb, qvh, qvl, bkp, b, h, q0, 0, 0, tid);

    int qg0 = q0 + wid * 16 + g, qg1 = qg0 + 8;
    int r0l = wid * 16 + g, r1l = r0l + 8;
    float m0 = -1e30f, m1 = -1e30f, l0 = 0.f, l1 = 0.f;
    float acc_o[8][4];
    #pragma unroll
    for (int nt = 0; nt < 8; nt++)
        #pragma unroll
        for (int i = 0; i < 4; i++) acc_o[nt][i] = 0.f;

    uint32_t qhf[4][4], qlf[4][4];
    asm volatile("cp.async.wait_group 0;");
    __syncthreads();
    #pragma unroll
    for (int kc = 0; kc < 4; kc++) {
        uint32_t ad = sb + AQH_OFF + (uint32_t)((wid * 16 + ar) * 72 + kc * 16 + a8 * 8) * 2;
        ldsm4(qhf[kc], ad);
        ldsm4(qlf[kc], ad + (AQL_OFF - AQH_OFF));
    }

    const float* tb = (const float*)(sm + ATB_OFF);

    for (int kt = 0; kt < nkt; kt++) {
        int st = kt & 1;
        if (kt + 1 < nkt) {
            load_kv_tile(sb, qvh, qvl, bkp, b, h, q0, kt + 1, st ^ 1, tid);
            asm volatile("cp.async.wait_group 1;");
        } else {
            asm volatile("cp.async.wait_group 0;");
        }
        __syncthreads();

        uint32_t stb = sb + ASTG_BASE + st * ASTG_SZ;
        const unsigned char* bkt = (const unsigned char*)(sm + ASTG_BASE + st * ASTG_SZ + ABK_OFF);

        float S[8][4];
        #pragma unroll
        for (int nt = 0; nt < 8; nt++)
            #pragma unroll
            for (int i = 0; i < 4; i++) S[nt][i] = 0.f;

        #pragma unroll
        for (int kc = 0; kc < 4; kc++) {
            #pragma unroll
            for (int nt2 = 0; nt2 < 4; nt2++) {
                uint32_t kd = stb + AKH_OFF + (uint32_t)((nt2 * 16 + ar) * 72 + kc * 16 + a8 * 8) * 2;
                uint32_t th[4], tl[4];
                ldsm4(th, kd);
                ldsm4(tl, kd + (AKL_OFF - AKH_OFF));
                uint32_t b0h[2] = {th[0], th[2]}, b1h[2] = {th[1], th[3]};
                uint32_t b0l[2] = {tl[0], tl[2]}, b1l[2] = {tl[1], tl[3]};
                mma16816(S[2*nt2],   qhf[kc], b0h);
                mma16816(S[2*nt2],   qlf[kc], b0h);
                mma16816(S[2*nt2],   qhf[kc], b0l);
                mma16816(S[2*nt2+1], qhf[kc], b1h);
                mma16816(S[2*nt2+1], qlf[kc], b1h);
                mma16816(S[2*nt2+1], qhf[kc], b1l);
            }
        }

        bool needMask = (kt >= 2 * qt);
        float mx0 = -1e30f, mx1 = -1e30f;
        #pragma unroll
        for (int nt = 0; nt < 8; nt++) {
            int colb = nt * 8 + tig2;
            uint32_t pb0 = *(const unsigned short*)(bkt + r0l * 64 + colb);
            uint32_t pb1 = *(const unsigned short*)(bkt + r1l * 64 + colb);
            float s0a = S[nt][0] + tb[pb0 & 0xFF];
            float s0b = S[nt][1] + tb[pb0 >> 8];
            float s1a = S[nt][2] + tb[pb1 & 0xFF];
            float s1b = S[nt][3] + tb[pb1 >> 8];
            if (needMask) {
                int kg = kt * 64 + colb;
                if (kg     > qg0) s0a = -1e30f;
                if (kg + 1 > qg0) s0b = -1e30f;
                if (kg     > qg1) s1a = -1e30f;
                if (kg + 1 > qg1) s1b = -1e30f;
            }
            S[nt][0] = s0a; S[nt][1] = s0b; S[nt][2] = s1a; S[nt][3] = s1b;
            mx0 = fmaxf(mx0, fmaxf(s0a, s0b));
            mx1 = fmaxf(mx1, fmaxf(s1a, s1b));
        }
        mx0 = fmaxf(mx0, __shfl_xor_sync(~0u, mx0, 1));
        mx0 = fmaxf(mx0, __shfl_xor_sync(~0u, mx0, 2));
        mx1 = fmaxf(mx1, __shfl_xor_sync(~0u, mx1, 1));
        mx1 = fmaxf(mx1, __shfl_xor_sync(~0u, mx1, 2));
        float mn0 = fmaxf(m0, mx0), mn1 = fmaxf(m1, mx1);
        float rs0 = __expf(m0 - mn0), rs1 = __expf(m1 - mn1);
        m0 = mn0; m1 = mn1;

        float sum0 = 0.f, sum1 = 0.f;
        #pragma unroll
        for (int nt = 0; nt < 8; nt++) {
            float p0 = __expf(S[nt][0] - mn0);
            float p1 = __expf(S[nt][1] - mn0);
            float p2 = __expf(S[nt][2] - mn1);
            float p3 = __expf(S[nt][3] - mn1);
            S[nt][0] = p0; S[nt][1] = p1; S[nt][2] = p2; S[nt][3] = p3;
            sum0 += p0 + p1; sum1 += p2 + p3;
        }
        sum0 += __shfl_xor_sync(~0u, sum0, 1); sum0 += __shfl_xor_sync(~0u, sum0, 2);
        sum1 += __shfl_xor_sync(~0u, sum1, 1); sum1 += __shfl_xor_sync(~0u, sum1, 2);
        l0 = l0 * rs0 + sum0;
        l1 = l1 * rs1 + sum1;
        #pragma unroll
        for (int nt = 0; nt < 8; nt++) {
            acc_o[nt][0] *= rs0; acc_o[nt][1] *= rs0;
            acc_o[nt][2] *= rs1; acc_o[nt][3] *= rs1;
        }

        #pragma unroll
        for (int t = 0; t < 4; t++) {
            uint32_t aph[4], apl[4];
            pack_hilo(S[2*t][0],   S[2*t][1],   aph[0], apl[0]);
            pack_hilo(S[2*t][2],   S[2*t][3],   aph[1], apl[1]);
            pack_hilo(S[2*t+1][0], S[2*t+1][1], aph[2], apl[2]);
            pack_hilo(S[2*t+1][2], S[2*t+1][3], aph[3], apl[3]);
            #pragma unroll
            for (int j2 = 0; j2 < 4; j2++) {
                uint32_t vd = stb + AVH_OFF + (uint32_t)((t * 16 + ar) * 72 + j2 * 16 + a8 * 8) * 2;
                uint32_t th[4], tl[4];
                ldsm4t(th, vd);
                ldsm4t(tl, vd + (AVL_OFF - AVH_OFF));
                uint32_t bh0[2] = {th[0], th[1]}, bh1[2] = {th[2], th[3]};
                uint32_t bl0[2] = {tl[0], tl[1]}, bl1[2] = {tl[2], tl[3]};
                mma16816(acc_o[2*j2],   aph, bh0);
                mma16816(acc_o[2*j2],   apl, bh0);
                mma16816(acc_o[2*j2],   aph, bl0);
                mma16816(acc_o[2*j2+1], aph, bh1);
                mma16816(acc_o[2*j2+1], apl, bh1);
                mma16816(acc_o[2*j2+1], aph, bl1);
            }
        }
        __syncthreads();
    }

    float inv0 = 1.0f / l0, inv1 = 1.0f / l1;
    size_t row0 = ((size_t)(b * L_ + qg0)) * D_ + h * DH_;
    size_t row1 = ((size_t)(b * L_ + qg1)) * D_ + h * DH_;
    #pragma unroll
    for (int nt = 0; nt < 8; nt++) {
        int cc = nt * 8 + tig2;
        split_store(oh, ol, row0 + cc, acc_o[nt][0] * inv0, acc_o[nt][1] * inv0);
        split_store(oh, ol, row1 + cc, acc_o[nt][2] * inv1, acc_o[nt][3] * inv1);
    }
}

// ====================== fused residual add + LayerNorm (+ optional split) ======================
__global__ __launch_bounds__(128)
void add_ln_kernel(const float* __restrict__ xin, const float* __restrict__ res,
                   const float* __restrict__ g, const float* __restrict__ bb,
                   float* __restrict__ xout,
                   bf16* __restrict__ oh, bf16* __restrict__ ol, int writeSplit)
{
    __shared__ float sy[D_];
    __shared__ float red[4];
    int row = blockIdx.x;
    int tid = threadIdx.x;
    int lane = tid & 31, w = tid >> 5;

    const float* xr = xin + (size_t)row * D_;
    const float* rr = res + (size_t)row * D_;

    float lsum = 0.f;
    #pragma unroll
    for (int i = 0; i < 4; i++) {
        int d = tid + i * 128;
        float val = xr[d] + rr[d];
        sy[d] = val;
        lsum += val;
    }
    #pragma unroll
    for (int o = 16; o > 0; o >>= 1) lsum += __shfl_xor_sync(~0u, lsum, o);
    if (lane == 0) red[w] = lsum;
    __syncthreads();
    float mean = (red[0] + red[1] + red[2] + red[3]) * (1.0f / D_);
    __syncthreads();

    float lv = 0.f;
    #pragma unroll
    for (int i = 0; i < 4; i++) {
        int d = tid + i * 128;
        float c = sy[d] - mean;
        lv += c * c;
    }
    #pragma unroll
    for (int o = 16; o > 0; o >>= 1) lv += __shfl_xor_sync(~0u, lv, o);
    if (lane == 0) red[w] = lv;
    __syncthreads();
    float var = (red[0] + red[1] + red[2] + red[3]) * (1.0f / D_);
    float inv = rsqrtf(var + 1e-5f);

    #pragma unroll
    for (int i = 0; i < 4; i++) {
        int d = tid + i * 128;
        float val = (sy[d] - mean) * inv * g[d] + bb[d];
        xout[(size_t)row * D_ + d] = val;
        if (writeSplit) {
            size_t off = (size_t)row * D_ + d;
            bf16 hh = __float2bfloat16_rn(val);
            oh[off] = hh;
            ol[off] = __float2bfloat16_rn(val - __bfloat162float(hh));
        }
    }
}

// ====================== launch ======================
extern "C" void kernel_launch(void* const* d_in, const int* in_sizes, int n_in,
                              void* d_out, int out_size)
{
    const int*   seq      = (const int*)  d_in[0];
    const float* ts       = (const float*)d_in[1];
    const float* item_emb = (const float*)d_in[2];
    const float* pos_emb  = (const float*)d_in[3];
    const float* Wq  = (const float*)d_in[4];  const float* bq  = (const float*)d_in[5];
    const float* Wk  = (const float*)d_in[6];  const float* bk  = (const float*)d_in[7];
    const float* Wv  = (const float*)d_in[8];  const float* bv  = (const float*)d_in[9];
    const float* tbias = (const float*)d_in[10];
    const float* Wo  = (const float*)d_in[11]; const float* bo  = (const float*)d_in[12];
    const float* g1  = (const float*)d_in[13]; const float* be1 = (const float*)d_in[14];
    const float* W1  = (const float*)d_in[15]; const float* bf1 = (const float*)d_in[16];
    const float* W2  = (const float*)d_in[17]; const float* bf2 = (const float*)d_in[18];
    const float* g2  = (const float*)d_in[19]; const float* be2 = (const float*)d_in[20];

    float *x, *po, *bqkv;
    bf16 *ah, *al, *qvh, *qvl, *fh, *fl, *wth, *wtl;
    unsigned char* bkptr;
    cudaGetSymbolAddress((void**)&x,  g_x);
    cudaGetSymbolAddress((void**)&po, g_po);
    cudaGetSymbolAddress((void**)&ah, g_ah);
    cudaGetSymbolAddress((void**)&al, g_al);
    cudaGetSymbolAddress((void**)&qvh, g_qvh);
    cudaGetSymbolAddress((void**)&qvl, g_qvl);
    cudaGetSymbolAddress((void**)&fh, g_fh);
    cudaGetSymbolAddress((void**)&fl, g_fl);
    cudaGetSymbolAddress((void**)&wth, g_wth);
    cudaGetSymbolAddress((void**)&wtl, g_wtl);
    cudaGetSymbolAddress((void**)&bkptr, g_bk);
    cudaGetSymbolAddress((void**)&bqkv, g_bqkv);

    cudaFuncSetAttribute(attn_mma,  cudaFuncAttributeMaxDynamicSharedMemorySize, ATTN2_SMEM);
    cudaFuncSetAttribute(gemm_hmma, cudaFuncAttributeMaxDynamicSharedMemorySize, GSMEM);

    const size_t OQ = 0, OO = 786432, O1 = 1048576, O2 = 2097152;
    dim3 t32(32, 8);
    dim3 gQKV(NQKV / 128, ML_ / 128);  // (12, 128)
    dim3 gD(D_ / 128, ML_ / 128);      // (4, 128)
    dim3 gF(DFF_ / 128, ML_ / 128);    // (16, 128)
    dim3 ga(L_ / 128, H_, B_);         // (4, 8, 32)

    // --- launches 1..5: minimum prerequisites for the layer-0 QKV GEMM ---
    conv_wt_kernel<<<dim3(16, 16), t32>>>(Wq, wth+0,      wtl+0,      512, 512);
    conv_wt_kernel<<<dim3(16, 16), t32>>>(Wk, wth+262144, wtl+262144, 512, 512);
    conv_wt_kernel<<<dim3(16, 16), t32>>>(Wv, wth+524288, wtl+524288, 512, 512);
    biascat_kernel<<<(NL_*NQKV)/256, 256>>>(bq, bk, bv);
    embed_kernel<<<(ML_ * D_ / 4) / 256, 256>>>(seq, item_emb, pos_emb);

    // --- launch 6: the big fused QKV GEMM (profiled by ncu -s 5 -c 1) ---
    gemm_hmma<<<gQKV, 256, GSMEM>>>(ah, al, wth+OQ, wtl+OQ, bqkv,
                                    0, qvh, qvl, ML_, NQKV, D_, 4|8, 1.0f);

    // --- remaining prep ---
    bucket_kernel<<<(B_*L_*L_)/256, 256>>>(ts);
    conv_wt_kernel<<<dim3(16, 16), t32>>>(Wo, wth+OO, wtl+OO, 512, 512);
    conv_wt_kernel<<<dim3(64, 16), t32>>>(W1, wth+O1, wtl+O1, 512, 2048);
    conv_wt_kernel<<<dim3(16, 64), t32>>>(W2, wth+O2, wtl+O2, 2048, 512);
    {
        size_t wb = WT_LAYER;
        conv_wt_kernel<<<dim3(16, 16), t32>>>(Wq + (size_t)D_*D_,   wth+wb+0,      wtl+wb+0,      512, 512);
        conv_wt_kernel<<<dim3(16, 16), t32>>>(Wk + (size_t)D_*D_,   wth+wb+262144, wtl+wb+262144, 512, 512);
        conv_wt_kernel<<<dim3(16, 16), t32>>>(Wv + (size_t)D_*D_,   wth+wb+524288, wtl+wb+524288, 512, 512);
        conv_wt_kernel<<<dim3(16, 16), t32>>>(Wo + (size_t)D_*D_,   wth+wb+OO, wtl+wb+OO, 512, 512);
        conv_wt_kernel<<<dim3(64, 16), t32>>>(W1 + (size_t)D_*DFF_, wth+wb+O1, wtl+wb+O1, 512, 2048);
        conv_wt_kernel<<<dim3(16, 64), t32>>>(W2 + (size_t)DFF_*D_, wth+wb+O2, wtl+wb+O2, 2048, 512);
    }

    for (int i = 0; i < NL_; i++) {
        size_t wb = (size_t)i * WT_LAYER;

        if (i > 0) {
            gemm_hmma<<<gQKV, 256, GSMEM>>>(ah, al, wth+wb+OQ, wtl+wb+OQ, bqkv + i*NQKV,
                                            0, qvh, qvl, ML_, NQKV, D_, 4|8, 1.0f);
        }

        attn_mma<<<ga, 256, ATTN2_SMEM>>>(qvh, qvl, bkptr, tbias + (size_t)i*NB_*H_, ah, al);

        gemm_hmma<<<gD, 256, GSMEM>>>(ah, al, wth+wb+OO, wtl+wb+OO, bo + i*D_, po, 0, 0, ML_, D_, D_, 2, 1.0f);
        add_ln_kernel<<<ML_, 128>>>(x, po, g1 + i*D_, be1 + i*D_, x, ah, al, 1);

        gemm_hmma<<<gF, 256, GSMEM>>>(ah, al, wth+wb+O1, wtl+wb+O1, bf1 + i*DFF_, 0, fh, fl, ML_, DFF_, D_, 5, 1.0f);
        gemm_hmma<<<gD, 256, GSMEM>>>(fh, fl, wth+wb+O2, wtl+wb+O2, bf2 + i*D_, po, 0, 0, ML_, D_, DFF_, 2, 1.0f);

        float* xo = (i == NL_ - 1) ? (float*)d_out : x;
        add_ln_kernel<<<ML_, 128>>>(x, po, g2 + i*D_, be2 + i*D_, xo, ah, al, (i < NL_ - 1) ? 1 : 0);
    }
}

// round 8
// speedup vs baseline: 3.1115x; 1.3028x over previous
#include <cuda_runtime.h>
#include <cuda_bf16.h>
#include <cuda_fp16.h>
#include <math.h>
#include <stdint.h>

#define B_   32
#define L_   512
#define D_   512
#define H_   8
#define DH_  64
#define NL_  2
#define DFF_ 2048
#define NB_  32
#define ML_  (B_*L_)   // 16384 rows
#define NQKV 1536

typedef __nv_bfloat16 bf16;

// ---------------- scratch (device globals; no allocations) ----------------
__device__ float g_x [ML_*D_];
__device__ float g_po[ML_*D_];
// fp16 hi/lo split activations (GEMM A operands)
__device__ __align__(16) __half g_ah[ML_*D_];
__device__ __align__(16) __half g_al[ML_*D_];
__device__ __align__(16) __half g_fh[ML_*DFF_];
__device__ __align__(16) __half g_fl[ML_*DFF_];
// bf16 hi/lo split QKV (attention operands, 3-term path)
__device__ __align__(16) bf16 g_qvh[ML_*NQKV];
__device__ __align__(16) bf16 g_qvl[ML_*NQKV];
// fp16 transposed weights (single precision level)
#define WT_LAYER (4*512*512 + 2048*512 + 512*2048)
__device__ __align__(16) __half g_wth[NL_*WT_LAYER];
// precomputed time-bucket indices [B][L][L]
__device__ __align__(16) unsigned char g_bk[B_*L_*L_];
__device__ float g_bqkv[NL_*NQKV];

// ====================== PTX helpers ======================
__device__ __forceinline__ uint32_t smem_u32(const void* p) {
    uint32_t a;
    asm("{ .reg .u64 t; cvta.to.shared.u64 t, %1; cvt.u32.u64 %0, t; }" : "=r"(a) : "l"(p));
    return a;
}
__device__ __forceinline__ void cp16(uint32_t s, const void* g) {
    asm volatile("cp.async.cg.shared.global [%0], [%1], 16;" :: "r"(s), "l"(g));
}
__device__ __forceinline__ void ldsm4(uint32_t* r, uint32_t a) {
    asm volatile("ldmatrix.sync.aligned.m8n8.x4.shared.b16 {%0,%1,%2,%3}, [%4];"
        : "=r"(r[0]), "=r"(r[1]), "=r"(r[2]), "=r"(r[3]) : "r"(a));
}
__device__ __forceinline__ void ldsm4t(uint32_t* r, uint32_t a) {
    asm volatile("ldmatrix.sync.aligned.m8n8.x4.trans.shared.b16 {%0,%1,%2,%3}, [%4];"
        : "=r"(r[0]), "=r"(r[1]), "=r"(r[2]), "=r"(r[3]) : "r"(a));
}
// bf16 MMA (attention path)
__device__ __forceinline__ void mma16816(float* c, const uint32_t* a, const uint32_t* b) {
    asm volatile("mma.sync.aligned.m16n8k16.row.col.f32.bf16.bf16.f32 "
        "{%0,%1,%2,%3}, {%4,%5,%6,%7}, {%8,%9}, {%0,%1,%2,%3};"
        : "+f"(c[0]), "+f"(c[1]), "+f"(c[2]), "+f"(c[3])
        : "r"(a[0]), "r"(a[1]), "r"(a[2]), "r"(a[3]), "r"(b[0]), "r"(b[1]));
}
// fp16 MMA (linear GEMM path)
__device__ __forceinline__ void mma16816h(float* c, const uint32_t* a, const uint32_t* b) {
    asm volatile("mma.sync.aligned.m16n8k16.row.col.f32.f16.f16.f32 "
        "{%0,%1,%2,%3}, {%4,%5,%6,%7}, {%8,%9}, {%0,%1,%2,%3};"
        : "+f"(c[0]), "+f"(c[1]), "+f"(c[2]), "+f"(c[3])
        : "r"(a[0]), "r"(a[1]), "r"(a[2]), "r"(a[3]), "r"(b[0]), "r"(b[1]));
}

// ---- bf16 hi/lo pack (attention / QKV output) ----
__device__ __forceinline__ void pack_hilo(float x, float y, uint32_t& h, uint32_t& l) {
    bf16 hx = __float2bfloat16_rn(x), hy = __float2bfloat16_rn(y);
    __nv_bfloat162 th = __halves2bfloat162(hx, hy);
    h = *(uint32_t*)&th;
    __nv_bfloat162 tl = __halves2bfloat162(
        __float2bfloat16_rn(x - __bfloat162float(hx)),
        __float2bfloat16_rn(y - __bfloat162float(hy)));
    l = *(uint32_t*)&tl;
}
__device__ __forceinline__ void split_store_bf(bf16* Oh, bf16* Ol, size_t off, float v0, float v1) {
    uint32_t h, l;
    pack_hilo(v0, v1, h, l);
    *(uint32_t*)(Oh + off) = h;
    *(uint32_t*)(Ol + off) = l;
}
// ---- fp16 hi/lo pack (GEMM A operands) ----
__device__ __forceinline__ void pack_hilo_f16(float x, float y, uint32_t& h, uint32_t& l) {
    __half hx = __float2half_rn(x), hy = __float2half_rn(y);
    __half2 th = __halves2half2(hx, hy);
    h = *(uint32_t*)&th;
    __half2 tl = __halves2half2(
        __float2half_rn(x - __half2float(hx)),
        __float2half_rn(y - __half2float(hy)));
    l = *(uint32_t*)&tl;
}
__device__ __forceinline__ void split_store_f16(__half* Oh, __half* Ol, size_t off, float v0, float v1) {
    uint32_t h, l;
    pack_hilo_f16(v0, v1, h, l);
    *(uint32_t*)(Oh + off) = h;
    *(uint32_t*)(Ol + off) = l;
}

// ====================== time bucket ======================
__device__ __forceinline__ int time_bucket(float delta)
{
    float a = fmaxf(fabsf(delta), 1.0f);
    const float scale = 0.71018780958489f;   // float32(log2(2592000)/30)
    int idx = (int)(log2f(a) / scale) + 1;
    idx = max(1, min(idx, NB_ - 2));
    if (a <= 1.0f)       idx = 0;
    if (a >= 2592000.0f) idx = NB_ - 1;
    return idx;
}

__global__ void bucket_kernel(const float* __restrict__ ts)
{
    int idx = blockIdx.x * blockDim.x + threadIdx.x;   // over B*L*L
    int k = idx & (L_-1);
    int q = (idx >> 9) & (L_-1);
    int b = idx >> 18;
    float d = ts[b * L_ + q] - ts[b * L_ + k];
    g_bk[idx] = (unsigned char)time_bucket(d);
}

__global__ void biascat_kernel(const float* __restrict__ bq,
                               const float* __restrict__ bk,
                               const float* __restrict__ bv)
{
    int i = blockIdx.x * blockDim.x + threadIdx.x;   // NL*1536
    int l = i / NQKV, c = i % NQKV;
    float v = (c < 512) ? bq[l*512 + c] : (c < 1024 ? bk[l*512 + c - 512] : bv[l*512 + c - 1024]);
    g_bqkv[i] = v;
}

// ====================== embedding (+ fp16 split) ======================
__global__ void embed_kernel(const int* __restrict__ seq,
                             const float* __restrict__ item_emb,
                             const float* __restrict__ pos_emb)
{
    int idx = blockIdx.x * blockDim.x + threadIdx.x;   // over ML*D/4
    int d4 = idx & (D_/4 - 1);
    int bl = idx >> 7;
    int l  = bl & (L_-1);
    int it = seq[bl];
    float4 a = *(const float4*)(item_emb + (size_t)it * D_ + d4*4);
    float4 p = *(const float4*)(pos_emb  + (size_t)l  * D_ + d4*4);
    a.x += p.x; a.y += p.y; a.z += p.z; a.w += p.w;
    ((float4*)g_x)[idx] = a;
    size_t off = (size_t)idx * 4;
    split_store_f16(g_ah, g_al, off,     a.x, a.y);
    split_store_f16(g_ah, g_al, off + 2, a.z, a.w);
}

// ====================== weight transpose (fp16) ======================
__global__ void conv_wt_kernel(const float* __restrict__ W,
                               __half* __restrict__ Th, int K, int N)
{
    __shared__ float s[32][33];
    int tx = threadIdx.x, ty = threadIdx.y;   // 32 x 8
    int n0 = blockIdx.x * 32, k0 = blockIdx.y * 32;
    #pragma unroll
    for (int j = 0; j < 32; j += 8)
        s[ty + j][tx] = W[(size_t)(k0 + ty + j) * N + n0 + tx];
    __syncthreads();
    #pragma unroll
    for (int j = 0; j < 32; j += 8) {
        int n = n0 + ty + j, k = k0 + tx;
        Th[(size_t)n * K + k] = __float2half_rn(s[tx][ty + j]);
    }
}

// ====================== fp16 HMMA GEMM (2-term: (Ah+Al)·Bh) ======================
#define TILE_B   10240
#define STAGE_B  30720   // 3 tiles (Ah, Al, Bh)
#define GSMEM    92160   // 3 stages
#define STRIDE   40

// flags: 1 = relu, 2 = write fp32 C, 4 = write split, 8 = qkv col-scale, 16 = split in bf16
__global__ __launch_bounds__(256, 1)
void gemm_hmma(const __half* __restrict__ Ah, const __half* __restrict__ Al,
               const __half* __restrict__ Bh,
               const float* __restrict__ bias, float* __restrict__ C,
               void* __restrict__ Oh, void* __restrict__ Ol,
               int M, int N, int K, int flags, float oscale)
{
    extern __shared__ char sm[];
    uint32_t sb = smem_u32(sm);
    int tid = threadIdx.x, lane = tid & 31, wid = tid >> 5;
    int wm = wid & 1, wn = wid >> 1;
    int m0 = blockIdx.y * 128, n0 = blockIdx.x * 128;

    int lrow = tid >> 2, lseg = tid & 3;
    const char* gAh = (const char*)(Ah + (size_t)(m0 + lrow) * K + lseg * 8);
    const char* gAl = (const char*)(Al + (size_t)(m0 + lrow) * K + lseg * 8);
    const char* gBh = (const char*)(Bh + (size_t)(n0 + lrow) * K + lseg * 8);
    size_t rowskip = (size_t)64 * K * 2;
    uint32_t s0off = (uint32_t)(lrow * STRIDE + lseg * 8) * 2;
    uint32_t s1off = s0off + 64 * STRIDE * 2;

    float acc[4][4][4];
    #pragma unroll
    for (int a = 0; a < 4; a++)
        #pragma unroll
        for (int b = 0; b < 4; b++)
            #pragma unroll
            for (int c = 0; c < 4; c++) acc[a][b][c] = 0.f;

    int NC = K >> 5;

#define LOADC(cc, st) do { \
    size_t ko = (size_t)(cc) * 64; \
    uint32_t s0 = sb + (st) * STAGE_B + s0off; \
    uint32_t s1 = sb + (st) * STAGE_B + s1off; \
    cp16(s0,            gAh + ko); cp16(s1,            gAh + ko + rowskip); \
    cp16(s0 + TILE_B,   gAl + ko); cp16(s1 + TILE_B,   gAl + ko + rowskip); \
    cp16(s0 + 2*TILE_B, gBh + ko); cp16(s1 + 2*TILE_B, gBh + ko + rowskip); \
    asm volatile("cp.async.commit_group;"); \
} while (0)

    LOADC(0, 0);
    LOADC(1, 1);

    int ar = lane & 15, a8 = lane >> 4;
    int st = 0;

    for (int c = 0; c < NC; c++) {
        if (c + 2 < NC) {
            LOADC(c + 2, (c + 2) % 3);
            asm volatile("cp.async.wait_group 2;");
        } else if (c + 1 < NC) {
            asm volatile("cp.async.wait_group 1;");
        } else {
            asm volatile("cp.async.wait_group 0;");
        }
        __syncthreads();

        uint32_t tb = sb + st * STAGE_B;
        st = (st + 1 == 3) ? 0 : st + 1;
        #pragma unroll
        for (int ks = 0; ks < 2; ks++) {
            int acol = ks * 16 + a8 * 8;
            uint32_t Ahf[4][4], Alf[4][4], Bhf[4][2];
            #pragma unroll
            for (int mt = 0; mt < 4; mt++) {
                uint32_t ad = tb + (uint32_t)((wm * 64 + mt * 16 + ar) * STRIDE + acol) * 2;
                ldsm4(Ahf[mt], ad);
                ldsm4(Alf[mt], ad + TILE_B);
            }
            #pragma unroll
            for (int p = 0; p < 2; p++) {
                uint32_t bd = tb + 2 * TILE_B +
                              (uint32_t)((wn * 32 + p * 16 + ar) * STRIDE + acol) * 2;
                uint32_t t[4];
                ldsm4(t, bd);
                Bhf[2*p][0] = t[0]; Bhf[2*p][1] = t[2];
                Bhf[2*p+1][0] = t[1]; Bhf[2*p+1][1] = t[3];
            }
            #pragma unroll
            for (int mt = 0; mt < 4; mt++)
                #pragma unroll
                for (int nt = 0; nt < 4; nt++) {
                    mma16816h(acc[mt][nt], Ahf[mt], Bhf[nt]);
                    mma16816h(acc[mt][nt], Alf[mt], Bhf[nt]);
                }
        }
        __syncthreads();
    }
#undef LOADC

    int relu = flags & 1, wf = flags & 2, ws = flags & 4, bfmode = flags & 16;
    int r_base = m0 + wm * 64 + (lane >> 2);
    int c_base = n0 + wn * 32 + (lane & 3) * 2;
    #pragma unroll
    for (int nt = 0; nt < 4; nt++) {
        int c0 = c_base + nt * 8;
        float sc = (flags & 8) ? ((c0 < 512) ? 0.125f : 1.0f) : oscale;
        float2 bv = *(const float2*)(bias + c0);
        #pragma unroll
        for (int mt = 0; mt < 4; mt++) {
            #pragma unroll
            for (int h = 0; h < 2; h++) {
                int r = r_base + mt * 16 + h * 8;
                float v0 = (acc[mt][nt][h*2+0] + bv.x) * sc;
                float v1 = (acc[mt][nt][h*2+1] + bv.y) * sc;
                if (relu) { v0 = fmaxf(v0, 0.f); v1 = fmaxf(v1, 0.f); }
                size_t off = (size_t)r * N + c0;
                if (wf) *(float2*)(C + off) = make_float2(v0, v1);
                if (ws) {
                    if (bfmode) split_store_bf((bf16*)Oh, (bf16*)Ol, off, v0, v1);
                    else        split_store_f16((__half*)Oh, (__half*)Ol, off, v0, v1);
                }
            }
        }
    }
}

// ====================== HMMA flash attention (bf16 3-term, precomputed buckets) ======================
#define AQH_OFF   0
#define AQL_OFF   18432
#define ASTG_BASE 36864
#define ASTG_SZ   45056
#define AKH_OFF   0
#define AKL_OFF   9216
#define AVH_OFF   18432
#define AVL_OFF   27648
#define ABK_OFF   36864
#define ATB_OFF   (ASTG_BASE + 2*ASTG_SZ)        // 126976
#define ATTN2_SMEM (ATB_OFF + 128)               // 127104

__device__ __forceinline__ void load_kv_tile(
    uint32_t sb, const bf16* qvh, const bf16* qvl, const unsigned char* bkp,
    int b, int h, int q0, int kt, int st, int tid)
{
    uint32_t stb = sb + ASTG_BASE + st * ASTG_SZ;
    const char* gkh = (const char*)qvh + ((size_t)(b * L_) * NQKV + 512  + h * DH_) * 2;
    const char* gkl = (const char*)qvl + ((size_t)(b * L_) * NQKV + 512  + h * DH_) * 2;
    const char* gvh = (const char*)qvh + ((size_t)(b * L_) * NQKV + 1024 + h * DH_) * 2;
    const char* gvl = (const char*)qvl + ((size_t)(b * L_) * NQKV + 1024 + h * DH_) * 2;
    #pragma unroll
    for (int i = 0; i < 2; i++) {
        int idx = tid + i * 256;
        int r = idx >> 3, c = idx & 7;
        size_t go = (size_t)(kt * 64 + r) * (NQKV * 2) + c * 16;
        uint32_t so = (uint32_t)(r * 144 + c * 16);
        cp16(stb + AKH_OFF + so, gkh + go);
        cp16(stb + AKL_OFF + so, gkl + go);
        cp16(stb + AVH_OFF + so, gvh + go);
        cp16(stb + AVL_OFF + so, gvl + go);
    }
    #pragma unroll
    for (int i = 0; i < 2; i++) {
        int idx = tid + i * 256;
        int r = idx >> 2, c = idx & 3;
        size_t go = ((size_t)(b * L_ + q0 + r)) * L_ + kt * 64 + c * 16;
        cp16(stb + ABK_OFF + (uint32_t)(r * 64 + c * 16), bkp + go);
    }
    asm volatile("cp.async.commit_group;");
}

__global__ __launch_bounds__(256, 1)
void attn_mma(const bf16* __restrict__ qvh, const bf16* __restrict__ qvl,
              const unsigned char* __restrict__ bkp, const float* __restrict__ tbias,
              __half* __restrict__ oh, __half* __restrict__ ol)
{
    extern __shared__ char sm[];
    uint32_t sb = smem_u32(sm);
    float* smf = (float*)sm;

    int qt = blockIdx.x, h = blockIdx.y, b = blockIdx.z;
    int q0 = qt * 128;
    int tid = threadIdx.x, lane = tid & 31, wid = tid >> 5;
    int g = lane >> 2, tig = lane & 3, tig2 = tig * 2;
    int ar = lane & 15, a8 = lane >> 4;

    {
        const char* gq  = (const char*)qvh + ((size_t)(b * L_ + q0) * NQKV + h * DH_) * 2;
        const char* gq2 = (const char*)qvl + ((size_t)(b * L_ + q0) * NQKV + h * DH_) * 2;
        #pragma unroll
        for (int i = 0; i < 4; i++) {
            int idx = tid + i * 256;
            int r = idx >> 3, c = idx & 7;
            size_t go = (size_t)r * (NQKV * 2) + c * 16;
            uint32_t so = (uint32_t)(r * 144 + c * 16);
            cp16(sb + AQH_OFF + so, gq + go);
            cp16(sb + AQL_OFF + so, gq2 + go);
        }
    }
    if (tid < NB_) smf[ATB_OFF/4 + tid] = tbias[tid * H_ + h];

    int nkt = 2 * qt + 2;
    load_kv_tile(sb, qvh, qvl, bkp, b, h, q0, 0, 0, tid);

    int qg0 = q0 + wid * 16 + g, qg1 = qg0 + 8;
    int r0l = wid * 16 + g, r1l = r0l + 8;
    float m0 = -1e30f, m1 = -1e30f, l0 = 0.f, l1 = 0.f;
    float acc_o[8][4];
    #pragma unroll
    for (int nt = 0; nt < 8; nt++)
        #pragma unroll
        for (int i = 0; i < 4; i++) acc_o[nt][i] = 0.f;

    uint32_t qhf[4][4], qlf[4][4];
    asm volatile("cp.async.wait_group 0;");
    __syncthreads();
    #pragma unroll
    for (int kc = 0; kc < 4; kc++) {
        uint32_t ad = sb + AQH_OFF + (uint32_t)((wid * 16 + ar) * 72 + kc * 16 + a8 * 8) * 2;
        ldsm4(qhf[kc], ad);
        ldsm4(qlf[kc], ad + (AQL_OFF - AQH_OFF));
    }

    const float* tb = (const float*)(sm + ATB_OFF);

    for (int kt = 0; kt < nkt; kt++) {
        int st = kt & 1;
        if (kt + 1 < nkt) {
            load_kv_tile(sb, qvh, qvl, bkp, b, h, q0, kt + 1, st ^ 1, tid);
            asm volatile("cp.async.wait_group 1;");
        } else {
            asm volatile("cp.async.wait_group 0;");
        }
        __syncthreads();

        uint32_t stb = sb + ASTG_BASE + st * ASTG_SZ;
        const unsigned char* bkt = (const unsigned char*)(sm + ASTG_BASE + st * ASTG_SZ + ABK_OFF);

        float S[8][4];
        #pragma unroll
        for (int nt = 0; nt < 8; nt++)
            #pragma unroll
            for (int i = 0; i < 4; i++) S[nt][i] = 0.f;

        #pragma unroll
        for (int kc = 0; kc < 4; kc++) {
            #pragma unroll
            for (int nt2 = 0; nt2 < 4; nt2++) {
                uint32_t kd = stb + AKH_OFF + (uint32_t)((nt2 * 16 + ar) * 72 + kc * 16 + a8 * 8) * 2;
                uint32_t th[4], tl[4];
                ldsm4(th, kd);
                ldsm4(tl, kd + (AKL_OFF - AKH_OFF));
                uint32_t b0h[2] = {th[0], th[2]}, b1h[2] = {th[1], th[3]};
                uint32_t b0l[2] = {tl[0], tl[2]}, b1l[2] = {tl[1], tl[3]};
                mma16816(S[2*nt2],   qhf[kc], b0h);
                mma16816(S[2*nt2],   qlf[kc], b0h);
                mma16816(S[2*nt2],   qhf[kc], b0l);
                mma16816(S[2*nt2+1], qhf[kc], b1h);
                mma16816(S[2*nt2+1], qlf[kc], b1h);
                mma16816(S[2*nt2+1], qhf[kc], b1l);
            }
        }

        bool needMask = (kt >= 2 * qt);
        float mx0 = -1e30f, mx1 = -1e30f;
        #pragma unroll
        for (int nt = 0; nt < 8; nt++) {
            int colb = nt * 8 + tig2;
            uint32_t pb0 = *(const unsigned short*)(bkt + r0l * 64 + colb);
            uint32_t pb1 = *(const unsigned short*)(bkt + r1l * 64 + colb);
            float s0a = S[nt][0] + tb[pb0 & 0xFF];
            float s0b = S[nt][1] + tb[pb0 >> 8];
            float s1a = S[nt][2] + tb[pb1 & 0xFF];
            float s1b = S[nt][3] + tb[pb1 >> 8];
            if (needMask) {
                int kg = kt * 64 + colb;
                if (kg     > qg0) s0a = -1e30f;
                if (kg + 1 > qg0) s0b = -1e30f;
                if (kg     > qg1) s1a = -1e30f;
                if (kg + 1 > qg1) s1b = -1e30f;
            }
            S[nt][0] = s0a; S[nt][1] = s0b; S[nt][2] = s1a; S[nt][3] = s1b;
            mx0 = fmaxf(mx0, fmaxf(s0a, s0b));
            mx1 = fmaxf(mx1, fmaxf(s1a, s1b));
        }
        mx0 = fmaxf(mx0, __shfl_xor_sync(~0u, mx0, 1));
        mx0 = fmaxf(mx0, __shfl_xor_sync(~0u, mx0, 2));
        mx1 = fmaxf(mx1, __shfl_xor_sync(~0u, mx1, 1));
        mx1 = fmaxf(mx1, __shfl_xor_sync(~0u, mx1, 2));
        float mn0 = fmaxf(m0, mx0), mn1 = fmaxf(m1, mx1);
        float rs0 = __expf(m0 - mn0), rs1 = __expf(m1 - mn1);
        m0 = mn0; m1 = mn1;

        float sum0 = 0.f, sum1 = 0.f;
        #pragma unroll
        for (int nt = 0; nt < 8; nt++) {
            float p0 = __expf(S[nt][0] - mn0);
            float p1 = __expf(S[nt][1] - mn0);
            float p2 = __expf(S[nt][2] - mn1);
            float p3 = __expf(S[nt][3] - mn1);
            S[nt][0] = p0; S[nt][1] = p1; S[nt][2] = p2; S[nt][3] = p3;
            sum0 += p0 + p1; sum1 += p2 + p3;
        }
        sum0 += __shfl_xor_sync(~0u, sum0, 1); sum0 += __shfl_xor_sync(~0u, sum0, 2);
        sum1 += __shfl_xor_sync(~0u, sum1, 1); sum1 += __shfl_xor_sync(~0u, sum1, 2);
        l0 = l0 * rs0 + sum0;
        l1 = l1 * rs1 + sum1;
        #pragma unroll
        for (int nt = 0; nt < 8; nt++) {
            acc_o[nt][0] *= rs0; acc_o[nt][1] *= rs0;
            acc_o[nt][2] *= rs1; acc_o[nt][3] *= rs1;
        }

        #pragma unroll
        for (int t = 0; t < 4; t++) {
            uint32_t aph[4], apl[4];
            pack_hilo(S[2*t][0],   S[2*t][1],   aph[0], apl[0]);
            pack_hilo(S[2*t][2],   S[2*t][3],   aph[1], apl[1]);
            pack_hilo(S[2*t+1][0], S[2*t+1][1], aph[2], apl[2]);
            pack_hilo(S[2*t+1][2], S[2*t+1][3], aph[3], apl[3]);
            #pragma unroll
            for (int j2 = 0; j2 < 4; j2++) {
                uint32_t vd = stb + AVH_OFF + (uint32_t)((t * 16 + ar) * 72 + j2 * 16 + a8 * 8) * 2;
                uint32_t th[4], tl[4];
                ldsm4t(th, vd);
                ldsm4t(tl, vd + (AVL_OFF - AVH_OFF));
                uint32_t bh0[2] = {th[0], th[1]}, bh1[2] = {th[2], th[3]};
                uint32_t bl0[2] = {tl[0], tl[1]}, bl1[2] = {tl[2], tl[3]};
                mma16816(acc_o[2*j2],   aph, bh0);
                mma16816(acc_o[2*j2],   apl, bh0);
                mma16816(acc_o[2*j2],   aph, bl0);
                mma16816(acc_o[2*j2+1], aph, bh1);
                mma16816(acc_o[2*j2+1], apl, bh1);
                mma16816(acc_o[2*j2+1], aph, bl1);
            }
        }
        __syncthreads();
    }

    // epilogue: fp16 split output (feeds Wo GEMM)
    float inv0 = 1.0f / l0, inv1 = 1.0f / l1;
    size_t row0 = ((size_t)(b * L_ + qg0)) * D_ + h * DH_;
    size_t row1 = ((size_t)(b * L_ + qg1)) * D_ + h * DH_;
    #pragma unroll
    for (int nt = 0; nt < 8; nt++) {
        int cc = nt * 8 + tig2;
        split_store_f16(oh, ol, row0 + cc, acc_o[nt][0] * inv0, acc_o[nt][1] * inv0);
        split_store_f16(oh, ol, row1 + cc, acc_o[nt][2] * inv1, acc_o[nt][3] * inv1);
    }
}

// ====================== fused residual add + LayerNorm (+ optional fp16 split) ======================
__global__ __launch_bounds__(128)
void add_ln_kernel(const float* __restrict__ xin, const float* __restrict__ res,
                   const float* __restrict__ g, const float* __restrict__ bb,
                   float* __restrict__ xout,
                   __half* __restrict__ oh, __half* __restrict__ ol, int writeSplit)
{
    __shared__ float sy[D_];
    __shared__ float red[4];
    int row = blockIdx.x;
    int tid = threadIdx.x;
    int lane = tid & 31, w = tid >> 5;

    const float* xr = xin + (size_t)row * D_;
    const float* rr = res + (size_t)row * D_;

    float lsum = 0.f;
    #pragma unroll
    for (int i = 0; i < 4; i++) {
        int d = tid + i * 128;
        float val = xr[d] + rr[d];
        sy[d] = val;
        lsum += val;
    }
    #pragma unroll
    for (int o = 16; o > 0; o >>= 1) lsum += __shfl_xor_sync(~0u, lsum, o);
    if (lane == 0) red[w] = lsum;
    __syncthreads();
    float mean = (red[0] + red[1] + red[2] + red[3]) * (1.0f / D_);
    __syncthreads();

    float lv = 0.f;
    #pragma unroll
    for (int i = 0; i < 4; i++) {
        int d = tid + i * 128;
        float c = sy[d] - mean;
        lv += c * c;
    }
    #pragma unroll
    for (int o = 16; o > 0; o >>= 1) lv += __shfl_xor_sync(~0u, lv, o);
    if (lane == 0) red[w] = lv;
    __syncthreads();
    float var = (red[0] + red[1] + red[2] + red[3]) * (1.0f / D_);
    float inv = rsqrtf(var + 1e-5f);

    #pragma unroll
    for (int i = 0; i < 4; i++) {
        int d = tid + i * 128;
        float val = (sy[d] - mean) * inv * g[d] + bb[d];
        xout[(size_t)row * D_ + d] = val;
        if (writeSplit) {
            size_t off = (size_t)row * D_ + d;
            __half hh = __float2half_rn(val);
            oh[off] = hh;
            ol[off] = __float2half_rn(val - __half2float(hh));
        }
    }
}

// ====================== launch ======================
extern "C" void kernel_launch(void* const* d_in, const int* in_sizes, int n_in,
                              void* d_out, int out_size)
{
    const int*   seq      = (const int*)  d_in[0];
    const float* ts       = (const float*)d_in[1];
    const float* item_emb = (const float*)d_in[2];
    const float* pos_emb  = (const float*)d_in[3];
    const float* Wq  = (const float*)d_in[4];  const float* bq  = (const float*)d_in[5];
    const float* Wk  = (const float*)d_in[6];  const float* bk  = (const float*)d_in[7];
    const float* Wv  = (const float*)d_in[8];  const float* bv  = (const float*)d_in[9];
    const float* tbias = (const float*)d_in[10];
    const float* Wo  = (const float*)d_in[11]; const float* bo  = (const float*)d_in[12];
    const float* g1  = (const float*)d_in[13]; const float* be1 = (const float*)d_in[14];
    const float* W1  = (const float*)d_in[15]; const float* bf1 = (const float*)d_in[16];
    const float* W2  = (const float*)d_in[17]; const float* bf2 = (const float*)d_in[18];
    const float* g2  = (const float*)d_in[19]; const float* be2 = (const float*)d_in[20];

    float *x, *po, *bqkv;
    __half *ah, *al, *fh, *fl, *wth;
    bf16 *qvh, *qvl;
    unsigned char* bkptr;
    cudaGetSymbolAddress((void**)&x,  g_x);
    cudaGetSymbolAddress((void**)&po, g_po);
    cudaGetSymbolAddress((void**)&ah, g_ah);
    cudaGetSymbolAddress((void**)&al, g_al);
    cudaGetSymbolAddress((void**)&qvh, g_qvh);
    cudaGetSymbolAddress((void**)&qvl, g_qvl);
    cudaGetSymbolAddress((void**)&fh, g_fh);
    cudaGetSymbolAddress((void**)&fl, g_fl);
    cudaGetSymbolAddress((void**)&wth, g_wth);
    cudaGetSymbolAddress((void**)&bkptr, g_bk);
    cudaGetSymbolAddress((void**)&bqkv, g_bqkv);

    cudaFuncSetAttribute(attn_mma,  cudaFuncAttributeMaxDynamicSharedMemorySize, ATTN2_SMEM);
    cudaFuncSetAttribute(gemm_hmma, cudaFuncAttributeMaxDynamicSharedMemorySize, GSMEM);

    const size_t OQ = 0, OO = 786432, O1 = 1048576, O2 = 2097152;
    dim3 t32(32, 8);
    dim3 gQKV(NQKV / 128, ML_ / 128);  // (12, 128)
    dim3 gD(D_ / 128, ML_ / 128);      // (4, 128)
    dim3 gF(DFF_ / 128, ML_ / 128);    // (16, 128)
    dim3 ga(L_ / 128, H_, B_);         // (4, 8, 32)

    for (int i = 0; i < NL_; i++) {
        size_t wb = (size_t)i * WT_LAYER;
        conv_wt_kernel<<<dim3(16, 16), t32>>>(Wq + (size_t)i*D_*D_,   wth+wb+0,      512, 512);
        conv_wt_kernel<<<dim3(16, 16), t32>>>(Wk + (size_t)i*D_*D_,   wth+wb+262144, 512, 512);
        conv_wt_kernel<<<dim3(16, 16), t32>>>(Wv + (size_t)i*D_*D_,   wth+wb+524288, 512, 512);
        conv_wt_kernel<<<dim3(16, 16), t32>>>(Wo + (size_t)i*D_*D_,   wth+wb+OO, 512, 512);
        conv_wt_kernel<<<dim3(64, 16), t32>>>(W1 + (size_t)i*D_*DFF_, wth+wb+O1, 512, 2048);
        conv_wt_kernel<<<dim3(16, 64), t32>>>(W2 + (size_t)i*DFF_*D_, wth+wb+O2, 2048, 512);
    }
    biascat_kernel<<<(NL_*NQKV)/256, 256>>>(bq, bk, bv);
    embed_kernel<<<(ML_ * D_ / 4) / 256, 256>>>(seq, item_emb, pos_emb);
    bucket_kernel<<<(B_*L_*L_)/256, 256>>>(ts);

    for (int i = 0; i < NL_; i++) {
        size_t wb = (size_t)i * WT_LAYER;

        // fused QKV: bf16-split packed output (flag 16), q-section scaled 0.125
        gemm_hmma<<<gQKV, 256, GSMEM>>>(ah, al, wth+wb+OQ, bqkv + i*NQKV,
                                        0, qvh, qvl, ML_, NQKV, D_, 4|8|16, 1.0f);

        attn_mma<<<ga, 256, ATTN2_SMEM>>>(qvh, qvl, bkptr, tbias + (size_t)i*NB_*H_, ah, al);

        gemm_hmma<<<gD, 256, GSMEM>>>(ah, al, wth+wb+OO, bo + i*D_, po, 0, 0, ML_, D_, D_, 2, 1.0f);
        add_ln_kernel<<<ML_, 128>>>(x, po, g1 + i*D_, be1 + i*D_, x, ah, al, 1);

        gemm_hmma<<<gF, 256, GSMEM>>>(ah, al, wth+wb+O1, bf1 + i*DFF_, 0, fh, fl, ML_, DFF_, D_, 1|4, 1.0f);
        gemm_hmma<<<gD, 256, GSMEM>>>(fh, fl, wth+wb+O2, bf2 + i*D_, po, 0, 0, ML_, D_, DFF_, 2, 1.0f);

        float* xo = (i == NL_ - 1) ? (float*)d_out : x;
        add_ln_kernel<<<ML_, 128>>>(x, po, g2 + i*D_, be2 + i*D_, xo, ah, al, (i < NL_ - 1) ? 1 : 0);
    }
}

// round 9
// speedup vs baseline: 4.6258x; 1.4867x over previous
#include <cuda_runtime.h>
#include <cuda_bf16.h>
#include <cuda_fp16.h>
#include <math.h>
#include <stdint.h>

#define B_   32
#define L_   512
#define D_   512
#define H_   8
#define DH_  64
#define NL_  2
#define DFF_ 2048
#define NB_  32
#define ML_  (B_*L_)   // 16384 rows
#define NQKV 1536

typedef __nv_bfloat16 bf16;

// ---------------- scratch (device globals; no allocations) ----------------
__device__ float g_x [ML_*D_];
__device__ float g_po[ML_*D_];
// fp16 activations (GEMM A operands, single precision level)
__device__ __align__(16) __half g_ah[ML_*D_];
__device__ __align__(16) __half g_fh[ML_*DFF_];
// bf16 hi/lo split QKV (attention operands, 3-term path)
__device__ __align__(16) bf16 g_qvh[ML_*NQKV];
__device__ __align__(16) bf16 g_qvl[ML_*NQKV];
// fp16 transposed weights
#define WT_LAYER (4*512*512 + 2048*512 + 512*2048)
__device__ __align__(16) __half g_wth[NL_*WT_LAYER];
// precomputed time-bucket indices [B][L][L]
__device__ __align__(16) unsigned char g_bk[B_*L_*L_];
__device__ float g_bqkv[NL_*NQKV];

// ====================== PTX helpers ======================
__device__ __forceinline__ uint32_t smem_u32(const void* p) {
    uint32_t a;
    asm("{ .reg .u64 t; cvta.to.shared.u64 t, %1; cvt.u32.u64 %0, t; }" : "=r"(a) : "l"(p));
    return a;
}
__device__ __forceinline__ void cp16(uint32_t s, const void* g) {
    asm volatile("cp.async.cg.shared.global [%0], [%1], 16;" :: "r"(s), "l"(g));
}
__device__ __forceinline__ void ldsm4(uint32_t* r, uint32_t a) {
    asm volatile("ldmatrix.sync.aligned.m8n8.x4.shared.b16 {%0,%1,%2,%3}, [%4];"
        : "=r"(r[0]), "=r"(r[1]), "=r"(r[2]), "=r"(r[3]) : "r"(a));
}
__device__ __forceinline__ void ldsm4t(uint32_t* r, uint32_t a) {
    asm volatile("ldmatrix.sync.aligned.m8n8.x4.trans.shared.b16 {%0,%1,%2,%3}, [%4];"
        : "=r"(r[0]), "=r"(r[1]), "=r"(r[2]), "=r"(r[3]) : "r"(a));
}
// bf16 MMA (attention path)
__device__ __forceinline__ void mma16816(float* c, const uint32_t* a, const uint32_t* b) {
    asm volatile("mma.sync.aligned.m16n8k16.row.col.f32.bf16.bf16.f32 "
        "{%0,%1,%2,%3}, {%4,%5,%6,%7}, {%8,%9}, {%0,%1,%2,%3};"
        : "+f"(c[0]), "+f"(c[1]), "+f"(c[2]), "+f"(c[3])
        : "r"(a[0]), "r"(a[1]), "r"(a[2]), "r"(a[3]), "r"(b[0]), "r"(b[1]));
}
// fp16 MMA (linear GEMM path)
__device__ __forceinline__ void mma16816h(float* c, const uint32_t* a, const uint32_t* b) {
    asm volatile("mma.sync.aligned.m16n8k16.row.col.f32.f16.f16.f32 "
        "{%0,%1,%2,%3}, {%4,%5,%6,%7}, {%8,%9}, {%0,%1,%2,%3};"
        : "+f"(c[0]), "+f"(c[1]), "+f"(c[2]), "+f"(c[3])
        : "r"(a[0]), "r"(a[1]), "r"(a[2]), "r"(a[3]), "r"(b[0]), "r"(b[1]));
}

// ---- bf16 hi/lo pack (attention / QKV output) ----
__device__ __forceinline__ void pack_hilo(float x, float y, uint32_t& h, uint32_t& l) {
    bf16 hx = __float2bfloat16_rn(x), hy = __float2bfloat16_rn(y);
    __nv_bfloat162 th = __halves2bfloat162(hx, hy);
    h = *(uint32_t*)&th;
    __nv_bfloat162 tl = __halves2bfloat162(
        __float2bfloat16_rn(x - __bfloat162float(hx)),
        __float2bfloat16_rn(y - __bfloat162float(hy)));
    l = *(uint32_t*)&tl;
}
__device__ __forceinline__ void split_store_bf(bf16* Oh, bf16* Ol, size_t off, float v0, float v1) {
    uint32_t h, l;
    pack_hilo(v0, v1, h, l);
    *(uint32_t*)(Oh + off) = h;
    *(uint32_t*)(Ol + off) = l;
}
// ---- fp16 single store ----
__device__ __forceinline__ void store_f16x2(__half* O, size_t off, float v0, float v1) {
    __half2 t = __halves2half2(__float2half_rn(v0), __float2half_rn(v1));
    *(uint32_t*)(O + off) = *(uint32_t*)&t;
}

// ====================== time bucket ======================
__device__ __forceinline__ int time_bucket(float delta)
{
    float a = fmaxf(fabsf(delta), 1.0f);
    const float scale = 0.71018780958489f;   // float32(log2(2592000)/30)
    int idx = (int)(log2f(a) / scale) + 1;
    idx = max(1, min(idx, NB_ - 2));
    if (a <= 1.0f)       idx = 0;
    if (a >= 2592000.0f) idx = NB_ - 1;
    return idx;
}

__global__ void bucket_kernel(const float* __restrict__ ts)
{
    int idx = blockIdx.x * blockDim.x + threadIdx.x;   // over B*L*L
    int k = idx & (L_-1);
    int q = (idx >> 9) & (L_-1);
    int b = idx >> 18;
    float d = ts[b * L_ + q] - ts[b * L_ + k];
    g_bk[idx] = (unsigned char)time_bucket(d);
}

__global__ void biascat_kernel(const float* __restrict__ bq,
                               const float* __restrict__ bk,
                               const float* __restrict__ bv)
{
    int i = blockIdx.x * blockDim.x + threadIdx.x;   // NL*1536
    int l = i / NQKV, c = i % NQKV;
    float v = (c < 512) ? bq[l*512 + c] : (c < 1024 ? bk[l*512 + c - 512] : bv[l*512 + c - 1024]);
    g_bqkv[i] = v;
}

// ====================== embedding (+ fp16) ======================
__global__ void embed_kernel(const int* __restrict__ seq,
                             const float* __restrict__ item_emb,
                             const float* __restrict__ pos_emb)
{
    int idx = blockIdx.x * blockDim.x + threadIdx.x;   // over ML*D/4
    int d4 = idx & (D_/4 - 1);
    int bl = idx >> 7;
    int l  = bl & (L_-1);
    int it = seq[bl];
    float4 a = *(const float4*)(item_emb + (size_t)it * D_ + d4*4);
    float4 p = *(const float4*)(pos_emb  + (size_t)l  * D_ + d4*4);
    a.x += p.x; a.y += p.y; a.z += p.z; a.w += p.w;
    ((float4*)g_x)[idx] = a;
    size_t off = (size_t)idx * 4;
    store_f16x2(g_ah, off,     a.x, a.y);
    store_f16x2(g_ah, off + 2, a.z, a.w);
}

// ====================== weight transpose (fp16) ======================
__global__ void conv_wt_kernel(const float* __restrict__ W,
                               __half* __restrict__ Th, int K, int N)
{
    __shared__ float s[32][33];
    int tx = threadIdx.x, ty = threadIdx.y;   // 32 x 8
    int n0 = blockIdx.x * 32, k0 = blockIdx.y * 32;
    #pragma unroll
    for (int j = 0; j < 32; j += 8)
        s[ty + j][tx] = W[(size_t)(k0 + ty + j) * N + n0 + tx];
    __syncthreads();
    #pragma unroll
    for (int j = 0; j < 32; j += 8) {
        int n = n0 + ty + j, k = k0 + tx;
        Th[(size_t)n * K + k] = __float2half_rn(s[tx][ty + j]);
    }
}

// ====================== fp16 HMMA GEMM (single-term A·B) ======================
#define TILE_B   10240
#define STAGE_B  20480   // 2 tiles (A, B)
#define GSMEM    61440   // 3 stages
#define STRIDE   40

// flags: 1 = relu, 2 = write fp32 C, 4 = write fp16 (Oh), 8 = qkv col-scale, 16 = write bf16 split (Oh/Ol)
__global__ __launch_bounds__(256, 1)
void gemm_hmma(const __half* __restrict__ Ah, const __half* __restrict__ Bh,
               const float* __restrict__ bias, float* __restrict__ C,
               void* __restrict__ Oh, void* __restrict__ Ol,
               int M, int N, int K, int flags, float oscale)
{
    extern __shared__ char sm[];
    uint32_t sb = smem_u32(sm);
    int tid = threadIdx.x, lane = tid & 31, wid = tid >> 5;
    int wm = wid & 1, wn = wid >> 1;
    int m0 = blockIdx.y * 128, n0 = blockIdx.x * 128;

    int lrow = tid >> 2, lseg = tid & 3;
    const char* gAh = (const char*)(Ah + (size_t)(m0 + lrow) * K + lseg * 8);
    const char* gBh = (const char*)(Bh + (size_t)(n0 + lrow) * K + lseg * 8);
    size_t rowskip = (size_t)64 * K * 2;
    uint32_t s0off = (uint32_t)(lrow * STRIDE + lseg * 8) * 2;
    uint32_t s1off = s0off + 64 * STRIDE * 2;

    float acc[4][4][4];
    #pragma unroll
    for (int a = 0; a < 4; a++)
        #pragma unroll
        for (int b = 0; b < 4; b++)
            #pragma unroll
            for (int c = 0; c < 4; c++) acc[a][b][c] = 0.f;

    int NC = K >> 5;

#define LOADC(cc, st) do { \
    size_t ko = (size_t)(cc) * 64; \
    uint32_t s0 = sb + (st) * STAGE_B + s0off; \
    uint32_t s1 = sb + (st) * STAGE_B + s1off; \
    cp16(s0,          gAh + ko); cp16(s1,          gAh + ko + rowskip); \
    cp16(s0 + TILE_B, gBh + ko); cp16(s1 + TILE_B, gBh + ko + rowskip); \
    asm volatile("cp.async.commit_group;"); \
} while (0)

    LOADC(0, 0);
    LOADC(1, 1);

    int ar = lane & 15, a8 = lane >> 4;
    int st = 0;

    for (int c = 0; c < NC; c++) {
        if (c + 2 < NC) {
            LOADC(c + 2, (c + 2) % 3);
            asm volatile("cp.async.wait_group 2;");
        } else if (c + 1 < NC) {
            asm volatile("cp.async.wait_group 1;");
        } else {
            asm volatile("cp.async.wait_group 0;");
        }
        __syncthreads();

        uint32_t tb = sb + st * STAGE_B;
        st = (st + 1 == 3) ? 0 : st + 1;
        #pragma unroll
        for (int ks = 0; ks < 2; ks++) {
            int acol = ks * 16 + a8 * 8;
            uint32_t Ahf[4][4], Bhf[4][2];
            #pragma unroll
            for (int mt = 0; mt < 4; mt++) {
                uint32_t ad = tb + (uint32_t)((wm * 64 + mt * 16 + ar) * STRIDE + acol) * 2;
                ldsm4(Ahf[mt], ad);
            }
            #pragma unroll
            for (int p = 0; p < 2; p++) {
                uint32_t bd = tb + TILE_B +
                              (uint32_t)((wn * 32 + p * 16 + ar) * STRIDE + acol) * 2;
                uint32_t t[4];
                ldsm4(t, bd);
                Bhf[2*p][0] = t[0]; Bhf[2*p][1] = t[2];
                Bhf[2*p+1][0] = t[1]; Bhf[2*p+1][1] = t[3];
            }
            #pragma unroll
            for (int mt = 0; mt < 4; mt++)
                #pragma unroll
                for (int nt = 0; nt < 4; nt++)
                    mma16816h(acc[mt][nt], Ahf[mt], Bhf[nt]);
        }
        __syncthreads();
    }
#undef LOADC

    int relu = flags & 1, wf = flags & 2, wh = flags & 4, wbf = flags & 16;
    int r_base = m0 + wm * 64 + (lane >> 2);
    int c_base = n0 + wn * 32 + (lane & 3) * 2;
    #pragma unroll
    for (int nt = 0; nt < 4; nt++) {
        int c0 = c_base + nt * 8;
        float sc = (flags & 8) ? ((c0 < 512) ? 0.125f : 1.0f) : oscale;
        float2 bv = *(const float2*)(bias + c0);
        #pragma unroll
        for (int mt = 0; mt < 4; mt++) {
            #pragma unroll
            for (int h = 0; h < 2; h++) {
                int r = r_base + mt * 16 + h * 8;
                float v0 = (acc[mt][nt][h*2+0] + bv.x) * sc;
                float v1 = (acc[mt][nt][h*2+1] + bv.y) * sc;
                if (relu) { v0 = fmaxf(v0, 0.f); v1 = fmaxf(v1, 0.f); }
                size_t off = (size_t)r * N + c0;
                if (wf)  *(float2*)(C + off) = make_float2(v0, v1);
                if (wh)  store_f16x2((__half*)Oh, off, v0, v1);
                if (wbf) split_store_bf((bf16*)Oh, (bf16*)Ol, off, v0, v1);
            }
        }
    }
}

// ====================== HMMA flash attention (bf16 3-term, precomputed buckets) ======================
#define AQH_OFF   0
#define AQL_OFF   18432
#define ASTG_BASE 36864
#define ASTG_SZ   45056
#define AKH_OFF   0
#define AKL_OFF   9216
#define AVH_OFF   18432
#define AVL_OFF   27648
#define ABK_OFF   36864
#define ATB_OFF   (ASTG_BASE + 2*ASTG_SZ)        // 126976
#define ATTN2_SMEM (ATB_OFF + 128)               // 127104

__device__ __forceinline__ void load_kv_tile(
    uint32_t sb, const bf16* qvh, const bf16* qvl, const unsigned char* bkp,
    int b, int h, int q0, int kt, int st, int tid)
{
    uint32_t stb = sb + ASTG_BASE + st * ASTG_SZ;
    const char* gkh = (const char*)qvh + ((size_t)(b * L_) * NQKV + 512  + h * DH_) * 2;
    const char* gkl = (const char*)qvl + ((size_t)(b * L_) * NQKV + 512  + h * DH_) * 2;
    const char* gvh = (const char*)qvh + ((size_t)(b * L_) * NQKV + 1024 + h * DH_) * 2;
    const char* gvl = (const char*)qvl + ((size_t)(b * L_) * NQKV + 1024 + h * DH_) * 2;
    #pragma unroll
    for (int i = 0; i < 2; i++) {
        int idx = tid + i * 256;
        int r = idx >> 3, c = idx & 7;
        size_t go = (size_t)(kt * 64 + r) * (NQKV * 2) + c * 16;
        uint32_t so = (uint32_t)(r * 144 + c * 16);
        cp16(stb + AKH_OFF + so, gkh + go);
        cp16(stb + AKL_OFF + so, gkl + go);
        cp16(stb + AVH_OFF + so, gvh + go);
        cp16(stb + AVL_OFF + so, gvl + go);
    }
    #pragma unroll
    for (int i = 0; i < 2; i++) {
        int idx = tid + i * 256;
        int r = idx >> 2, c = idx & 3;
        size_t go = ((size_t)(b * L_ + q0 + r)) * L_ + kt * 64 + c * 16;
        cp16(stb + ABK_OFF + (uint32_t)(r * 64 + c * 16), bkp + go);
    }
    asm volatile("cp.async.commit_group;");
}

__global__ __launch_bounds__(256, 1)
void attn_mma(const bf16* __restrict__ qvh, const bf16* __restrict__ qvl,
              const unsigned char* __restrict__ bkp, const float* __restrict__ tbias,
              __half* __restrict__ oh)
{
    extern __shared__ char sm[];
    uint32_t sb = smem_u32(sm);
    float* smf = (float*)sm;

    int qt = blockIdx.x, h = blockIdx.y, b = blockIdx.z;
    int q0 = qt * 128;
    int tid = threadIdx.x, lane = tid & 31, wid = tid >> 5;
    int g = lane >> 2, tig = lane & 3, tig2 = tig * 2;
    int ar = lane & 15, a8 = lane >> 4;

    {
        const char* gq  = (const char*)qvh + ((size_t)(b * L_ + q0) * NQKV + h * DH_) * 2;
        const char* gq2 = (const char*)qvl + ((size_t)(b * L_ + q0) * NQKV + h * DH_) * 2;
        #pragma unroll
        for (int i = 0; i < 4; i++) {
            int idx = tid + i * 256;
            int r = idx >> 3, c = idx & 7;
            size_t go = (size_t)r * (NQKV * 2) + c * 16;
            uint32_t so = (uint32_t)(r * 144 + c * 16);
            cp16(sb + AQH_OFF + so, gq + go);
            cp16(sb + AQL_OFF + so, gq2 + go);
        }
    }
    if (tid < NB_) smf[ATB_OFF/4 + tid] = tbias[tid * H_ + h];

    int nkt = 2 * qt + 2;
    load_kv_tile(sb, qvh, qvl, bkp, b, h, q0, 0, 0, tid);

    int qg0 = q0 + wid * 16 + g, qg1 = qg0 + 8;
    int r0l = wid * 16 + g, r1l = r0l + 8;
    float m0 = -1e30f, m1 = -1e30f, l0 = 0.f, l1 = 0.f;
    float acc_o[8][4];
    #pragma unroll
    for (int nt = 0; nt < 8; nt++)
        #pragma unroll
        for (int i = 0; i < 4; i++) acc_o[nt][i] = 0.f;

    uint32_t qhf[4][4], qlf[4][4];
    asm volatile("cp.async.wait_group 0;");
    __syncthreads();
    #pragma unroll
    for (int kc = 0; kc < 4; kc++) {
        uint32_t ad = sb + AQH_OFF + (uint32_t)((wid * 16 + ar) * 72 + kc * 16 + a8 * 8) * 2;
        ldsm4(qhf[kc], ad);
        ldsm4(qlf[kc], ad + (AQL_OFF - AQH_OFF));
    }

    const float* tb = (const float*)(sm + ATB_OFF);

    for (int kt = 0; kt < nkt; kt++) {
        int st = kt & 1;
        if (kt + 1 < nkt) {
            load_kv_tile(sb, qvh, qvl, bkp, b, h, q0, kt + 1, st ^ 1, tid);
            asm volatile("cp.async.wait_group 1;");
        } else {
            asm volatile("cp.async.wait_group 0;");
        }
        __syncthreads();

        uint32_t stb = sb + ASTG_BASE + st * ASTG_SZ;
        const unsigned char* bkt = (const unsigned char*)(sm + ASTG_BASE + st * ASTG_SZ + ABK_OFF);

        float S[8][4];
        #pragma unroll
        for (int nt = 0; nt < 8; nt++)
            #pragma unroll
            for (int i = 0; i < 4; i++) S[nt][i] = 0.f;

        #pragma unroll
        for (int kc = 0; kc < 4; kc++) {
            #pragma unroll
            for (int nt2 = 0; nt2 < 4; nt2++) {
                uint32_t kd = stb + AKH_OFF + (uint32_t)((nt2 * 16 + ar) * 72 + kc * 16 + a8 * 8) * 2;
                uint32_t th[4], tl[4];
                ldsm4(th, kd);
                ldsm4(tl, kd + (AKL_OFF - AKH_OFF));
                uint32_t b0h[2] = {th[0], th[2]}, b1h[2] = {th[1], th[3]};
                uint32_t b0l[2] = {tl[0], tl[2]}, b1l[2] = {tl[1], tl[3]};
                mma16816(S[2*nt2],   qhf[kc], b0h);
                mma16816(S[2*nt2],   qlf[kc], b0h);
                mma16816(S[2*nt2],   qhf[kc], b0l);
                mma16816(S[2*nt2+1], qhf[kc], b1h);
                mma16816(S[2*nt2+1], qlf[kc], b1h);
                mma16816(S[2*nt2+1], qhf[kc], b1l);
            }
        }

        bool needMask = (kt >= 2 * qt);
        float mx0 = -1e30f, mx1 = -1e30f;
        #pragma unroll
        for (int nt = 0; nt < 8; nt++) {
            int colb = nt * 8 + tig2;
            uint32_t pb0 = *(const unsigned short*)(bkt + r0l * 64 + colb);
            uint32_t pb1 = *(const unsigned short*)(bkt + r1l * 64 + colb);
            float s0a = S[nt][0] + tb[pb0 & 0xFF];
            float s0b = S[nt][1] + tb[pb0 >> 8];
            float s1a = S[nt][2] + tb[pb1 & 0xFF];
            float s1b = S[nt][3] + tb[pb1 >> 8];
            if (needMask) {
                int kg = kt * 64 + colb;
                if (kg     > qg0) s0a = -1e30f;
                if (kg + 1 > qg0) s0b = -1e30f;
                if (kg     > qg1) s1a = -1e30f;
                if (kg + 1 > qg1) s1b = -1e30f;
            }
            S[nt][0] = s0a; S[nt][1] = s0b; S[nt][2] = s1a; S[nt][3] = s1b;
            mx0 = fmaxf(mx0, fmaxf(s0a, s0b));
            mx1 = fmaxf(mx1, fmaxf(s1a, s1b));
        }
        mx0 = fmaxf(mx0, __shfl_xor_sync(~0u, mx0, 1));
        mx0 = fmaxf(mx0, __shfl_xor_sync(~0u, mx0, 2));
        mx1 = fmaxf(mx1, __shfl_xor_sync(~0u, mx1, 1));
        mx1 = fmaxf(mx1, __shfl_xor_sync(~0u, mx1, 2));
        float mn0 = fmaxf(m0, mx0), mn1 = fmaxf(m1, mx1);
        float rs0 = __expf(m0 - mn0), rs1 = __expf(m1 - mn1);
        m0 = mn0; m1 = mn1;

        float sum0 = 0.f, sum1 = 0.f;
        #pragma unroll
        for (int nt = 0; nt < 8; nt++) {
            float p0 = __expf(S[nt][0] - mn0);
            float p1 = __expf(S[nt][1] - mn0);
            float p2 = __expf(S[nt][2] - mn1);
            float p3 = __expf(S[nt][3] - mn1);
            S[nt][0] = p0; S[nt][1] = p1; S[nt][2] = p2; S[nt][3] = p3;
            sum0 += p0 + p1; sum1 += p2 + p3;
        }
        sum0 += __shfl_xor_sync(~0u, sum0, 1); sum0 += __shfl_xor_sync(~0u, sum0, 2);
        sum1 += __shfl_xor_sync(~0u, sum1, 1); sum1 += __shfl_xor_sync(~0u, sum1, 2);
        l0 = l0 * rs0 + sum0;
        l1 = l1 * rs1 + sum1;
        #pragma unroll
        for (int nt = 0; nt < 8; nt++) {
            acc_o[nt][0] *= rs0; acc_o[nt][1] *= rs0;
            acc_o[nt][2] *= rs1; acc_o[nt][3] *= rs1;
        }

        #pragma unroll
        for (int t = 0; t < 4; t++) {
            uint32_t aph[4], apl[4];
            pack_hilo(S[2*t][0],   S[2*t][1],   aph[0], apl[0]);
            pack_hilo(S[2*t][2],   S[2*t][3],   aph[1], apl[1]);
            pack_hilo(S[2*t+1][0], S[2*t+1][1], aph[2], apl[2]);
            pack_hilo(S[2*t+1][2], S[2*t+1][3], aph[3], apl[3]);
            #pragma unroll
            for (int j2 = 0; j2 < 4; j2++) {
                uint32_t vd = stb + AVH_OFF + (uint32_t)((t * 16 + ar) * 72 + j2 * 16 + a8 * 8) * 2;
                uint32_t th[4], tl[4];
                ldsm4t(th, vd);
                ldsm4t(tl, vd + (AVL_OFF - AVH_OFF));
                uint32_t bh0[2] = {th[0], th[1]}, bh1[2] = {th[2], th[3]};
                uint32_t bl0[2] = {tl[0], tl[1]}, bl1[2] = {tl[2], tl[3]};
                mma16816(acc_o[2*j2],   aph, bh0);
                mma16816(acc_o[2*j2],   apl, bh0);
                mma16816(acc_o[2*j2],   aph, bl0);
                mma16816(acc_o[2*j2+1], aph, bh1);
                mma16816(acc_o[2*j2+1], apl, bh1);
                mma16816(acc_o[2*j2+1], aph, bl1);
            }
        }
        __syncthreads();
    }

    // epilogue: fp16 output (feeds Wo GEMM)
    float inv0 = 1.0f / l0, inv1 = 1.0f / l1;
    size_t row0 = ((size_t)(b * L_ + qg0)) * D_ + h * DH_;
    size_t row1 = ((size_t)(b * L_ + qg1)) * D_ + h * DH_;
    #pragma unroll
    for (int nt = 0; nt < 8; nt++) {
        int cc = nt * 8 + tig2;
        store_f16x2(oh, row0 + cc, acc_o[nt][0] * inv0, acc_o[nt][1] * inv0);
        store_f16x2(oh, row1 + cc, acc_o[nt][2] * inv1, acc_o[nt][3] * inv1);
    }
}

// ====================== fused residual add + LayerNorm (+ optional fp16 out) ======================
__global__ __launch_bounds__(128)
void add_ln_kernel(const float* __restrict__ xin, const float* __restrict__ res,
                   const float* __restrict__ g, const float* __restrict__ bb,
                   float* __restrict__ xout, __half* __restrict__ oh, int writeH)
{
    __shared__ float sy[D_];
    __shared__ float red[4];
    int row = blockIdx.x;
    int tid = threadIdx.x;
    int lane = tid & 31, w = tid >> 5;

    const float* xr = xin + (size_t)row * D_;
    const float* rr = res + (size_t)row * D_;

    float lsum = 0.f;
    #pragma unroll
    for (int i = 0; i < 4; i++) {
        int d = tid + i * 128;
        float val = xr[d] + rr[d];
        sy[d] = val;
        lsum += val;
    }
    #pragma unroll
    for (int o = 16; o > 0; o >>= 1) lsum += __shfl_xor_sync(~0u, lsum, o);
    if (lane == 0) red[w] = lsum;
    __syncthreads();
    float mean = (red[0] + red[1] + red[2] + red[3]) * (1.0f / D_);
    __syncthreads();

    float lv = 0.f;
    #pragma unroll
    for (int i = 0; i < 4; i++) {
        int d = tid + i * 128;
        float c = sy[d] - mean;
        lv += c * c;
    }
    #pragma unroll
    for (int o = 16; o > 0; o >>= 1) lv += __shfl_xor_sync(~0u, lv, o);
    if (lane == 0) red[w] = lv;
    __syncthreads();
    float var = (red[0] + red[1] + red[2] + red[3]) * (1.0f / D_);
    float inv = rsqrtf(var + 1e-5f);

    #pragma unroll
    for (int i = 0; i < 4; i++) {
        int d = tid + i * 128;
        float val = (sy[d] - mean) * inv * g[d] + bb[d];
        xout[(size_t)row * D_ + d] = val;
        if (writeH)
            oh[(size_t)row * D_ + d] = __float2half_rn(val);
    }
}

// ====================== launch ======================
extern "C" void kernel_launch(void* const* d_in, const int* in_sizes, int n_in,
                              void* d_out, int out_size)
{
    const int*   seq      = (const int*)  d_in[0];
    const float* ts       = (const float*)d_in[1];
    const float* item_emb = (const float*)d_in[2];
    const float* pos_emb  = (const float*)d_in[3];
    const float* Wq  = (const float*)d_in[4];  const float* bq  = (const float*)d_in[5];
    const float* Wk  = (const float*)d_in[6];  const float* bk  = (const float*)d_in[7];
    const float* Wv  = (const float*)d_in[8];  const float* bv  = (const float*)d_in[9];
    const float* tbias = (const float*)d_in[10];
    const float* Wo  = (const float*)d_in[11]; const float* bo  = (const float*)d_in[12];
    const float* g1  = (const float*)d_in[13]; const float* be1 = (const float*)d_in[14];
    const float* W1  = (const float*)d_in[15]; const float* bf1 = (const float*)d_in[16];
    const float* W2  = (const float*)d_in[17]; const float* bf2 = (const float*)d_in[18];
    const float* g2  = (const float*)d_in[19]; const float* be2 = (const float*)d_in[20];

    float *x, *po, *bqkv;
    __half *ah, *fh, *wth;
    bf16 *qvh, *qvl;
    unsigned char* bkptr;
    cudaGetSymbolAddress((void**)&x,  g_x);
    cudaGetSymbolAddress((void**)&po, g_po);
    cudaGetSymbolAddress((void**)&ah, g_ah);
    cudaGetSymbolAddress((void**)&qvh, g_qvh);
    cudaGetSymbolAddress((void**)&qvl, g_qvl);
    cudaGetSymbolAddress((void**)&fh, g_fh);
    cudaGetSymbolAddress((void**)&wth, g_wth);
    cudaGetSymbolAddress((void**)&bkptr, g_bk);
    cudaGetSymbolAddress((void**)&bqkv, g_bqkv);

    cudaFuncSetAttribute(attn_mma,  cudaFuncAttributeMaxDynamicSharedMemorySize, ATTN2_SMEM);
    cudaFuncSetAttribute(gemm_hmma, cudaFuncAttributeMaxDynamicSharedMemorySize, GSMEM);

    const size_t OQ = 0, OO = 786432, O1 = 1048576, O2 = 2097152;
    dim3 t32(32, 8);
    dim3 gQKV(NQKV / 128, ML_ / 128);  // (12, 128)
    dim3 gD(D_ / 128, ML_ / 128);      // (4, 128)
    dim3 gF(DFF_ / 128, ML_ / 128);    // (16, 128)
    dim3 ga(L_ / 128, H_, B_);         // (4, 8, 32)

    for (int i = 0; i < NL_; i++) {
        size_t wb = (size_t)i * WT_LAYER;
        conv_wt_kernel<<<dim3(16, 16), t32>>>(Wq + (size_t)i*D_*D_,   wth+wb+0,      512, 512);
        conv_wt_kernel<<<dim3(16, 16), t32>>>(Wk + (size_t)i*D_*D_,   wth+wb+262144, 512, 512);
        conv_wt_kernel<<<dim3(16, 16), t32>>>(Wv + (size_t)i*D_*D_,   wth+wb+524288, 512, 512);
        conv_wt_kernel<<<dim3(16, 16), t32>>>(Wo + (size_t)i*D_*D_,   wth+wb+OO, 512, 512);
        conv_wt_kernel<<<dim3(64, 16), t32>>>(W1 + (size_t)i*D_*DFF_, wth+wb+O1, 512, 2048);
        conv_wt_kernel<<<dim3(16, 64), t32>>>(W2 + (size_t)i*DFF_*D_, wth+wb+O2, 2048, 512);
    }
    biascat_kernel<<<(NL_*NQKV)/256, 256>>>(bq, bk, bv);
    embed_kernel<<<(ML_ * D_ / 4) / 256, 256>>>(seq, item_emb, pos_emb);
    bucket_kernel<<<(B_*L_*L_)/256, 256>>>(ts);

    for (int i = 0; i < NL_; i++) {
        size_t wb = (size_t)i * WT_LAYER;

        // fused QKV: bf16-split packed output (flag 16), q-section scaled 0.125
        gemm_hmma<<<gQKV, 256, GSMEM>>>(ah, wth+wb+OQ, bqkv + i*NQKV,
                                        0, qvh, qvl, ML_, NQKV, D_, 8|16, 1.0f);

        attn_mma<<<ga, 256, ATTN2_SMEM>>>(qvh, qvl, bkptr, tbias + (size_t)i*NB_*H_, ah);

        gemm_hmma<<<gD, 256, GSMEM>>>(ah, wth+wb+OO, bo + i*D_, po, 0, 0, ML_, D_, D_, 2, 1.0f);
        add_ln_kernel<<<ML_, 128>>>(x, po, g1 + i*D_, be1 + i*D_, x, ah, 1);

        gemm_hmma<<<gF, 256, GSMEM>>>(ah, wth+wb+O1, bf1 + i*DFF_, 0, fh, 0, ML_, DFF_, D_, 1|4, 1.0f);
        gemm_hmma<<<gD, 256, GSMEM>>>(fh, wth+wb+O2, bf2 + i*D_, po, 0, 0, ML_, D_, DFF_, 2, 1.0f);

        float* xo = (i == NL_ - 1) ? (float*)d_out : x;
        add_ln_kernel<<<ML_, 128>>>(x, po, g2 + i*D_, be2 + i*D_, xo, ah, (i < NL_ - 1) ? 1 : 0);
    }
}

// round 10
// speedup vs baseline: 5.9291x; 1.2817x over previous
#include <cuda_runtime.h>
#include <cuda_fp16.h>
#include <math.h>
#include <stdint.h>

#define B_   32
#define L_   512
#define D_   512
#define H_   8
#define DH_  64
#define NL_  2
#define DFF_ 2048
#define NB_  32
#define ML_  (B_*L_)   // 16384 rows
#define NQKV 1536

// ---------------- scratch (device globals; no allocations) ----------------
__device__ float g_x [ML_*D_];
__device__ float g_po[ML_*D_];
__device__ __align__(16) __half g_ah[ML_*D_];
__device__ __align__(16) __half g_fh[ML_*DFF_];
__device__ __align__(16) __half g_qv[ML_*NQKV];
#define WT_LAYER (4*512*512 + 2048*512 + 512*2048)
__device__ __align__(16) __half g_wth[NL_*WT_LAYER];
__device__ __align__(16) unsigned char g_bk[B_*L_*L_];
__device__ float g_bqkv[NL_*NQKV];

// ====================== PTX helpers ======================
__device__ __forceinline__ uint32_t smem_u32(const void* p) {
    uint32_t a;
    asm("{ .reg .u64 t; cvta.to.shared.u64 t, %1; cvt.u32.u64 %0, t; }" : "=r"(a) : "l"(p));
    return a;
}
__device__ __forceinline__ void cp16(uint32_t s, const void* g) {
    asm volatile("cp.async.cg.shared.global [%0], [%1], 16;" :: "r"(s), "l"(g));
}
__device__ __forceinline__ void ldsm4(uint32_t* r, uint32_t a) {
    asm volatile("ldmatrix.sync.aligned.m8n8.x4.shared.b16 {%0,%1,%2,%3}, [%4];"
        : "=r"(r[0]), "=r"(r[1]), "=r"(r[2]), "=r"(r[3]) : "r"(a));
}
__device__ __forceinline__ void ldsm4t(uint32_t* r, uint32_t a) {
    asm volatile("ldmatrix.sync.aligned.m8n8.x4.trans.shared.b16 {%0,%1,%2,%3}, [%4];"
        : "=r"(r[0]), "=r"(r[1]), "=r"(r[2]), "=r"(r[3]) : "r"(a));
}
__device__ __forceinline__ void mma16816h(float* c, const uint32_t* a, const uint32_t* b) {
    asm volatile("mma.sync.aligned.m16n8k16.row.col.f32.f16.f16.f32 "
        "{%0,%1,%2,%3}, {%4,%5,%6,%7}, {%8,%9}, {%0,%1,%2,%3};"
        : "+f"(c[0]), "+f"(c[1]), "+f"(c[2]), "+f"(c[3])
        : "r"(a[0]), "r"(a[1]), "r"(a[2]), "r"(a[3]), "r"(b[0]), "r"(b[1]));
}
__device__ __forceinline__ uint32_t pack_f16(float x, float y) {
    __half2 t = __halves2half2(__float2half_rn(x), __float2half_rn(y));
    return *(uint32_t*)&t;
}
__device__ __forceinline__ void store_f16x2(__half* O, size_t off, float v0, float v1) {
    *(uint32_t*)(O + off) = pack_f16(v0, v1);
}

// ====================== time bucket ======================
__device__ __forceinline__ int time_bucket(float delta)
{
    float a = fmaxf(fabsf(delta), 1.0f);
    const float scale = 0.71018780958489f;   // float32(log2(2592000)/30)
    int idx = (int)(log2f(a) / scale) + 1;
    idx = max(1, min(idx, NB_ - 2));
    if (a <= 1.0f)       idx = 0;
    if (a >= 2592000.0f) idx = NB_ - 1;
    return idx;
}

__global__ void bucket_kernel(const float* __restrict__ ts)
{
    int idx = blockIdx.x * blockDim.x + threadIdx.x;   // over B*L*L
    int k = idx & (L_-1);
    int q = (idx >> 9) & (L_-1);
    int b = idx >> 18;
    float d = ts[b * L_ + q] - ts[b * L_ + k];
    g_bk[idx] = (unsigned char)time_bucket(d);
}

__global__ void biascat_kernel(const float* __restrict__ bq,
                               const float* __restrict__ bk,
                               const float* __restrict__ bv)
{
    int i = blockIdx.x * blockDim.x + threadIdx.x;   // NL*1536
    int l = i / NQKV, c = i % NQKV;
    float v = (c < 512) ? bq[l*512 + c] : (c < 1024 ? bk[l*512 + c - 512] : bv[l*512 + c - 1024]);
    g_bqkv[i] = v;
}

// ====================== embedding (+ fp16) ======================
__global__ void embed_kernel(const int* __restrict__ seq,
                             const float* __restrict__ item_emb,
                             const float* __restrict__ pos_emb)
{
    int idx = blockIdx.x * blockDim.x + threadIdx.x;   // over ML*D/4
    int d4 = idx & (D_/4 - 1);
    int bl = idx >> 7;
    int l  = bl & (L_-1);
    int it = seq[bl];
    float4 a = *(const float4*)(item_emb + (size_t)it * D_ + d4*4);
    float4 p = *(const float4*)(pos_emb  + (size_t)l  * D_ + d4*4);
    a.x += p.x; a.y += p.y; a.z += p.z; a.w += p.w;
    ((float4*)g_x)[idx] = a;
    size_t off = (size_t)idx * 4;
    store_f16x2(g_ah, off,     a.x, a.y);
    store_f16x2(g_ah, off + 2, a.z, a.w);
}

// ====================== weight transpose (fp16) ======================
__global__ void conv_wt_kernel(const float* __restrict__ W,
                               __half* __restrict__ Th, int K, int N)
{
    __shared__ float s[32][33];
    int tx = threadIdx.x, ty = threadIdx.y;   // 32 x 8
    int n0 = blockIdx.x * 32, k0 = blockIdx.y * 32;
    #pragma unroll
    for (int j = 0; j < 32; j += 8)
        s[ty + j][tx] = W[(size_t)(k0 + ty + j) * N + n0 + tx];
    __syncthreads();
    #pragma unroll
    for (int j = 0; j < 32; j += 8) {
        int n = n0 + ty + j, k = k0 + tx;
        Th[(size_t)n * K + k] = __float2half_rn(s[tx][ty + j]);
    }
}

// ====================== fp16 HMMA GEMM (single-term A·B) ======================
#define TILE_B   10240
#define STAGE_B  20480   // 2 tiles (A, B)
#define GSMEM    61440   // 3 stages
#define STRIDE   40

// flags: 1 = relu, 2 = write fp32 C, 4 = write fp16 (Oh), 8 = qkv col-scale
__global__ __launch_bounds__(256, 1)
void gemm_hmma(const __half* __restrict__ Ah, const __half* __restrict__ Bh,
               const float* __restrict__ bias, float* __restrict__ C,
               __half* __restrict__ Oh,
               int M, int N, int K, int flags, float oscale)
{
    extern __shared__ char sm[];
    uint32_t sb = smem_u32(sm);
    int tid = threadIdx.x, lane = tid & 31, wid = tid >> 5;
    int wm = wid & 1, wn = wid >> 1;
    int m0 = blockIdx.y * 128, n0 = blockIdx.x * 128;

    int lrow = tid >> 2, lseg = tid & 3;
    const char* gAh = (const char*)(Ah + (size_t)(m0 + lrow) * K + lseg * 8);
    const char* gBh = (const char*)(Bh + (size_t)(n0 + lrow) * K + lseg * 8);
    size_t rowskip = (size_t)64 * K * 2;
    uint32_t s0off = (uint32_t)(lrow * STRIDE + lseg * 8) * 2;
    uint32_t s1off = s0off + 64 * STRIDE * 2;

    float acc[4][4][4];
    #pragma unroll
    for (int a = 0; a < 4; a++)
        #pragma unroll
        for (int b = 0; b < 4; b++)
            #pragma unroll
            for (int c = 0; c < 4; c++) acc[a][b][c] = 0.f;

    int NC = K >> 5;

#define LOADC(cc, st) do { \
    size_t ko = (size_t)(cc) * 64; \
    uint32_t s0 = sb + (st) * STAGE_B + s0off; \
    uint32_t s1 = sb + (st) * STAGE_B + s1off; \
    cp16(s0,          gAh + ko); cp16(s1,          gAh + ko + rowskip); \
    cp16(s0 + TILE_B, gBh + ko); cp16(s1 + TILE_B, gBh + ko + rowskip); \
    asm volatile("cp.async.commit_group;"); \
} while (0)

    LOADC(0, 0);
    LOADC(1, 1);

    int ar = lane & 15, a8 = lane >> 4;
    int st = 0;

    for (int c = 0; c < NC; c++) {
        if (c + 2 < NC) {
            LOADC(c + 2, (c + 2) % 3);
            asm volatile("cp.async.wait_group 2;");
        } else if (c + 1 < NC) {
            asm volatile("cp.async.wait_group 1;");
        } else {
            asm volatile("cp.async.wait_group 0;");
        }
        __syncthreads();

        uint32_t tb = sb + st * STAGE_B;
        st = (st + 1 == 3) ? 0 : st + 1;
        #pragma unroll
        for (int ks = 0; ks < 2; ks++) {
            int acol = ks * 16 + a8 * 8;
            uint32_t Ahf[4][4], Bhf[4][2];
            #pragma unroll
            for (int mt = 0; mt < 4; mt++) {
                uint32_t ad = tb + (uint32_t)((wm * 64 + mt * 16 + ar) * STRIDE + acol) * 2;
                ldsm4(Ahf[mt], ad);
            }
            #pragma unroll
            for (int p = 0; p < 2; p++) {
                uint32_t bd = tb + TILE_B +
                              (uint32_t)((wn * 32 + p * 16 + ar) * STRIDE + acol) * 2;
                uint32_t t[4];
                ldsm4(t, bd);
                Bhf[2*p][0] = t[0]; Bhf[2*p][1] = t[2];
                Bhf[2*p+1][0] = t[1]; Bhf[2*p+1][1] = t[3];
            }
            #pragma unroll
            for (int mt = 0; mt < 4; mt++)
                #pragma unroll
                for (int nt = 0; nt < 4; nt++)
                    mma16816h(acc[mt][nt], Ahf[mt], Bhf[nt]);
        }
        __syncthreads();
    }
#undef LOADC

    int relu = flags & 1, wf = flags & 2, wh = flags & 4;
    int r_base = m0 + wm * 64 + (lane >> 2);
    int c_base = n0 + wn * 32 + (lane & 3) * 2;
    #pragma unroll
    for (int nt = 0; nt < 4; nt++) {
        int c0 = c_base + nt * 8;
        float sc = (flags & 8) ? ((c0 < 512) ? 0.125f : 1.0f) : oscale;
        float2 bv = *(const float2*)(bias + c0);
        #pragma unroll
        for (int mt = 0; mt < 4; mt++) {
            #pragma unroll
            for (int h = 0; h < 2; h++) {
                int r = r_base + mt * 16 + h * 8;
                float v0 = (acc[mt][nt][h*2+0] + bv.x) * sc;
                float v1 = (acc[mt][nt][h*2+1] + bv.y) * sc;
                if (relu) { v0 = fmaxf(v0, 0.f); v1 = fmaxf(v1, 0.f); }
                size_t off = (size_t)r * N + c0;
                if (wf) *(float2*)(C + off) = make_float2(v0, v1);
                if (wh) store_f16x2(Oh, off, v0, v1);
            }
        }
    }
}

// ====================== fp16 HMMA flash attention (single-term) ======================
// block = 128 q rows of one (b,h); 8 warps x 16 rows; 64-key K/V tiles, double-buffered.
// smem: Q 18432 | stage{K 9216, V 9216, BK 8192} x2 | tb 128
#define AQ_OFF    0
#define ASTG_BASE 18432
#define AK_OFF    0
#define AV_OFF    9216
#define ABK_OFF   18432
#define ASTG_SZ   26624
#define ATB_OFF   (ASTG_BASE + 2*ASTG_SZ)        // 71680
#define ATTN2_SMEM (ATB_OFF + 128)               // 71808

__device__ __forceinline__ void load_kv_tile(
    uint32_t sb, const __half* qv, const unsigned char* bkp,
    int b, int h, int q0, int kt, int st, int tid)
{
    uint32_t stb = sb + ASTG_BASE + st * ASTG_SZ;
    const char* gk = (const char*)qv + ((size_t)(b * L_) * NQKV + 512  + h * DH_) * 2;
    const char* gv = (const char*)qv + ((size_t)(b * L_) * NQKV + 1024 + h * DH_) * 2;
    #pragma unroll
    for (int i = 0; i < 2; i++) {
        int idx = tid + i * 256;             // 0..511: r = idx>>3 (0..63), c = idx&7
        int r = idx >> 3, c = idx & 7;
        size_t go = (size_t)(kt * 64 + r) * (NQKV * 2) + c * 16;
        uint32_t so = (uint32_t)(r * 144 + c * 16);
        cp16(stb + AK_OFF + so, gk + go);
        cp16(stb + AV_OFF + so, gv + go);
    }
    #pragma unroll
    for (int i = 0; i < 2; i++) {
        int idx = tid + i * 256;             // 0..511: r = idx>>2 (0..127), c = idx&3
        int r = idx >> 2, c = idx & 3;
        size_t go = ((size_t)(b * L_ + q0 + r)) * L_ + kt * 64 + c * 16;
        cp16(stb + ABK_OFF + (uint32_t)(r * 64 + c * 16), bkp + go);
    }
    asm volatile("cp.async.commit_group;");
}

__global__ __launch_bounds__(256, 1)
void attn_mma(const __half* __restrict__ qv,
              const unsigned char* __restrict__ bkp, const float* __restrict__ tbias,
              __half* __restrict__ oh)
{
    extern __shared__ char sm[];
    uint32_t sb = smem_u32(sm);
    float* smf = (float*)sm;

    int qt = blockIdx.x, h = blockIdx.y, b = blockIdx.z;
    int q0 = qt * 128;
    int tid = threadIdx.x, lane = tid & 31, wid = tid >> 5;
    int g = lane >> 2, tig = lane & 3, tig2 = tig * 2;
    int ar = lane & 15, a8 = lane >> 4;

    {
        const char* gq = (const char*)qv + ((size_t)(b * L_ + q0) * NQKV + h * DH_) * 2;
        #pragma unroll
        for (int i = 0; i < 4; i++) {
            int idx = tid + i * 256;          // 0..1023: r = idx>>3, c = idx&7
            int r = idx >> 3, c = idx & 7;
            cp16(sb + AQ_OFF + (uint32_t)(r * 144 + c * 16),
                 gq + (size_t)r * (NQKV * 2) + c * 16);
        }
    }
    if (tid < NB_) smf[ATB_OFF/4 + tid] = tbias[tid * H_ + h];

    int nkt = 2 * qt + 2;
    load_kv_tile(sb, qv, bkp, b, h, q0, 0, 0, tid);

    int qg0 = q0 + wid * 16 + g, qg1 = qg0 + 8;
    int r0l = wid * 16 + g, r1l = r0l + 8;
    float m0 = -1e30f, m1 = -1e30f, l0 = 0.f, l1 = 0.f;
    float acc_o[8][4];
    #pragma unroll
    for (int nt = 0; nt < 8; nt++)
        #pragma unroll
        for (int i = 0; i < 4; i++) acc_o[nt][i] = 0.f;

    uint32_t qhf[4][4];
    asm volatile("cp.async.wait_group 0;");
    __syncthreads();
    #pragma unroll
    for (int kc = 0; kc < 4; kc++) {
        uint32_t ad = sb + AQ_OFF + (uint32_t)((wid * 16 + ar) * 72 + kc * 16 + a8 * 8) * 2;
        ldsm4(qhf[kc], ad);
    }

    const float* tb = (const float*)(sm + ATB_OFF);

    for (int kt = 0; kt < nkt; kt++) {
        int st = kt & 1;
        if (kt + 1 < nkt) {
            load_kv_tile(sb, qv, bkp, b, h, q0, kt + 1, st ^ 1, tid);
            asm volatile("cp.async.wait_group 1;");
        } else {
            asm volatile("cp.async.wait_group 0;");
        }
        __syncthreads();

        uint32_t stb = sb + ASTG_BASE + st * ASTG_SZ;
        const unsigned char* bkt = (const unsigned char*)(sm + ASTG_BASE + st * ASTG_SZ + ABK_OFF);

        float S[8][4];
        #pragma unroll
        for (int nt = 0; nt < 8; nt++)
            #pragma unroll
            for (int i = 0; i < 4; i++) S[nt][i] = 0.f;

        #pragma unroll
        for (int kc = 0; kc < 4; kc++) {
            #pragma unroll
            for (int nt2 = 0; nt2 < 4; nt2++) {
                uint32_t kd = stb + AK_OFF + (uint32_t)((nt2 * 16 + ar) * 72 + kc * 16 + a8 * 8) * 2;
                uint32_t th[4];
                ldsm4(th, kd);
                uint32_t b0[2] = {th[0], th[2]}, b1[2] = {th[1], th[3]};
                mma16816h(S[2*nt2],   qhf[kc], b0);
                mma16816h(S[2*nt2+1], qhf[kc], b1);
            }
        }

        bool needMask = (kt >= 2 * qt);
        float mx0 = -1e30f, mx1 = -1e30f;
        #pragma unroll
        for (int nt = 0; nt < 8; nt++) {
            int colb = nt * 8 + tig2;
            uint32_t pb0 = *(const unsigned short*)(bkt + r0l * 64 + colb);
            uint32_t pb1 = *(const unsigned short*)(bkt + r1l * 64 + colb);
            float s0a = S[nt][0] + tb[pb0 & 0xFF];
            float s0b = S[nt][1] + tb[pb0 >> 8];
            float s1a = S[nt][2] + tb[pb1 & 0xFF];
            float s1b = S[nt][3] + tb[pb1 >> 8];
            if (needMask) {
                int kg = kt * 64 + colb;
                if (kg     > qg0) s0a = -1e30f;
                if (kg + 1 > qg0) s0b = -1e30f;
                if (kg     > qg1) s1a = -1e30f;
                if (kg + 1 > qg1) s1b = -1e30f;
            }
            S[nt][0] = s0a; S[nt][1] = s0b; S[nt][2] = s1a; S[nt][3] = s1b;
            mx0 = fmaxf(mx0, fmaxf(s0a, s0b));
            mx1 = fmaxf(mx1, fmaxf(s1a, s1b));
        }
        mx0 = fmaxf(mx0, __shfl_xor_sync(~0u, mx0, 1));
        mx0 = fmaxf(mx0, __shfl_xor_sync(~0u, mx0, 2));
        mx1 = fmaxf(mx1, __shfl_xor_sync(~0u, mx1, 1));
        mx1 = fmaxf(mx1, __shfl_xor_sync(~0u, mx1, 2));
        float mn0 = fmaxf(m0, mx0), mn1 = fmaxf(m1, mx1);
        float rs0 = __expf(m0 - mn0), rs1 = __expf(m1 - mn1);
        m0 = mn0; m1 = mn1;

        float sum0 = 0.f, sum1 = 0.f;
        #pragma unroll
        for (int nt = 0; nt < 8; nt++) {
            float p0 = __expf(S[nt][0] - mn0);
            float p1 = __expf(S[nt][1] - mn0);
            float p2 = __expf(S[nt][2] - mn1);
            float p3 = __expf(S[nt][3] - mn1);
            S[nt][0] = p0; S[nt][1] = p1; S[nt][2] = p2; S[nt][3] = p3;
            sum0 += p0 + p1; sum1 += p2 + p3;
        }
        sum0 += __shfl_xor_sync(~0u, sum0, 1); sum0 += __shfl_xor_sync(~0u, sum0, 2);
        sum1 += __shfl_xor_sync(~0u, sum1, 1); sum1 += __shfl_xor_sync(~0u, sum1, 2);
        l0 = l0 * rs0 + sum0;
        l1 = l1 * rs1 + sum1;
        #pragma unroll
        for (int nt = 0; nt < 8; nt++) {
            acc_o[nt][0] *= rs0; acc_o[nt][1] *= rs0;
            acc_o[nt][2] *= rs1; acc_o[nt][3] *= rs1;
        }

        #pragma unroll
        for (int t = 0; t < 4; t++) {
            uint32_t ap[4];
            ap[0] = pack_f16(S[2*t][0],   S[2*t][1]);
            ap[1] = pack_f16(S[2*t][2],   S[2*t][3]);
            ap[2] = pack_f16(S[2*t+1][0], S[2*t+1][1]);
            ap[3] = pack_f16(S[2*t+1][2], S[2*t+1][3]);
            #pragma unroll
            for (int j2 = 0; j2 < 4; j2++) {
                uint32_t vd = stb + AV_OFF + (uint32_t)((t * 16 + ar) * 72 + j2 * 16 + a8 * 8) * 2;
                uint32_t th[4];
                ldsm4t(th, vd);
                uint32_t b0[2] = {th[0], th[1]}, b1[2] = {th[2], th[3]};
                mma16816h(acc_o[2*j2],   ap, b0);
                mma16816h(acc_o[2*j2+1], ap, b1);
            }
        }
        __syncthreads();
    }

    // epilogue: fp16 output (feeds Wo GEMM)
    float inv0 = 1.0f / l0, inv1 = 1.0f / l1;
    size_t row0 = ((size_t)(b * L_ + qg0)) * D_ + h * DH_;
    size_t row1 = ((size_t)(b * L_ + qg1)) * D_ + h * DH_;
    #pragma unroll
    for (int nt = 0; nt < 8; nt++) {
        int cc = nt * 8 + tig2;
        store_f16x2(oh, row0 + cc, acc_o[nt][0] * inv0, acc_o[nt][1] * inv0);
        store_f16x2(oh, row1 + cc, acc_o[nt][2] * inv1, acc_o[nt][3] * inv1);
    }
}

// ====================== fused residual add + LayerNorm (+ optional fp16 out) ======================
__global__ __launch_bounds__(128)
void add_ln_kernel(const float* __restrict__ xin, const float* __restrict__ res,
                   const float* __restrict__ g, const float* __restrict__ bb,
                   float* __restrict__ xout, __half* __restrict__ oh, int writeH)
{
    __shared__ float sy[D_];
    __shared__ float red[4];
    int row = blockIdx.x;
    int tid = threadIdx.x;
    int lane = tid & 31, w = tid >> 5;

    const float* xr = xin + (size_t)row * D_;
    const float* rr = res + (size_t)row * D_;

    float lsum = 0.f;
    #pragma unroll
    for (int i = 0; i < 4; i++) {
        int d = tid + i * 128;
        float val = xr[d] + rr[d];
        sy[d] = val;
        lsum += val;
    }
    #pragma unroll
    for (int o = 16; o > 0; o >>= 1) lsum += __shfl_xor_sync(~0u, lsum, o);
    if (lane == 0) red[w] = lsum;
    __syncthreads();
    float mean = (red[0] + red[1] + red[2] + red[3]) * (1.0f / D_);
    __syncthreads();

    float lv = 0.f;
    #pragma unroll
    for (int i = 0; i < 4; i++) {
        int d = tid + i * 128;
        float c = sy[d] - mean;
        lv += c * c;
    }
    #pragma unroll
    for (int o = 16; o > 0; o >>= 1) lv += __shfl_xor_sync(~0u, lv, o);
    if (lane == 0) red[w] = lv;
    __syncthreads();
    float var = (red[0] + red[1] + red[2] + red[3]) * (1.0f / D_);
    float inv = rsqrtf(var + 1e-5f);

    #pragma unroll
    for (int i = 0; i < 4; i++) {
        int d = tid + i * 128;
        float val = (sy[d] - mean) * inv * g[d] + bb[d];
        xout[(size_t)row * D_ + d] = val;
        if (writeH)
            oh[(size_t)row * D_ + d] = __float2half_rn(val);
    }
}

// ====================== launch ======================
extern "C" void kernel_launch(void* const* d_in, const int* in_sizes, int n_in,
                              void* d_out, int out_size)
{
    const int*   seq      = (const int*)  d_in[0];
    const float* ts       = (const float*)d_in[1];
    const float* item_emb = (const float*)d_in[2];
    const float* pos_emb  = (const float*)d_in[3];
    const float* Wq  = (const float*)d_in[4];  const float* bq  = (const float*)d_in[5];
    const float* Wk  = (const float*)d_in[6];  const float* bk  = (const float*)d_in[7];
    const float* Wv  = (const float*)d_in[8];  const float* bv  = (const float*)d_in[9];
    const float* tbias = (const float*)d_in[10];
    const float* Wo  = (const float*)d_in[11]; const float* bo  = (const float*)d_in[12];
    const float* g1  = (const float*)d_in[13]; const float* be1 = (const float*)d_in[14];
    const float* W1  = (const float*)d_in[15]; const float* bf1 = (const float*)d_in[16];
    const float* W2  = (const float*)d_in[17]; const float* bf2 = (const float*)d_in[18];
    const float* g2  = (const float*)d_in[19]; const float* be2 = (const float*)d_in[20];

    float *x, *po, *bqkv;
    __half *ah, *fh, *qv, *wth;
    unsigned char* bkptr;
    cudaGetSymbolAddress((void**)&x,  g_x);
    cudaGetSymbolAddress((void**)&po, g_po);
    cudaGetSymbolAddress((void**)&ah, g_ah);
    cudaGetSymbolAddress((void**)&qv, g_qv);
    cudaGetSymbolAddress((void**)&fh, g_fh);
    cudaGetSymbolAddress((void**)&wth, g_wth);
    cudaGetSymbolAddress((void**)&bkptr, g_bk);
    cudaGetSymbolAddress((void**)&bqkv, g_bqkv);

    cudaFuncSetAttribute(attn_mma,  cudaFuncAttributeMaxDynamicSharedMemorySize, ATTN2_SMEM);
    cudaFuncSetAttribute(gemm_hmma, cudaFuncAttributeMaxDynamicSharedMemorySize, GSMEM);

    const size_t OQ = 0, OO = 786432, O1 = 1048576, O2 = 2097152;
    dim3 t32(32, 8);
    dim3 gQKV(NQKV / 128, ML_ / 128);  // (12, 128)
    dim3 gD(D_ / 128, ML_ / 128);      // (4, 128)
    dim3 gF(DFF_ / 128, ML_ / 128);    // (16, 128)
    dim3 ga(L_ / 128, H_, B_);         // (4, 8, 32)

    for (int i = 0; i < NL_; i++) {
        size_t wb = (size_t)i * WT_LAYER;
        conv_wt_kernel<<<dim3(16, 16), t32>>>(Wq + (size_t)i*D_*D_,   wth+wb+0,      512, 512);
        conv_wt_kernel<<<dim3(16, 16), t32>>>(Wk + (size_t)i*D_*D_,   wth+wb+262144, 512, 512);
        conv_wt_kernel<<<dim3(16, 16), t32>>>(Wv + (size_t)i*D_*D_,   wth+wb+524288, 512, 512);
        conv_wt_kernel<<<dim3(16, 16), t32>>>(Wo + (size_t)i*D_*D_,   wth+wb+OO, 512, 512);
        conv_wt_kernel<<<dim3(64, 16), t32>>>(W1 + (size_t)i*D_*DFF_, wth+wb+O1, 512, 2048);
        conv_wt_kernel<<<dim3(16, 64), t32>>>(W2 + (size_t)i*DFF_*D_, wth+wb+O2, 2048, 512);
    }
    biascat_kernel<<<(NL_*NQKV)/256, 256>>>(bq, bk, bv);
    embed_kernel<<<(ML_ * D_ / 4) / 256, 256>>>(seq, item_emb, pos_emb);
    bucket_kernel<<<(B_*L_*L_)/256, 256>>>(ts);

    for (int i = 0; i < NL_; i++) {
        size_t wb = (size_t)i * WT_LAYER;

        // fused QKV -> fp16 packed output, q-section scaled 0.125
        gemm_hmma<<<gQKV, 256, GSMEM>>>(ah, wth+wb+OQ, bqkv + i*NQKV,
                                        0, qv, ML_, NQKV, D_, 4|8, 1.0f);

        attn_mma<<<ga, 256, ATTN2_SMEM>>>(qv, bkptr, tbias + (size_t)i*NB_*H_, ah);

        gemm_hmma<<<gD, 256, GSMEM>>>(ah, wth+wb+OO, bo + i*D_, po, 0, ML_, D_, D_, 2, 1.0f);
        add_ln_kernel<<<ML_, 128>>>(x, po, g1 + i*D_, be1 + i*D_, x, ah, 1);

        gemm_hmma<<<gF, 256, GSMEM>>>(ah, wth+wb+O1, bf1 + i*DFF_, 0, fh, ML_, DFF_, D_, 1|4, 1.0f);
        gemm_hmma<<<gD, 256, GSMEM>>>(fh, wth+wb+O2, bf2 + i*D_, po, 0, ML_, D_, DFF_, 2, 1.0f);

        float* xo = (i == NL_ - 1) ? (float*)d_out : x;
        add_ln_kernel<<<ML_, 128>>>(x, po, g2 + i*D_, be2 + i*D_, xo, ah, (i < NL_ - 1) ? 1 : 0);
    }
}

// round 11
// speedup vs baseline: 6.1027x; 1.0293x over previous
#include <cuda_runtime.h>
#include <cuda_fp16.h>
#include <math.h>
#include <stdint.h>

#define B_   32
#define L_   512
#define D_   512
#define H_   8
#define DH_  64
#define NL_  2
#define DFF_ 2048
#define NB_  32
#define ML_  (B_*L_)   // 16384 rows
#define NQKV 1536

// ---------------- scratch (device globals; no allocations) ----------------
__device__ float g_x [ML_*D_];
__device__ float g_po[ML_*D_];
__device__ __align__(16) __half g_ah[ML_*D_];
__device__ __align__(16) __half g_fh[ML_*DFF_];
__device__ __align__(16) __half g_qv[ML_*NQKV];
#define WT_LAYER (4*512*512 + 2048*512 + 512*2048)
__device__ __align__(16) __half g_wth[NL_*WT_LAYER];
__device__ __align__(16) unsigned char g_bk[B_*L_*L_];
__device__ float g_bqkv[NL_*NQKV];

// ====================== PTX helpers ======================
__device__ __forceinline__ uint32_t smem_u32(const void* p) {
    uint32_t a;
    asm("{ .reg .u64 t; cvta.to.shared.u64 t, %1; cvt.u32.u64 %0, t; }" : "=r"(a) : "l"(p));
    return a;
}
__device__ __forceinline__ void cp16(uint32_t s, const void* g) {
    asm volatile("cp.async.cg.shared.global [%0], [%1], 16;" :: "r"(s), "l"(g));
}
__device__ __forceinline__ void ldsm4(uint32_t* r, uint32_t a) {
    asm volatile("ldmatrix.sync.aligned.m8n8.x4.shared.b16 {%0,%1,%2,%3}, [%4];"
        : "=r"(r[0]), "=r"(r[1]), "=r"(r[2]), "=r"(r[3]) : "r"(a));
}
__device__ __forceinline__ void ldsm4t(uint32_t* r, uint32_t a) {
    asm volatile("ldmatrix.sync.aligned.m8n8.x4.trans.shared.b16 {%0,%1,%2,%3}, [%4];"
        : "=r"(r[0]), "=r"(r[1]), "=r"(r[2]), "=r"(r[3]) : "r"(a));
}
__device__ __forceinline__ void mma16816h(float* c, const uint32_t* a, const uint32_t* b) {
    asm volatile("mma.sync.aligned.m16n8k16.row.col.f32.f16.f16.f32 "
        "{%0,%1,%2,%3}, {%4,%5,%6,%7}, {%8,%9}, {%0,%1,%2,%3};"
        : "+f"(c[0]), "+f"(c[1]), "+f"(c[2]), "+f"(c[3])
        : "r"(a[0]), "r"(a[1]), "r"(a[2]), "r"(a[3]), "r"(b[0]), "r"(b[1]));
}
__device__ __forceinline__ uint32_t pack_f16(float x, float y) {
    __half2 t = __halves2half2(__float2half_rn(x), __float2half_rn(y));
    return *(uint32_t*)&t;
}
__device__ __forceinline__ void store_f16x2(__half* O, size_t off, float v0, float v1) {
    *(uint32_t*)(O + off) = pack_f16(v0, v1);
}

// ====================== time bucket ======================
__device__ __forceinline__ int time_bucket(float delta)
{
    float a = fmaxf(fabsf(delta), 1.0f);
    const float scale = 0.71018780958489f;   // float32(log2(2592000)/30)
    int idx = (int)(log2f(a) / scale) + 1;
    idx = max(1, min(idx, NB_ - 2));
    if (a <= 1.0f)       idx = 0;
    if (a >= 2592000.0f) idx = NB_ - 1;
    return idx;
}

__global__ void bucket_kernel(const float* __restrict__ ts)
{
    int idx = blockIdx.x * blockDim.x + threadIdx.x;   // over B*L*L
    int k = idx & (L_-1);
    int q = (idx >> 9) & (L_-1);
    int b = idx >> 18;
    float d = ts[b * L_ + q] - ts[b * L_ + k];
    g_bk[idx] = (unsigned char)time_bucket(d);
}

__global__ void biascat_kernel(const float* __restrict__ bq,
                               const float* __restrict__ bk,
                               const float* __restrict__ bv)
{
    int i = blockIdx.x * blockDim.x + threadIdx.x;   // NL*1536
    int l = i / NQKV, c = i % NQKV;
    float v = (c < 512) ? bq[l*512 + c] : (c < 1024 ? bk[l*512 + c - 512] : bv[l*512 + c - 1024]);
    g_bqkv[i] = v;
}

// ====================== embedding (+ fp16) ======================
__global__ void embed_kernel(const int* __restrict__ seq,
                             const float* __restrict__ item_emb,
                             const float* __restrict__ pos_emb)
{
    int idx = blockIdx.x * blockDim.x + threadIdx.x;   // over ML*D/4
    int d4 = idx & (D_/4 - 1);
    int bl = idx >> 7;
    int l  = bl & (L_-1);
    int it = seq[bl];
    float4 a = *(const float4*)(item_emb + (size_t)it * D_ + d4*4);
    float4 p = *(const float4*)(pos_emb  + (size_t)l  * D_ + d4*4);
    a.x += p.x; a.y += p.y; a.z += p.z; a.w += p.w;
    ((float4*)g_x)[idx] = a;
    size_t off = (size_t)idx * 4;
    store_f16x2(g_ah, off,     a.x, a.y);
    store_f16x2(g_ah, off + 2, a.z, a.w);
}

// ====================== weight transpose (fp16, layer-batched) ======================
__global__ void conv_wt_kernel(const float* __restrict__ W,
                               __half* __restrict__ Th, int K, int N,
                               size_t in_stride, size_t out_stride)
{
    W  += (size_t)blockIdx.z * in_stride;
    Th += (size_t)blockIdx.z * out_stride;
    __shared__ float s[32][33];
    int tx = threadIdx.x, ty = threadIdx.y;   // 32 x 8
    int n0 = blockIdx.x * 32, k0 = blockIdx.y * 32;
    #pragma unroll
    for (int j = 0; j < 32; j += 8)
        s[ty + j][tx] = W[(size_t)(k0 + ty + j) * N + n0 + tx];
    __syncthreads();
    #pragma unroll
    for (int j = 0; j < 32; j += 8) {
        int n = n0 + ty + j, k = k0 + tx;
        Th[(size_t)n * K + k] = __float2half_rn(s[tx][ty + j]);
    }
}

// ====================== fp16 HMMA GEMM (single-term A·B) ======================
#define TILE_B   10240
#define STAGE_B  20480   // 2 tiles (A, B)
#define GSMEM    61440   // 3 stages
#define STRIDE   40

// flags: 1 = relu, 2 = write fp32 C, 4 = write fp16 (Oh), 8 = qkv col-scale
__global__ __launch_bounds__(256, 2)
void gemm_hmma(const __half* __restrict__ Ah, const __half* __restrict__ Bh,
               const float* __restrict__ bias, float* __restrict__ C,
               __half* __restrict__ Oh,
               int M, int N, int K, int flags, float oscale)
{
    extern __shared__ char sm[];
    uint32_t sb = smem_u32(sm);
    int tid = threadIdx.x, lane = tid & 31, wid = tid >> 5;
    int wm = wid & 1, wn = wid >> 1;
    int m0 = blockIdx.y * 128, n0 = blockIdx.x * 128;

    int lrow = tid >> 2, lseg = tid & 3;
    const char* gAh = (const char*)(Ah + (size_t)(m0 + lrow) * K + lseg * 8);
    const char* gBh = (const char*)(Bh + (size_t)(n0 + lrow) * K + lseg * 8);
    size_t rowskip = (size_t)64 * K * 2;
    uint32_t s0off = (uint32_t)(lrow * STRIDE + lseg * 8) * 2;
    uint32_t s1off = s0off + 64 * STRIDE * 2;

    float acc[4][4][4];
    #pragma unroll
    for (int a = 0; a < 4; a++)
        #pragma unroll
        for (int b = 0; b < 4; b++)
            #pragma unroll
            for (int c = 0; c < 4; c++) acc[a][b][c] = 0.f;

    int NC = K >> 5;

#define LOADC(cc, st) do { \
    size_t ko = (size_t)(cc) * 64; \
    uint32_t s0 = sb + (st) * STAGE_B + s0off; \
    uint32_t s1 = sb + (st) * STAGE_B + s1off; \
    cp16(s0,          gAh + ko); cp16(s1,          gAh + ko + rowskip); \
    cp16(s0 + TILE_B, gBh + ko); cp16(s1 + TILE_B, gBh + ko + rowskip); \
    asm volatile("cp.async.commit_group;"); \
} while (0)

    LOADC(0, 0);
    LOADC(1, 1);

    int ar = lane & 15, a8 = lane >> 4;
    int st = 0;

    for (int c = 0; c < NC; c++) {
        if (c + 2 < NC) {
            LOADC(c + 2, (c + 2) % 3);
            asm volatile("cp.async.wait_group 2;");
        } else if (c + 1 < NC) {
            asm volatile("cp.async.wait_group 1;");
        } else {
            asm volatile("cp.async.wait_group 0;");
        }
        __syncthreads();

        uint32_t tb = sb + st * STAGE_B;
        st = (st + 1 == 3) ? 0 : st + 1;
        #pragma unroll
        for (int ks = 0; ks < 2; ks++) {
            int acol = ks * 16 + a8 * 8;
            uint32_t Ahf[4][4], Bhf[4][2];
            #pragma unroll
            for (int mt = 0; mt < 4; mt++) {
                uint32_t ad = tb + (uint32_t)((wm * 64 + mt * 16 + ar) * STRIDE + acol) * 2;
                ldsm4(Ahf[mt], ad);
            }
            #pragma unroll
            for (int p = 0; p < 2; p++) {
                uint32_t bd = tb + TILE_B +
                              (uint32_t)((wn * 32 + p * 16 + ar) * STRIDE + acol) * 2;
                uint32_t t[4];
                ldsm4(t, bd);
                Bhf[2*p][0] = t[0]; Bhf[2*p][1] = t[2];
                Bhf[2*p+1][0] = t[1]; Bhf[2*p+1][1] = t[3];
            }
            #pragma unroll
            for (int mt = 0; mt < 4; mt++)
                #pragma unroll
                for (int nt = 0; nt < 4; nt++)
                    mma16816h(acc[mt][nt], Ahf[mt], Bhf[nt]);
        }
        __syncthreads();
    }
#undef LOADC

    int relu = flags & 1, wf = flags & 2, wh = flags & 4;
    int r_base = m0 + wm * 64 + (lane >> 2);
    int c_base = n0 + wn * 32 + (lane & 3) * 2;
    #pragma unroll
    for (int nt = 0; nt < 4; nt++) {
        int c0 = c_base + nt * 8;
        float sc = (flags & 8) ? ((c0 < 512) ? 0.125f : 1.0f) : oscale;
        float2 bv = *(const float2*)(bias + c0);
        #pragma unroll
        for (int mt = 0; mt < 4; mt++) {
            #pragma unroll
            for (int h = 0; h < 2; h++) {
                int r = r_base + mt * 16 + h * 8;
                float v0 = (acc[mt][nt][h*2+0] + bv.x) * sc;
                float v1 = (acc[mt][nt][h*2+1] + bv.y) * sc;
                if (relu) { v0 = fmaxf(v0, 0.f); v1 = fmaxf(v1, 0.f); }
                size_t off = (size_t)r * N + c0;
                if (wf) *(float2*)(C + off) = make_float2(v0, v1);
                if (wh) store_f16x2(Oh, off, v0, v1);
            }
        }
    }
}

// ====================== fp16 HMMA flash attention (single-term) ======================
#define AQ_OFF    0
#define ASTG_BASE 18432
#define AK_OFF    0
#define AV_OFF    9216
#define ABK_OFF   18432
#define ASTG_SZ   26624
#define ATB_OFF   (ASTG_BASE + 2*ASTG_SZ)        // 71680
#define ATTN2_SMEM (ATB_OFF + 128)               // 71808

__device__ __forceinline__ void load_kv_tile(
    uint32_t sb, const __half* qv, const unsigned char* bkp,
    int b, int h, int q0, int kt, int st, int tid)
{
    uint32_t stb = sb + ASTG_BASE + st * ASTG_SZ;
    const char* gk = (const char*)qv + ((size_t)(b * L_) * NQKV + 512  + h * DH_) * 2;
    const char* gv = (const char*)qv + ((size_t)(b * L_) * NQKV + 1024 + h * DH_) * 2;
    #pragma unroll
    for (int i = 0; i < 2; i++) {
        int idx = tid + i * 256;
        int r = idx >> 3, c = idx & 7;
        size_t go = (size_t)(kt * 64 + r) * (NQKV * 2) + c * 16;
        uint32_t so = (uint32_t)(r * 144 + c * 16);
        cp16(stb + AK_OFF + so, gk + go);
        cp16(stb + AV_OFF + so, gv + go);
    }
    #pragma unroll
    for (int i = 0; i < 2; i++) {
        int idx = tid + i * 256;
        int r = idx >> 2, c = idx & 3;
        size_t go = ((size_t)(b * L_ + q0 + r)) * L_ + kt * 64 + c * 16;
        cp16(stb + ABK_OFF + (uint32_t)(r * 64 + c * 16), bkp + go);
    }
    asm volatile("cp.async.commit_group;");
}

__global__ __launch_bounds__(256, 2)
void attn_mma(const __half* __restrict__ qv,
              const unsigned char* __restrict__ bkp, const float* __restrict__ tbias,
              __half* __restrict__ oh)
{
    extern __shared__ char sm[];
    uint32_t sb = smem_u32(sm);
    float* smf = (float*)sm;

    int qt = blockIdx.x, h = blockIdx.y, b = blockIdx.z;
    int q0 = qt * 128;
    int tid = threadIdx.x, lane = tid & 31, wid = tid >> 5;
    int g = lane >> 2, tig = lane & 3, tig2 = tig * 2;
    int ar = lane & 15, a8 = lane >> 4;

    {
        const char* gq = (const char*)qv + ((size_t)(b * L_ + q0) * NQKV + h * DH_) * 2;
        #pragma unroll
        for (int i = 0; i < 4; i++) {
            int idx = tid + i * 256;
            int r = idx >> 3, c = idx & 7;
            cp16(sb + AQ_OFF + (uint32_t)(r * 144 + c * 16),
                 gq + (size_t)r * (NQKV * 2) + c * 16);
        }
    }
    if (tid < NB_) smf[ATB_OFF/4 + tid] = tbias[tid * H_ + h];

    int nkt = 2 * qt + 2;
    load_kv_tile(sb, qv, bkp, b, h, q0, 0, 0, tid);

    int qg0 = q0 + wid * 16 + g, qg1 = qg0 + 8;
    int r0l = wid * 16 + g, r1l = r0l + 8;
    float m0 = -1e30f, m1 = -1e30f, l0 = 0.f, l1 = 0.f;
    float acc_o[8][4];
    #pragma unroll
    for (int nt = 0; nt < 8; nt++)
        #pragma unroll
        for (int i = 0; i < 4; i++) acc_o[nt][i] = 0.f;

    uint32_t qhf[4][4];
    asm volatile("cp.async.wait_group 0;");
    __syncthreads();
    #pragma unroll
    for (int kc = 0; kc < 4; kc++) {
        uint32_t ad = sb + AQ_OFF + (uint32_t)((wid * 16 + ar) * 72 + kc * 16 + a8 * 8) * 2;
        ldsm4(qhf[kc], ad);
    }

    const float* tb = (const float*)(sm + ATB_OFF);

    for (int kt = 0; kt < nkt; kt++) {
        int st = kt & 1;
        if (kt + 1 < nkt) {
            load_kv_tile(sb, qv, bkp, b, h, q0, kt + 1, st ^ 1, tid);
            asm volatile("cp.async.wait_group 1;");
        } else {
            asm volatile("cp.async.wait_group 0;");
        }
        __syncthreads();

        uint32_t stb = sb + ASTG_BASE + st * ASTG_SZ;
        const unsigned char* bkt = (const unsigned char*)(sm + ASTG_BASE + st * ASTG_SZ + ABK_OFF);

        float S[8][4];
        #pragma unroll
        for (int nt = 0; nt < 8; nt++)
            #pragma unroll
            for (int i = 0; i < 4; i++) S[nt][i] = 0.f;

        #pragma unroll
        for (int kc = 0; kc < 4; kc++) {
            #pragma unroll
            for (int nt2 = 0; nt2 < 4; nt2++) {
                uint32_t kd = stb + AK_OFF + (uint32_t)((nt2 * 16 + ar) * 72 + kc * 16 + a8 * 8) * 2;
                uint32_t th[4];
                ldsm4(th, kd);
                uint32_t b0[2] = {th[0], th[2]}, b1[2] = {th[1], th[3]};
                mma16816h(S[2*nt2],   qhf[kc], b0);
                mma16816h(S[2*nt2+1], qhf[kc], b1);
            }
        }

        bool needMask = (kt >= 2 * qt);
        float mx0 = -1e30f, mx1 = -1e30f;
        #pragma unroll
        for (int nt = 0; nt < 8; nt++) {
            int colb = nt * 8 + tig2;
            uint32_t pb0 = *(const unsigned short*)(bkt + r0l * 64 + colb);
            uint32_t pb1 = *(const unsigned short*)(bkt + r1l * 64 + colb);
            float s0a = S[nt][0] + tb[pb0 & 0xFF];
            float s0b = S[nt][1] + tb[pb0 >> 8];
            float s1a = S[nt][2] + tb[pb1 & 0xFF];
            float s1b = S[nt][3] + tb[pb1 >> 8];
            if (needMask) {
                int kg = kt * 64 + colb;
                if (kg     > qg0) s0a = -1e30f;
                if (kg + 1 > qg0) s0b = -1e30f;
                if (kg     > qg1) s1a = -1e30f;
                if (kg + 1 > qg1) s1b = -1e30f;
            }
            S[nt][0] = s0a; S[nt][1] = s0b; S[nt][2] = s1a; S[nt][3] = s1b;
            mx0 = fmaxf(mx0, fmaxf(s0a, s0b));
            mx1 = fmaxf(mx1, fmaxf(s1a, s1b));
        }
        mx0 = fmaxf(mx0, __shfl_xor_sync(~0u, mx0, 1));
        mx0 = fmaxf(mx0, __shfl_xor_sync(~0u, mx0, 2));
        mx1 = fmaxf(mx1, __shfl_xor_sync(~0u, mx1, 1));
        mx1 = fmaxf(mx1, __shfl_xor_sync(~0u, mx1, 2));
        float mn0 = fmaxf(m0, mx0), mn1 = fmaxf(m1, mx1);
        float rs0 = __expf(m0 - mn0), rs1 = __expf(m1 - mn1);
        m0 = mn0; m1 = mn1;

        float sum0 = 0.f, sum1 = 0.f;
        #pragma unroll
        for (int nt = 0; nt < 8; nt++) {
            float p0 = __expf(S[nt][0] - mn0);
            float p1 = __expf(S[nt][1] - mn0);
            float p2 = __expf(S[nt][2] - mn1);
            float p3 = __expf(S[nt][3] - mn1);
            S[nt][0] = p0; S[nt][1] = p1; S[nt][2] = p2; S[nt][3] = p3;
            sum0 += p0 + p1; sum1 += p2 + p3;
        }
        sum0 += __shfl_xor_sync(~0u, sum0, 1); sum0 += __shfl_xor_sync(~0u, sum0, 2);
        sum1 += __shfl_xor_sync(~0u, sum1, 1); sum1 += __shfl_xor_sync(~0u, sum1, 2);
        l0 = l0 * rs0 + sum0;
        l1 = l1 * rs1 + sum1;
        #pragma unroll
        for (int nt = 0; nt < 8; nt++) {
            acc_o[nt][0] *= rs0; acc_o[nt][1] *= rs0;
            acc_o[nt][2] *= rs1; acc_o[nt][3] *= rs1;
        }

        #pragma unroll
        for (int t = 0; t < 4; t++) {
            uint32_t ap[4];
            ap[0] = pack_f16(S[2*t][0],   S[2*t][1]);
            ap[1] = pack_f16(S[2*t][2],   S[2*t][3]);
            ap[2] = pack_f16(S[2*t+1][0], S[2*t+1][1]);
            ap[3] = pack_f16(S[2*t+1][2], S[2*t+1][3]);
            #pragma unroll
            for (int j2 = 0; j2 < 4; j2++) {
                uint32_t vd = stb + AV_OFF + (uint32_t)((t * 16 + ar) * 72 + j2 * 16 + a8 * 8) * 2;
                uint32_t th[4];
                ldsm4t(th, vd);
                uint32_t b0[2] = {th[0], th[1]}, b1[2] = {th[2], th[3]};
                mma16816h(acc_o[2*j2],   ap, b0);
                mma16816h(acc_o[2*j2+1], ap, b1);
            }
        }
        __syncthreads();
    }

    float inv0 = 1.0f / l0, inv1 = 1.0f / l1;
    size_t row0 = ((size_t)(b * L_ + qg0)) * D_ + h * DH_;
    size_t row1 = ((size_t)(b * L_ + qg1)) * D_ + h * DH_;
    #pragma unroll
    for (int nt = 0; nt < 8; nt++) {
        int cc = nt * 8 + tig2;
        store_f16x2(oh, row0 + cc, acc_o[nt][0] * inv0, acc_o[nt][1] * inv0);
        store_f16x2(oh, row1 + cc, acc_o[nt][2] * inv1, acc_o[nt][3] * inv1);
    }
}

// ====================== fused residual add + LayerNorm (+ optional fp16 out) ======================
__global__ __launch_bounds__(128)
void add_ln_kernel(const float* __restrict__ xin, const float* __restrict__ res,
                   const float* __restrict__ g, const float* __restrict__ bb,
                   float* __restrict__ xout, __half* __restrict__ oh, int writeH)
{
    __shared__ float sy[D_];
    __shared__ float red[4];
    int row = blockIdx.x;
    int tid = threadIdx.x;
    int lane = tid & 31, w = tid >> 5;

    const float* xr = xin + (size_t)row * D_;
    const float* rr = res + (size_t)row * D_;

    float lsum = 0.f;
    #pragma unroll
    for (int i = 0; i < 4; i++) {
        int d = tid + i * 128;
        float val = xr[d] + rr[d];
        sy[d] = val;
        lsum += val;
    }
    #pragma unroll
    for (int o = 16; o > 0; o >>= 1) lsum += __shfl_xor_sync(~0u, lsum, o);
    if (lane == 0) red[w] = lsum;
    __syncthreads();
    float mean = (red[0] + red[1] + red[2] + red[3]) * (1.0f / D_);
    __syncthreads();

    float lv = 0.f;
    #pragma unroll
    for (int i = 0; i < 4; i++) {
        int d = tid + i * 128;
        float c = sy[d] - mean;
        lv += c * c;
    }
    #pragma unroll
    for (int o = 16; o > 0; o >>= 1) lv += __shfl_xor_sync(~0u, lv, o);
    if (lane == 0) red[w] = lv;
    __syncthreads();
    float var = (red[0] + red[1] + red[2] + red[3]) * (1.0f / D_);
    float inv = rsqrtf(var + 1e-5f);

    #pragma unroll
    for (int i = 0; i < 4; i++) {
        int d = tid + i * 128;
        float val = (sy[d] - mean) * inv * g[d] + bb[d];
        xout[(size_t)row * D_ + d] = val;
        if (writeH)
            oh[(size_t)row * D_ + d] = __float2half_rn(val);
    }
}

// ====================== launch ======================
extern "C" void kernel_launch(void* const* d_in, const int* in_sizes, int n_in,
                              void* d_out, int out_size)
{
    const int*   seq      = (const int*)  d_in[0];
    const float* ts       = (const float*)d_in[1];
    const float* item_emb = (const float*)d_in[2];
    const float* pos_emb  = (const float*)d_in[3];
    const float* Wq  = (const float*)d_in[4];  const float* bq  = (const float*)d_in[5];
    const float* Wk  = (const float*)d_in[6];  const float* bk  = (const float*)d_in[7];
    const float* Wv  = (const float*)d_in[8];  const float* bv  = (const float*)d_in[9];
    const float* tbias = (const float*)d_in[10];
    const float* Wo  = (const float*)d_in[11]; const float* bo  = (const float*)d_in[12];
    const float* g1  = (const float*)d_in[13]; const float* be1 = (const float*)d_in[14];
    const float* W1  = (const float*)d_in[15]; const float* bf1 = (const float*)d_in[16];
    const float* W2  = (const float*)d_in[17]; const float* bf2 = (const float*)d_in[18];
    const float* g2  = (const float*)d_in[19]; const float* be2 = (const float*)d_in[20];

    float *x, *po, *bqkv;
    __half *ah, *fh, *qv, *wth;
    unsigned char* bkptr;
    cudaGetSymbolAddress((void**)&x,  g_x);
    cudaGetSymbolAddress((void**)&po, g_po);
    cudaGetSymbolAddress((void**)&ah, g_ah);
    cudaGetSymbolAddress((void**)&qv, g_qv);
    cudaGetSymbolAddress((void**)&fh, g_fh);
    cudaGetSymbolAddress((void**)&wth, g_wth);
    cudaGetSymbolAddress((void**)&bkptr, g_bk);
    cudaGetSymbolAddress((void**)&bqkv, g_bqkv);

    cudaFuncSetAttribute(attn_mma,  cudaFuncAttributeMaxDynamicSharedMemorySize, ATTN2_SMEM);
    cudaFuncSetAttribute(gemm_hmma, cudaFuncAttributeMaxDynamicSharedMemorySize, GSMEM);

    const size_t OQ = 0, OO = 786432, O1 = 1048576, O2 = 2097152;
    dim3 t32(32, 8);
    dim3 gQKV(NQKV / 128, ML_ / 128);  // (12, 128)
    dim3 gD(D_ / 128, ML_ / 128);      // (4, 128)
    dim3 gF(DFF_ / 128, ML_ / 128);    // (16, 128)
    dim3 ga(L_ / 128, H_, B_);         // (4, 8, 32)

    // layer-batched weight transposes (grid.z = NL)
    conv_wt_kernel<<<dim3(16, 16, NL_), t32>>>(Wq, wth+0,      512, 512,  (size_t)D_*D_,   WT_LAYER);
    conv_wt_kernel<<<dim3(16, 16, NL_), t32>>>(Wk, wth+262144, 512, 512,  (size_t)D_*D_,   WT_LAYER);
    conv_wt_kernel<<<dim3(16, 16, NL_), t32>>>(Wv, wth+524288, 512, 512,  (size_t)D_*D_,   WT_LAYER);
    conv_wt_kernel<<<dim3(16, 16, NL_), t32>>>(Wo, wth+OO,     512, 512,  (size_t)D_*D_,   WT_LAYER);
    conv_wt_kernel<<<dim3(64, 16, NL_), t32>>>(W1, wth+O1,     512, 2048, (size_t)D_*DFF_, WT_LAYER);
    conv_wt_kernel<<<dim3(16, 64, NL_), t32>>>(W2, wth+O2,     2048, 512, (size_t)DFF_*D_, WT_LAYER);

    biascat_kernel<<<(NL_*NQKV)/256, 256>>>(bq, bk, bv);
    embed_kernel<<<(ML_ * D_ / 4) / 256, 256>>>(seq, item_emb, pos_emb);
    bucket_kernel<<<(B_*L_*L_)/256, 256>>>(ts);

    for (int i = 0; i < NL_; i++) {
        size_t wb = (size_t)i * WT_LAYER;

        // fused QKV -> fp16 packed output, q-section scaled 0.125
        gemm_hmma<<<gQKV, 256, GSMEM>>>(ah, wth+wb+OQ, bqkv + i*NQKV,
                                        0, qv, ML_, NQKV, D_, 4|8, 1.0f);

        attn_mma<<<ga, 256, ATTN2_SMEM>>>(qv, bkptr, tbias + (size_t)i*NB_*H_, ah);

        gemm_hmma<<<gD, 256, GSMEM>>>(ah, wth+wb+OO, bo + i*D_, po, 0, ML_, D_, D_, 2, 1.0f);
        add_ln_kernel<<<ML_, 128>>>(x, po, g1 + i*D_, be1 + i*D_, x, ah, 1);

        gemm_hmma<<<gF, 256, GSMEM>>>(ah, wth+wb+O1, bf1 + i*DFF_, 0, fh, ML_, DFF_, D_, 1|4, 1.0f);
        gemm_hmma<<<gD, 256, GSMEM>>>(fh, wth+wb+O2, bf2 + i*D_, po, 0, ML_, D_, DFF_, 2, 1.0f);

        float* xo = (i == NL_ - 1) ? (float*)d_out : x;
        add_ln_kernel<<<ML_, 128>>>(x, po, g2 + i*D_, be2 + i*D_, xo, ah, (i < NL_ - 1) ? 1 : 0);
    }
}